// round 1
// baseline (speedup 1.0000x reference)
#include <cuda_runtime.h>

#define NB 2048
#define ND 32
#define NH 256
#define TSTR 36   // padded smem stride (floats): 144B rows, 16B aligned, bank-spread

// ---------------- scratch (device globals; no allocation allowed) ----------------
__device__ float g_h1[2][NB*NH];
__device__ float g_g1[2][NB*NH];
__device__ float g_h2[2][NB*NH];
__device__ float g_g2[2][NB*NH];
__device__ float g_P[NH*NH];          // trace bilinear matrix
__device__ float g_Q[ND*NH*NH];       // 32 cov-div bilinear matrices (8 MB)

// ---------------- packed fp32x2 helpers ----------------
static __device__ __forceinline__ unsigned long long pack2(float x, float y){
    unsigned long long r;
    asm("mov.b64 %0, {%1, %2};" : "=l"(r)
        : "r"(__float_as_uint(x)), "r"(__float_as_uint(y)));
    return r;
}
static __device__ __forceinline__ float2 unpack2(unsigned long long v){
    unsigned lo, hi;
    asm("mov.b64 {%0, %1}, %2;" : "=r"(lo), "=r"(hi) : "l"(v));
    return make_float2(__uint_as_float(lo), __uint_as_float(hi));
}
static __device__ __forceinline__ void ffma2(unsigned long long &d,
                                             unsigned long long a,
                                             unsigned long long b){
    asm("fma.rn.f32x2 %0, %1, %2, %0;" : "+l"(d) : "l"(a), "l"(b));
}

// load 32 samples x 256 features, transposed into smem: sm[a*TSTR + s]
static __device__ __forceinline__ void load_tileT(float* sm, const float* g, int b0){
    for (int idx = threadIdx.x; idx < 32*NH; idx += 256){
        int s = idx >> 8;
        int a = idx & 255;
        sm[a*TSTR + s] = g[(b0 + s)*NH + a];
    }
}

// ---------------- precompute P ----------------
// P[a][c] = sW2[a,c] * sum_i sW3[c,i]*sW1[i,a]
__global__ void k_precompP(const float* __restrict__ sW1,
                           const float* __restrict__ sW2,
                           const float* __restrict__ sW3){
    int a = blockIdx.x;
    int c = threadIdx.x;
    __shared__ float w1[ND];
    if (c < ND) w1[c] = sW1[c*NH + a];
    __syncthreads();
    const float* s3 = sW3 + c*ND;
    float acc = 0.f;
#pragma unroll
    for (int i = 0; i < ND; i++) acc = fmaf(s3[i], w1[i], acc);
    g_P[a*NH + c] = sW2[a*NH + c] * acc;
}

// ---------------- precompute Q ----------------
// Q[i][a][c] = cW2[a,c] * sum_j cW1[j,a]*cW3[c, i*32+j]
__global__ void k_precompQ(const float* __restrict__ cW1,
                           const float* __restrict__ cW2,
                           const float* __restrict__ cW3){
    int i  = blockIdx.x;
    int a0 = blockIdx.y * 32;
    int c  = threadIdx.x;
    __shared__ float w1s[ND][33];   // w1s[j][a-a0]
    for (int idx = threadIdx.x; idx < ND*32; idx += 256){
        int j = idx >> 5, aa = idx & 31;
        w1s[j][aa] = cW1[j*NH + a0 + aa];
    }
    __syncthreads();
    float w3[ND];
#pragma unroll
    for (int j = 0; j < ND; j++) w3[j] = cW3[c*(ND*ND) + i*ND + j];
#pragma unroll 4
    for (int aa = 0; aa < 32; aa++){
        float acc = 0.f;
#pragma unroll
        for (int j = 0; j < ND; j++) acc = fmaf(w3[j], w1s[j][aa], acc);
        int a = a0 + aa;
        g_Q[(i*NH + a)*NH + c] = cW2[a*NH + c] * acc;
    }
}

// ---------------- layer 1 (both nets): h1 = tanh(x@W1+b1), g1 = 1-h1^2 ----------------
__global__ void k_layer1(const float* __restrict__ x,
                         const float* __restrict__ sW1, const float* __restrict__ sb1,
                         const float* __restrict__ cW1, const float* __restrict__ cb1){
    int net = blockIdx.y;
    const float* W1 = net ? cW1 : sW1;
    const float* b1 = net ? cb1 : sb1;
    int b0 = blockIdx.x * 8;
    int u  = threadIdx.x;
    __shared__ float xs[8][ND];
    xs[u >> 5][u & 31] = x[b0*ND + u];
    __syncthreads();
    float acc[8];
    float bias = b1[u];
#pragma unroll
    for (int s = 0; s < 8; s++) acc[s] = bias;
#pragma unroll
    for (int k = 0; k < ND; k++){
        float w = W1[k*NH + u];
#pragma unroll
        for (int s = 0; s < 8; s++) acc[s] = fmaf(xs[s][k], w, acc[s]);
    }
    float* hout = g_h1[net];
    float* gout = g_g1[net];
#pragma unroll
    for (int s = 0; s < 8; s++){
        float h = tanhf(acc[s]);
        hout[(b0+s)*NH + u] = h;
        gout[(b0+s)*NH + u] = 1.0f - h*h;
    }
}

// ---------------- layer 2 (both nets): h2 = tanh(h1@W2+b2), g2 = 1-h2^2 ----------------
__global__ void k_layer2(const float* __restrict__ sW2, const float* __restrict__ sb2,
                         const float* __restrict__ cW2, const float* __restrict__ cb2){
    int net = blockIdx.y;
    const float* W = net ? cW2 : sW2;
    const float* bias = net ? cb2 : sb2;
    const float* h1 = g_h1[net];
    int b0 = blockIdx.x * 32;
    int c  = threadIdx.x;
    __shared__ __align__(16) float h1T[NH*TSTR];
    load_tileT(h1T, h1, b0);
    __syncthreads();

    unsigned long long acc[16];
    float bv = bias[c];
    unsigned long long bp = pack2(bv, bv);
#pragma unroll
    for (int q = 0; q < 16; q++) acc[q] = bp;

#pragma unroll 2
    for (int a = 0; a < NH; a++){
        float w = W[a*NH + c];
        unsigned long long w2 = pack2(w, w);
        const ulonglong2* row = reinterpret_cast<const ulonglong2*>(&h1T[a*TSTR]);
#pragma unroll
        for (int p = 0; p < 8; p++){
            ulonglong2 v = row[p];
            ffma2(acc[2*p],   v.x, w2);
            ffma2(acc[2*p+1], v.y, w2);
        }
    }
    float* h2 = g_h2[net];
    float* g2 = g_g2[net];
#pragma unroll
    for (int q = 0; q < 16; q++){
        float2 f = unpack2(acc[q]);
        int s0 = 2*q;
        float t0 = tanhf(f.x), t1 = tanhf(f.y);
        h2[(b0+s0  )*NH + c] = t0;  g2[(b0+s0  )*NH + c] = 1.0f - t0*t0;
        h2[(b0+s0+1)*NH + c] = t1;  g2[(b0+s0+1)*NH + c] = 1.0f - t1*t1;
    }
}

// ---------------- layer 3, score net: score = h2s@sW3 + sb3 ----------------
__global__ void k_layer3_score(const float* __restrict__ sW3,
                               const float* __restrict__ sb3,
                               float* __restrict__ out_score){
    int b0 = blockIdx.x * 32;
    int i  = threadIdx.x & 31;
    int sg = threadIdx.x >> 5;          // 8 groups of 4 samples
    __shared__ __align__(16) float h2T[NH*TSTR];
    load_tileT(h2T, g_h2[0], b0);
    __syncthreads();
    float acc[4];
    float bias = sb3[i];
#pragma unroll
    for (int k = 0; k < 4; k++) acc[k] = bias;
#pragma unroll 4
    for (int a = 0; a < NH; a++){
        float w = sW3[a*ND + i];
        float4 v = *reinterpret_cast<const float4*>(&h2T[a*TSTR + sg*4]);
        acc[0] = fmaf(v.x, w, acc[0]);
        acc[1] = fmaf(v.y, w, acc[1]);
        acc[2] = fmaf(v.z, w, acc[2]);
        acc[3] = fmaf(v.w, w, acc[3]);
    }
#pragma unroll
    for (int k = 0; k < 4; k++)
        out_score[(b0 + sg*4 + k)*ND + i] = acc[k];
}

// ---------------- layer 3, cov net: cov = h2c@cW3 + cb3 (written to output) ----------
__global__ void k_layer3_cov(const float* __restrict__ cW3,
                             const float* __restrict__ cb3,
                             float* __restrict__ out_cov){
    int b0 = blockIdx.x * 32;
    int c  = blockIdx.y * 256 + threadIdx.x;
    __shared__ __align__(16) float h2T[NH*TSTR];
    load_tileT(h2T, g_h2[1], b0);
    __syncthreads();

    unsigned long long acc[16];
    float bv = cb3[c];
    unsigned long long bp = pack2(bv, bv);
#pragma unroll
    for (int q = 0; q < 16; q++) acc[q] = bp;

#pragma unroll 2
    for (int a = 0; a < NH; a++){
        float w = cW3[a*(ND*ND) + c];
        unsigned long long w2 = pack2(w, w);
        const ulonglong2* row = reinterpret_cast<const ulonglong2*>(&h2T[a*TSTR]);
#pragma unroll
        for (int p = 0; p < 8; p++){
            ulonglong2 v = row[p];
            ffma2(acc[2*p],   v.x, w2);
            ffma2(acc[2*p+1], v.y, w2);
        }
    }
#pragma unroll
    for (int q = 0; q < 16; q++){
        float2 f = unpack2(acc[q]);
        int s0 = 2*q;
        out_cov[(b0+s0  )*(ND*ND) + c] = f.x;
        out_cov[(b0+s0+1)*(ND*ND) + c] = f.y;
    }
}

// ---------------- trace[b] = gs1[b]^T P gs2[b] ----------------
__global__ void k_trace(float* __restrict__ out_trace){
    int b0 = blockIdx.x * 32;
    int c  = threadIdx.x;
    __shared__ __align__(16) float g1T[NH*TSTR];
    __shared__ float partial[8][32];
    load_tileT(g1T, g_g1[0], b0);
    __syncthreads();

    unsigned long long acc[16];
#pragma unroll
    for (int q = 0; q < 16; q++) acc[q] = 0ull;

#pragma unroll 2
    for (int a = 0; a < NH; a++){
        float p = g_P[a*NH + c];
        unsigned long long p2 = pack2(p, p);
        const ulonglong2* row = reinterpret_cast<const ulonglong2*>(&g1T[a*TSTR]);
#pragma unroll
        for (int q = 0; q < 8; q++){
            ulonglong2 v = row[q];
            ffma2(acc[2*q],   v.x, p2);
            ffma2(acc[2*q+1], v.y, p2);
        }
    }
    const float* gs2 = g_g2[0];
    float val[32];
#pragma unroll
    for (int q = 0; q < 16; q++){
        float2 f = unpack2(acc[q]);
        val[2*q]   = f.x * gs2[(b0 + 2*q    )*NH + c];
        val[2*q+1] = f.y * gs2[(b0 + 2*q + 1)*NH + c];
    }
    int lane = threadIdx.x & 31, w = threadIdx.x >> 5;
#pragma unroll
    for (int s = 0; s < 32; s++){
        float v = val[s];
        v += __shfl_xor_sync(0xffffffffu, v, 16);
        v += __shfl_xor_sync(0xffffffffu, v, 8);
        v += __shfl_xor_sync(0xffffffffu, v, 4);
        v += __shfl_xor_sync(0xffffffffu, v, 2);
        v += __shfl_xor_sync(0xffffffffu, v, 1);
        val[s] = v;
    }
    if (lane == 0){
#pragma unroll
        for (int s = 0; s < 32; s++) partial[w][s] = val[s];
    }
    __syncthreads();
    if (threadIdx.x < 32){
        float t = 0.f;
#pragma unroll
        for (int ww = 0; ww < 8; ww++) t += partial[ww][threadIdx.x];
        out_trace[b0 + threadIdx.x] = t;
    }
}

// ---------------- cov_div[b,i] = gc1[b]^T Q_i gc2[b] ----------------
// grid: (i = 0..31, sample-group = 0..7 of 256 samples), 256 threads
__global__ void k_covdiv(float* __restrict__ out_covdiv){
    int i = blockIdx.x;
    int c = threadIdx.x;
    const float* gc1 = g_g1[1];
    const float* gc2 = g_g2[1];
    const float* Qi  = g_Q + i*NH*NH;
    __shared__ __align__(16) float g1T[NH*TSTR];
    __shared__ float partial[8][32];
    int lane = threadIdx.x & 31, w = threadIdx.x >> 5;

    for (int chunk = 0; chunk < 8; chunk++){
        int b0 = blockIdx.y * 256 + chunk * 32;
        __syncthreads();                      // previous chunk fully consumed
        load_tileT(g1T, gc1, b0);
        __syncthreads();

        unsigned long long acc[16];
#pragma unroll
        for (int q = 0; q < 16; q++) acc[q] = 0ull;

#pragma unroll 2
        for (int a = 0; a < NH; a++){
            float qv = Qi[a*NH + c];
            unsigned long long q2 = pack2(qv, qv);
            const ulonglong2* row = reinterpret_cast<const ulonglong2*>(&g1T[a*TSTR]);
#pragma unroll
            for (int p = 0; p < 8; p++){
                ulonglong2 v = row[p];
                ffma2(acc[2*p],   v.x, q2);
                ffma2(acc[2*p+1], v.y, q2);
            }
        }
        float val[32];
#pragma unroll
        for (int q = 0; q < 16; q++){
            float2 f = unpack2(acc[q]);
            val[2*q]   = f.x * gc2[(b0 + 2*q    )*NH + c];
            val[2*q+1] = f.y * gc2[(b0 + 2*q + 1)*NH + c];
        }
#pragma unroll
        for (int s = 0; s < 32; s++){
            float v = val[s];
            v += __shfl_xor_sync(0xffffffffu, v, 16);
            v += __shfl_xor_sync(0xffffffffu, v, 8);
            v += __shfl_xor_sync(0xffffffffu, v, 4);
            v += __shfl_xor_sync(0xffffffffu, v, 2);
            v += __shfl_xor_sync(0xffffffffu, v, 1);
            val[s] = v;
        }
        if (lane == 0){
#pragma unroll
            for (int s = 0; s < 32; s++) partial[w][s] = val[s];
        }
        __syncthreads();
        if (threadIdx.x < 32){
            float t = 0.f;
#pragma unroll
            for (int ww = 0; ww < 8; ww++) t += partial[ww][threadIdx.x];
            out_covdiv[(b0 + threadIdx.x)*ND + i] = t;
        }
    }
}

// ---------------- launch ----------------
extern "C" void kernel_launch(void* const* d_in, const int* in_sizes, int n_in,
                              void* d_out, int out_size){
    const float* x   = (const float*)d_in[0];
    const float* sW1 = (const float*)d_in[1];
    const float* sb1 = (const float*)d_in[2];
    const float* sW2 = (const float*)d_in[3];
    const float* sb2 = (const float*)d_in[4];
    const float* sW3 = (const float*)d_in[5];
    const float* sb3 = (const float*)d_in[6];
    const float* cW1 = (const float*)d_in[7];
    const float* cb1 = (const float*)d_in[8];
    const float* cW2 = (const float*)d_in[9];
    const float* cb2 = (const float*)d_in[10];
    const float* cW3 = (const float*)d_in[11];
    const float* cb3 = (const float*)d_in[12];

    float* out        = (float*)d_out;
    float* out_score  = out;                                   // [B,32]
    float* out_trace  = out + NB*ND;                           // [B]
    float* out_cov    = out + NB*ND + NB;                      // [B,1024]
    float* out_covdiv = out + NB*ND + NB + NB*ND*ND;           // [B,32]

    k_precompP<<<NH, NH>>>(sW1, sW2, sW3);
    k_precompQ<<<dim3(ND, 8), NH>>>(cW1, cW2, cW3);
    k_layer1<<<dim3(NB/8, 2), NH>>>(x, sW1, sb1, cW1, cb1);
    k_layer2<<<dim3(NB/32, 2), NH>>>(sW2, sb2, cW2, cb2);
    k_layer3_score<<<NB/32, NH>>>(sW3, sb3, out_score);
    k_layer3_cov<<<dim3(NB/32, 4), NH>>>(cW3, cb3, out_cov);
    k_trace<<<NB/32, NH>>>(out_trace);
    k_covdiv<<<dim3(ND, 8), NH>>>(out_covdiv);
}

// round 2
// speedup vs baseline: 2.5183x; 2.5183x over previous
#include <cuda_runtime.h>

#define NB 2048
#define ND 32
#define NH 256
#define TSTR 36   // padded smem stride (floats)
#define KT 16     // K-tile for W staging
#define NKT (NH/KT)

// ---------------- scratch (device globals) ----------------
__device__ float g_h1[2][NB*NH];
__device__ float g_g1[2][NB*NH];
__device__ float g_h2[2][NB*NH];
__device__ float g_g2[2][NB*NH];
__device__ float g_P[NH*NH];          // trace bilinear matrix
__device__ float g_Q[ND*NH*NH];       // 32 cov-div bilinear matrices (8 MB)

// shared layout (floats): [sT: NH*TSTR][wbuf: 2*KT*NH][partial: 64]
#define SM_WBUF (NH*TSTR)
#define SM_PART (NH*TSTR + 2*KT*NH)
#define SMEM_FLOATS (NH*TSTR + 2*KT*NH + 64)
#define SMEM_BYTES (SMEM_FLOATS*4)

// ---------------- packed fp32x2 helpers ----------------
static __device__ __forceinline__ unsigned long long pack2(float x, float y){
    unsigned long long r;
    asm("mov.b64 %0, {%1, %2};" : "=l"(r)
        : "r"(__float_as_uint(x)), "r"(__float_as_uint(y)));
    return r;
}
static __device__ __forceinline__ float2 unpack2(unsigned long long v){
    unsigned lo, hi;
    asm("mov.b64 {%0, %1}, %2;" : "=r"(lo), "=r"(hi) : "l"(v));
    return make_float2(__uint_as_float(lo), __uint_as_float(hi));
}
static __device__ __forceinline__ void ffma2(unsigned long long &d,
                                             unsigned long long a,
                                             unsigned long long b){
    asm("fma.rn.f32x2 %0, %1, %2, %0;" : "+l"(d) : "l"(a), "l"(b));
}

// load 32 samples x 256 features, transposed into smem: sm[a*TSTR + s]
static __device__ __forceinline__ void load_tileT(float* sm, const float* g, int b0){
    for (int idx = threadIdx.x; idx < 32*NH; idx += 256){
        int s = idx >> 8;
        int a = idx & 255;
        sm[a*TSTR + s] = g[(b0 + s)*NH + a];
    }
}

// ---------------- core: acc[sp][cc] += sum_a sT[a][sample] * W[a][c] ----------------
// thread t: cg = t&63 (c-quad), sq = t>>6 (sample octet)
// Wg points at W[0][cbase]; row stride wstride. Double-buffered KT staging.
static __device__ __forceinline__ void gemm_tile(
    const float* __restrict__ Wg, int wstride,
    const float* __restrict__ sT,
    float* __restrict__ wbuf,
    unsigned long long acc[4][4],
    int cg, int sq)
{
    const int t = threadIdx.x;
    float4 pre[4];
#pragma unroll
    for (int p = 0; p < 4; p++){
        int lin = t + p*256;
        pre[p] = *reinterpret_cast<const float4*>(Wg + (lin>>6)*wstride + (lin&63)*4);
    }
#pragma unroll 1
    for (int kt = 0; kt < NKT; kt++){
        float* wb = wbuf + (kt&1)*(KT*NH);
#pragma unroll
        for (int p = 0; p < 4; p++){
            int lin = t + p*256;
            *reinterpret_cast<float4*>(wb + lin*4) = pre[p];
        }
        __syncthreads();
        if (kt+1 < NKT){
            const float* Wn = Wg + (kt+1)*KT*wstride;
#pragma unroll
            for (int p = 0; p < 4; p++){
                int lin = t + p*256;
                pre[p] = *reinterpret_cast<const float4*>(Wn + (lin>>6)*wstride + (lin&63)*4);
            }
        }
        const float* srow = sT + (kt*KT)*TSTR + sq*8;
        const float* wrow = wb + cg*4;
#pragma unroll
        for (int aa = 0; aa < KT; aa++){
            ulonglong2 r0 = *reinterpret_cast<const ulonglong2*>(srow);
            ulonglong2 r1 = *reinterpret_cast<const ulonglong2*>(srow + 4);
            float4 wq = *reinterpret_cast<const float4*>(wrow);
            unsigned long long w0 = pack2(wq.x, wq.x);
            unsigned long long w1 = pack2(wq.y, wq.y);
            unsigned long long w2p = pack2(wq.z, wq.z);
            unsigned long long w3 = pack2(wq.w, wq.w);
            ffma2(acc[0][0], r0.x, w0); ffma2(acc[0][1], r0.x, w1);
            ffma2(acc[0][2], r0.x, w2p); ffma2(acc[0][3], r0.x, w3);
            ffma2(acc[1][0], r0.y, w0); ffma2(acc[1][1], r0.y, w1);
            ffma2(acc[1][2], r0.y, w2p); ffma2(acc[1][3], r0.y, w3);
            ffma2(acc[2][0], r1.x, w0); ffma2(acc[2][1], r1.x, w1);
            ffma2(acc[2][2], r1.x, w2p); ffma2(acc[2][3], r1.x, w3);
            ffma2(acc[3][0], r1.y, w0); ffma2(acc[3][1], r1.y, w1);
            ffma2(acc[3][2], r1.y, w2p); ffma2(acc[3][3], r1.y, w3);
            srow += TSTR; wrow += NH;
        }
        __syncthreads();
    }
}

static __device__ __forceinline__ void unpack_T(const unsigned long long acc[4][4],
                                                float T[8][4]){
#pragma unroll
    for (int sp = 0; sp < 4; sp++)
#pragma unroll
        for (int cc = 0; cc < 4; cc++){
            float2 f = unpack2(acc[sp][cc]);
            T[2*sp][cc]   = f.x;
            T[2*sp+1][cc] = f.y;
        }
}

// ---------------- precompute P ----------------
__global__ void k_precompP(const float* __restrict__ sW1,
                           const float* __restrict__ sW2,
                           const float* __restrict__ sW3){
    int a = blockIdx.x;
    int c = threadIdx.x;
    __shared__ float w1[ND];
    if (c < ND) w1[c] = sW1[c*NH + a];
    __syncthreads();
    const float* s3 = sW3 + c*ND;
    float acc = 0.f;
#pragma unroll
    for (int i = 0; i < ND; i++) acc = fmaf(s3[i], w1[i], acc);
    g_P[a*NH + c] = sW2[a*NH + c] * acc;
}

// ---------------- precompute Q ----------------
__global__ void k_precompQ(const float* __restrict__ cW1,
                           const float* __restrict__ cW2,
                           const float* __restrict__ cW3){
    int i  = blockIdx.x;
    int a0 = blockIdx.y * 32;
    int c  = threadIdx.x;
    __shared__ float w1s[ND][33];
    for (int idx = threadIdx.x; idx < ND*32; idx += 256){
        int j = idx >> 5, aa = idx & 31;
        w1s[j][aa] = cW1[j*NH + a0 + aa];
    }
    __syncthreads();
    float w3[ND];
#pragma unroll
    for (int j = 0; j < ND; j++) w3[j] = cW3[c*(ND*ND) + i*ND + j];
#pragma unroll 4
    for (int aa = 0; aa < 32; aa++){
        float acc = 0.f;
#pragma unroll
        for (int j = 0; j < ND; j++) acc = fmaf(w3[j], w1s[j][aa], acc);
        int a = a0 + aa;
        g_Q[(i*NH + a)*NH + c] = cW2[a*NH + c] * acc;
    }
}

// ---------------- layer 1 ----------------
__global__ void k_layer1(const float* __restrict__ x,
                         const float* __restrict__ sW1, const float* __restrict__ sb1,
                         const float* __restrict__ cW1, const float* __restrict__ cb1){
    int net = blockIdx.y;
    const float* W1 = net ? cW1 : sW1;
    const float* b1 = net ? cb1 : sb1;
    int b0 = blockIdx.x * 8;
    int u  = threadIdx.x;
    __shared__ float xs[8][ND];
    xs[u >> 5][u & 31] = x[b0*ND + u];
    __syncthreads();
    float acc[8];
    float bias = b1[u];
#pragma unroll
    for (int s = 0; s < 8; s++) acc[s] = bias;
#pragma unroll
    for (int k = 0; k < ND; k++){
        float w = W1[k*NH + u];
#pragma unroll
        for (int s = 0; s < 8; s++) acc[s] = fmaf(xs[s][k], w, acc[s]);
    }
    float* hout = g_h1[net];
    float* gout = g_g1[net];
#pragma unroll
    for (int s = 0; s < 8; s++){
        float h = tanhf(acc[s]);
        hout[(b0+s)*NH + u] = h;
        gout[(b0+s)*NH + u] = 1.0f - h*h;
    }
}

// ---------------- layer 2 ----------------
__global__ void __launch_bounds__(256, 3)
k_layer2(const float* __restrict__ sW2, const float* __restrict__ sb2,
         const float* __restrict__ cW2, const float* __restrict__ cb2){
    extern __shared__ float smemf[];
    float* sT   = smemf;
    float* wbuf = smemf + SM_WBUF;
    int net = blockIdx.y;
    const float* W    = net ? cW2 : sW2;
    const float* bias = net ? cb2 : sb2;
    int b0 = blockIdx.x * 32;
    int cg = threadIdx.x & 63;
    int sq = threadIdx.x >> 6;

    load_tileT(sT, g_h1[net], b0);
    __syncthreads();

    float4 bq = *reinterpret_cast<const float4*>(&bias[cg*4]);
    unsigned long long acc[4][4];
#pragma unroll
    for (int sp = 0; sp < 4; sp++){
        acc[sp][0] = pack2(bq.x, bq.x); acc[sp][1] = pack2(bq.y, bq.y);
        acc[sp][2] = pack2(bq.z, bq.z); acc[sp][3] = pack2(bq.w, bq.w);
    }
    gemm_tile(W, NH, sT, wbuf, acc, cg, sq);

    float T[8][4];
    unpack_T(acc, T);
    float* h2 = g_h2[net];
    float* g2 = g_g2[net];
#pragma unroll
    for (int s = 0; s < 8; s++){
        float4 hv, gv;
        hv.x = tanhf(T[s][0]); hv.y = tanhf(T[s][1]);
        hv.z = tanhf(T[s][2]); hv.w = tanhf(T[s][3]);
        gv.x = 1.0f - hv.x*hv.x; gv.y = 1.0f - hv.y*hv.y;
        gv.z = 1.0f - hv.z*hv.z; gv.w = 1.0f - hv.w*hv.w;
        int row = (b0 + sq*8 + s)*NH + cg*4;
        *reinterpret_cast<float4*>(&h2[row]) = hv;
        *reinterpret_cast<float4*>(&g2[row]) = gv;
    }
}

// ---------------- layer 3, score net ----------------
__global__ void k_layer3_score(const float* __restrict__ sW3,
                               const float* __restrict__ sb3,
                               float* __restrict__ out_score){
    int b0 = blockIdx.x * 32;
    int i  = threadIdx.x & 31;
    int sg = threadIdx.x >> 5;
    __shared__ __align__(16) float h2T[NH*TSTR];
    load_tileT(h2T, g_h2[0], b0);
    __syncthreads();
    float acc[4];
    float bias = sb3[i];
#pragma unroll
    for (int k = 0; k < 4; k++) acc[k] = bias;
#pragma unroll 4
    for (int a = 0; a < NH; a++){
        float w = sW3[a*ND + i];
        float4 v = *reinterpret_cast<const float4*>(&h2T[a*TSTR + sg*4]);
        acc[0] = fmaf(v.x, w, acc[0]);
        acc[1] = fmaf(v.y, w, acc[1]);
        acc[2] = fmaf(v.z, w, acc[2]);
        acc[3] = fmaf(v.w, w, acc[3]);
    }
#pragma unroll
    for (int k = 0; k < 4; k++)
        out_score[(b0 + sg*4 + k)*ND + i] = acc[k];
}

// ---------------- layer 3, cov net ----------------
__global__ void __launch_bounds__(256, 3)
k_layer3_cov(const float* __restrict__ cW3,
             const float* __restrict__ cb3,
             float* __restrict__ out_cov){
    extern __shared__ float smemf[];
    float* sT   = smemf;
    float* wbuf = smemf + SM_WBUF;
    int b0    = blockIdx.x * 32;
    int cbase = blockIdx.y * 256;
    int cg = threadIdx.x & 63;
    int sq = threadIdx.x >> 6;

    load_tileT(sT, g_h2[1], b0);
    __syncthreads();

    float4 bq = *reinterpret_cast<const float4*>(&cb3[cbase + cg*4]);
    unsigned long long acc[4][4];
#pragma unroll
    for (int sp = 0; sp < 4; sp++){
        acc[sp][0] = pack2(bq.x, bq.x); acc[sp][1] = pack2(bq.y, bq.y);
        acc[sp][2] = pack2(bq.z, bq.z); acc[sp][3] = pack2(bq.w, bq.w);
    }
    gemm_tile(cW3 + cbase, ND*ND, sT, wbuf, acc, cg, sq);

    float T[8][4];
    unpack_T(acc, T);
#pragma unroll
    for (int s = 0; s < 8; s++){
        float4 v = make_float4(T[s][0], T[s][1], T[s][2], T[s][3]);
        *reinterpret_cast<float4*>(&out_cov[(b0 + sq*8 + s)*(ND*ND) + cbase + cg*4]) = v;
    }
}

// ---------------- bilinear epilogue: val = sum_c T[s][c]*g2[s,c], reduce over c ------
static __device__ __forceinline__ void bilinear_reduce_store(
    const float T[8][4], const float* __restrict__ g2row, int b0,
    float* __restrict__ partial, float* __restrict__ outp, int ostride)
{
    int cg = threadIdx.x & 63;
    int sq = threadIdx.x >> 6;
    float val[8];
#pragma unroll
    for (int s = 0; s < 8; s++){
        float4 gq = *reinterpret_cast<const float4*>(&g2row[(b0 + sq*8 + s)*NH + cg*4]);
        val[s] = T[s][0]*gq.x + T[s][1]*gq.y + T[s][2]*gq.z + T[s][3]*gq.w;
    }
#pragma unroll
    for (int off = 16; off; off >>= 1)
#pragma unroll
        for (int s = 0; s < 8; s++)
            val[s] += __shfl_xor_sync(0xffffffffu, val[s], off);
    int w = threadIdx.x >> 5;
    if ((threadIdx.x & 31) == 0){
#pragma unroll
        for (int s = 0; s < 8; s++) partial[w*8 + s] = val[s];
    }
    __syncthreads();
    if (threadIdx.x < 32){
        int sq2 = threadIdx.x >> 3, s = threadIdx.x & 7;
        float v = partial[(2*sq2)*8 + s] + partial[(2*sq2+1)*8 + s];
        outp[(b0 + threadIdx.x)*ostride] = v;
    }
}

// ---------------- trace ----------------
__global__ void __launch_bounds__(256, 3)
k_trace(float* __restrict__ out_trace){
    extern __shared__ float smemf[];
    float* sT      = smemf;
    float* wbuf    = smemf + SM_WBUF;
    float* partial = smemf + SM_PART;
    int b0 = blockIdx.x * 32;
    int cg = threadIdx.x & 63;
    int sq = threadIdx.x >> 6;

    load_tileT(sT, g_g1[0], b0);
    __syncthreads();

    unsigned long long acc[4][4];
#pragma unroll
    for (int sp = 0; sp < 4; sp++)
#pragma unroll
        for (int cc = 0; cc < 4; cc++) acc[sp][cc] = 0ull;

    gemm_tile(g_P, NH, sT, wbuf, acc, cg, sq);

    float T[8][4];
    unpack_T(acc, T);
    bilinear_reduce_store(T, g_g2[0], b0, partial, out_trace, 1);
}

// ---------------- cov_div ----------------
// grid (32 i, 16 groups of 128 samples); 4 chunks of 32 samples per block
__global__ void __launch_bounds__(256, 3)
k_covdiv(float* __restrict__ out_covdiv){
    extern __shared__ float smemf[];
    float* sT      = smemf;
    float* wbuf    = smemf + SM_WBUF;
    float* partial = smemf + SM_PART;
    int i  = blockIdx.x;
    int cg = threadIdx.x & 63;
    int sq = threadIdx.x >> 6;
    const float* Qi = g_Q + i*NH*NH;

    for (int ch = 0; ch < 4; ch++){
        int b0 = blockIdx.y * 128 + ch * 32;
        __syncthreads();
        load_tileT(sT, g_g1[1], b0);
        __syncthreads();

        unsigned long long acc[4][4];
#pragma unroll
        for (int sp = 0; sp < 4; sp++)
#pragma unroll
            for (int cc = 0; cc < 4; cc++) acc[sp][cc] = 0ull;

        gemm_tile(Qi, NH, sT, wbuf, acc, cg, sq);

        float T[8][4];
        unpack_T(acc, T);
        bilinear_reduce_store(T, g_g2[1], b0, partial, out_covdiv + i, ND);
    }
}

// ---------------- launch ----------------
extern "C" void kernel_launch(void* const* d_in, const int* in_sizes, int n_in,
                              void* d_out, int out_size){
    const float* x   = (const float*)d_in[0];
    const float* sW1 = (const float*)d_in[1];
    const float* sb1 = (const float*)d_in[2];
    const float* sW2 = (const float*)d_in[3];
    const float* sb2 = (const float*)d_in[4];
    const float* sW3 = (const float*)d_in[5];
    const float* sb3 = (const float*)d_in[6];
    const float* cW1 = (const float*)d_in[7];
    const float* cb1 = (const float*)d_in[8];
    const float* cW2 = (const float*)d_in[9];
    const float* cb2 = (const float*)d_in[10];
    const float* cW3 = (const float*)d_in[11];
    const float* cb3 = (const float*)d_in[12];

    float* out        = (float*)d_out;
    float* out_score  = out;                                   // [B,32]
    float* out_trace  = out + NB*ND;                           // [B]
    float* out_cov    = out + NB*ND + NB;                      // [B,1024]
    float* out_covdiv = out + NB*ND + NB + NB*ND*ND;           // [B,32]

    cudaFuncSetAttribute(k_layer2,     cudaFuncAttributeMaxDynamicSharedMemorySize, SMEM_BYTES);
    cudaFuncSetAttribute(k_layer3_cov, cudaFuncAttributeMaxDynamicSharedMemorySize, SMEM_BYTES);
    cudaFuncSetAttribute(k_trace,      cudaFuncAttributeMaxDynamicSharedMemorySize, SMEM_BYTES);
    cudaFuncSetAttribute(k_covdiv,     cudaFuncAttributeMaxDynamicSharedMemorySize, SMEM_BYTES);

    k_precompP<<<NH, NH>>>(sW1, sW2, sW3);
    k_precompQ<<<dim3(ND, 8), NH>>>(cW1, cW2, cW3);
    k_layer1<<<dim3(NB/8, 2), NH>>>(x, sW1, sb1, cW1, cb1);
    k_layer2<<<dim3(NB/32, 2), NH, SMEM_BYTES>>>(sW2, sb2, cW2, cb2);
    k_layer3_score<<<NB/32, NH>>>(sW3, sb3, out_score);
    k_layer3_cov<<<dim3(NB/32, 4), NH, SMEM_BYTES>>>(cW3, cb3, out_cov);
    k_trace<<<NB/32, NH, SMEM_BYTES>>>(out_trace);
    k_covdiv<<<dim3(ND, 16), NH, SMEM_BYTES>>>(out_covdiv);
}

// round 5
// speedup vs baseline: 3.4675x; 1.3769x over previous
#include <cuda_runtime.h>

#define NB 2048
#define ND 32
#define NH 256
#define TSTR 36   // padded smem stride (floats)

// ---------------- scratch (device globals) ----------------
__device__ float g_h1[2][NB*NH];
__device__ float g_g1[2][NB*NH];
__device__ float g_h2[2][NB*NH];
__device__ float g_g2[2][NB*NH];
__device__ float g_P[NH*NH];          // trace bilinear matrix
__device__ float g_Q[ND*NH*NH];       // 32 cov-div bilinear matrices (8 MB)

#define SM_FLOATS (NH*TSTR + 64)
#define SM_BYTES  (SM_FLOATS*4)       // 37120 < 48K default

// ---------------- packed fp32x2 helpers ----------------
static __device__ __forceinline__ unsigned long long pack2(float x, float y){
    unsigned long long r;
    asm("mov.b64 %0, {%1, %2};" : "=l"(r)
        : "r"(__float_as_uint(x)), "r"(__float_as_uint(y)));
    return r;
}
static __device__ __forceinline__ float2 unpack2(unsigned long long v){
    unsigned lo, hi;
    asm("mov.b64 {%0, %1}, %2;" : "=r"(lo), "=r"(hi) : "l"(v));
    return make_float2(__uint_as_float(lo), __uint_as_float(hi));
}
static __device__ __forceinline__ void ffma2(unsigned long long &d,
                                             unsigned long long a,
                                             unsigned long long b){
    asm("fma.rn.f32x2 %0, %1, %2, %0;" : "+l"(d) : "l"(a), "l"(b));
}

// load 32 samples x 256 features, transposed into smem: sm[a*TSTR + s]
static __device__ __forceinline__ void load_tileT(float* sm, const float* g, int b0){
    for (int idx = threadIdx.x; idx < 32*NH; idx += 256){
        int s = idx >> 8;
        int a = idx & 255;
        sm[a*TSTR + s] = g[(b0 + s)*NH + a];
    }
}

// ---------------- streaming GEMM core ----------------
// acc[sp][cc] += sum_a sT[a][sample] * W[a][c]; W streamed by LDG.128.
// Wt pre-offset to this thread's c-quad; sTs pre-offset to this thread's samples.
template<int SP>
static __device__ __forceinline__ void gemm_stream(
    const float* __restrict__ Wt, int wstride,
    const float* __restrict__ sTs,
    unsigned long long (&acc)[SP][4])
{
#pragma unroll 8
    for (int a = 0; a < NH; a++){
        float4 wq = __ldg(reinterpret_cast<const float4*>(Wt + (size_t)a*wstride));
        unsigned long long w0 = pack2(wq.x, wq.x);
        unsigned long long w1 = pack2(wq.y, wq.y);
        unsigned long long w2 = pack2(wq.z, wq.z);
        unsigned long long w3 = pack2(wq.w, wq.w);
        const float* srow = sTs + a*TSTR;
#pragma unroll
        for (int p = 0; p < SP/2; p++){
            ulonglong2 r = *reinterpret_cast<const ulonglong2*>(srow + p*4);
            ffma2(acc[2*p][0],   r.x, w0); ffma2(acc[2*p][1],   r.x, w1);
            ffma2(acc[2*p][2],   r.x, w2); ffma2(acc[2*p][3],   r.x, w3);
            ffma2(acc[2*p+1][0], r.y, w0); ffma2(acc[2*p+1][1], r.y, w1);
            ffma2(acc[2*p+1][2], r.y, w2); ffma2(acc[2*p+1][3], r.y, w3);
        }
    }
}

// ---------------- bilinear epilogue (SP=4, 8 samples/thread) ----------------
static __device__ __forceinline__ void bilinear_reduce_store(
    const float T[8][4], const float* __restrict__ g2row, int b0,
    float* __restrict__ partial, float* __restrict__ outp, int ostride)
{
    int cg = threadIdx.x & 63;
    int sq = threadIdx.x >> 6;
    float val[8];
#pragma unroll
    for (int s = 0; s < 8; s++){
        float4 gq = *reinterpret_cast<const float4*>(&g2row[(b0 + sq*8 + s)*NH + cg*4]);
        val[s] = T[s][0]*gq.x + T[s][1]*gq.y + T[s][2]*gq.z + T[s][3]*gq.w;
    }
#pragma unroll
    for (int off = 16; off; off >>= 1)
#pragma unroll
        for (int s = 0; s < 8; s++)
            val[s] += __shfl_xor_sync(0xffffffffu, val[s], off);
    int w = threadIdx.x >> 5;
    if ((threadIdx.x & 31) == 0){
#pragma unroll
        for (int s = 0; s < 8; s++) partial[w*8 + s] = val[s];
    }
    __syncthreads();
    if (threadIdx.x < 32){
        int sq2 = threadIdx.x >> 3, s = threadIdx.x & 7;
        float v = partial[(2*sq2)*8 + s] + partial[(2*sq2+1)*8 + s];
        outp[(b0 + threadIdx.x)*ostride] = v;
    }
}

// ======================= STAGE A: precompP + precompQ + layer1 =======================
// grid 1024: [0,256) precompP, [256,512) precompQ, [512,1024) layer1
__global__ void __launch_bounds__(256)
k_stageA(const float* __restrict__ x,
         const float* __restrict__ sW1, const float* __restrict__ sb1,
         const float* __restrict__ sW2,
         const float* __restrict__ sW3,
         const float* __restrict__ cW1, const float* __restrict__ cb1,
         const float* __restrict__ cW2,
         const float* __restrict__ cW3)
{
    int bid = blockIdx.x;
    if (bid < 256){
        // ---- precompP: P[a][c] = sW2[a,c] * sum_i sW3[c,i]*sW1[i,a]
        int a = bid;
        int c = threadIdx.x;
        __shared__ float w1[ND];
        if (c < ND) w1[c] = sW1[c*NH + a];
        __syncthreads();
        const float* s3 = sW3 + c*ND;
        float acc = 0.f;
#pragma unroll
        for (int i = 0; i < ND; i++) acc = fmaf(s3[i], w1[i], acc);
        g_P[a*NH + c] = sW2[a*NH + c] * acc;
    } else if (bid < 512){
        // ---- precompQ: Q[i][a][c] = cW2[a,c] * sum_j cW1[j,a]*cW3[c, i*32+j]
        int r  = bid - 256;
        int i  = r & 31;
        int a0 = (r >> 5) * 32;
        int c  = threadIdx.x;
        __shared__ float w1s[ND][33];
        for (int idx = threadIdx.x; idx < ND*32; idx += 256){
            int j = idx >> 5, aa = idx & 31;
            w1s[j][aa] = cW1[j*NH + a0 + aa];
        }
        __syncthreads();
        float w3[ND];
#pragma unroll
        for (int j = 0; j < ND; j++) w3[j] = cW3[c*(ND*ND) + i*ND + j];
#pragma unroll 4
        for (int aa = 0; aa < 32; aa++){
            float acc = 0.f;
#pragma unroll
            for (int j = 0; j < ND; j++) acc = fmaf(w3[j], w1s[j][aa], acc);
            int a = a0 + aa;
            g_Q[(i*NH + a)*NH + c] = cW2[a*NH + c] * acc;
        }
    } else {
        // ---- layer1: h1 = tanh(x@W1+b1), g1 = 1-h1^2
        int r   = bid - 512;
        int net = r >> 8;
        int b0  = (r & 255) * 8;
        const float* W1 = net ? cW1 : sW1;
        const float* b1 = net ? cb1 : sb1;
        int u = threadIdx.x;
        __shared__ float xs[8][ND];
        xs[u >> 5][u & 31] = x[b0*ND + u];
        __syncthreads();
        float acc[8];
        float bias = b1[u];
#pragma unroll
        for (int s = 0; s < 8; s++) acc[s] = bias;
#pragma unroll
        for (int k = 0; k < ND; k++){
            float w = W1[k*NH + u];
#pragma unroll
            for (int s = 0; s < 8; s++) acc[s] = fmaf(xs[s][k], w, acc[s]);
        }
        float* hout = g_h1[net];
        float* gout = g_g1[net];
#pragma unroll
        for (int s = 0; s < 8; s++){
            float h = tanhf(acc[s]);
            hout[(b0+s)*NH + u] = h;
            gout[(b0+s)*NH + u] = 1.0f - h*h;
        }
    }
}

// ======================= STAGE B: layer2 =======================
// grid (64 sample-tiles, 2 c-halves, 2 nets); 32 samples x 128 c per block.
// threads: cg = t&31 (c-quad within half), sq = t>>5 (4-sample group)
__global__ void __launch_bounds__(256, 3)
k_stageB(const float* __restrict__ sW2, const float* __restrict__ sb2,
         const float* __restrict__ cW2, const float* __restrict__ cb2)
{
    extern __shared__ float smemf[];
    float* sT = smemf;
    int net   = blockIdx.z;
    int chalf = blockIdx.y;
    int b0    = blockIdx.x * 32;
    const float* W    = net ? cW2 : sW2;
    const float* bias = net ? cb2 : sb2;
    int cg = threadIdx.x & 31;
    int sq = threadIdx.x >> 5;
    int c0 = chalf*128 + cg*4;

    load_tileT(sT, g_h1[net], b0);
    __syncthreads();

    float4 bq = *reinterpret_cast<const float4*>(&bias[c0]);
    unsigned long long acc[2][4];
    acc[0][0] = pack2(bq.x, bq.x); acc[0][1] = pack2(bq.y, bq.y);
    acc[0][2] = pack2(bq.z, bq.z); acc[0][3] = pack2(bq.w, bq.w);
#pragma unroll
    for (int cc = 0; cc < 4; cc++) acc[1][cc] = acc[0][cc];

    gemm_stream<2>(W + c0, NH, sT + sq*4, acc);

    float* h2 = g_h2[net];
    float* g2 = g_g2[net];
#pragma unroll
    for (int p = 0; p < 2; p++){
#pragma unroll
        for (int half = 0; half < 2; half++){
            // sample index: sq*4 + p*2 + half ; values from acc[p][cc] lane half
            float v[4];
#pragma unroll
            for (int cc = 0; cc < 4; cc++){
                float2 f = unpack2(acc[p][cc]);
                v[cc] = half ? f.y : f.x;
            }
            float4 hv, gv;
            hv.x = tanhf(v[0]); hv.y = tanhf(v[1]);
            hv.z = tanhf(v[2]); hv.w = tanhf(v[3]);
            gv.x = 1.0f - hv.x*hv.x; gv.y = 1.0f - hv.y*hv.y;
            gv.z = 1.0f - hv.z*hv.z; gv.w = 1.0f - hv.w*hv.w;
            int row = (b0 + sq*4 + p*2 + half)*NH + c0;
            *reinterpret_cast<float4*>(&h2[row]) = hv;
            *reinterpret_cast<float4*>(&g2[row]) = gv;
        }
    }
}

// ======================= STAGE C: covdiv + layer3_cov + trace + score =======================
// grid 2432: [0,2048) covdiv, [2048,2304) layer3_cov, [2304,2368) trace, [2368,2432) score
__global__ void __launch_bounds__(256, 3)
k_stageC(const float* __restrict__ cW3, const float* __restrict__ cb3,
         const float* __restrict__ sW3, const float* __restrict__ sb3,
         float* __restrict__ out_score, float* __restrict__ out_trace,
         float* __restrict__ out_cov,   float* __restrict__ out_covdiv)
{
    extern __shared__ float smemf[];
    float* sT      = smemf;
    float* partial = smemf + NH*TSTR;
    int bid = blockIdx.x;
    int cg = threadIdx.x & 63;
    int sq = threadIdx.x >> 6;

    if (bid < 2048){
        // ---- covdiv: i = bid&31, sample group = bid>>5
        int i  = bid & 31;
        int b0 = (bid >> 5) * 32;
        load_tileT(sT, g_g1[1], b0);
        __syncthreads();
        unsigned long long acc[4][4];
#pragma unroll
        for (int sp = 0; sp < 4; sp++)
#pragma unroll
            for (int cc = 0; cc < 4; cc++) acc[sp][cc] = 0ull;
        gemm_stream<4>(g_Q + (size_t)i*NH*NH + cg*4, NH, sT + sq*8, acc);
        float T[8][4];
#pragma unroll
        for (int sp = 0; sp < 4; sp++)
#pragma unroll
            for (int cc = 0; cc < 4; cc++){
                float2 f = unpack2(acc[sp][cc]);
                T[2*sp][cc] = f.x; T[2*sp+1][cc] = f.y;
            }
        bilinear_reduce_store(T, g_g2[1], b0, partial, out_covdiv + i, ND);
    } else if (bid < 2304){
        // ---- layer3_cov: 64 sample-tiles x 4 c-groups of 256
        int r = bid - 2048;
        int b0    = (r >> 2) * 32;
        int cbase = (r & 3) * 256;
        load_tileT(sT, g_h2[1], b0);
        __syncthreads();
        float4 bq = *reinterpret_cast<const float4*>(&cb3[cbase + cg*4]);
        unsigned long long acc[4][4];
#pragma unroll
        for (int sp = 0; sp < 4; sp++){
            acc[sp][0] = pack2(bq.x, bq.x); acc[sp][1] = pack2(bq.y, bq.y);
            acc[sp][2] = pack2(bq.z, bq.z); acc[sp][3] = pack2(bq.w, bq.w);
        }
        gemm_stream<4>(cW3 + cbase + cg*4, ND*ND, sT + sq*8, acc);
#pragma unroll
        for (int sp = 0; sp < 4; sp++){
#pragma unroll
            for (int half = 0; half < 2; half++){
                float4 v;
                float2 f0 = unpack2(acc[sp][0]); float2 f1 = unpack2(acc[sp][1]);
                float2 f2 = unpack2(acc[sp][2]); float2 f3 = unpack2(acc[sp][3]);
                v.x = half ? f0.y : f0.x; v.y = half ? f1.y : f1.x;
                v.z = half ? f2.y : f2.x; v.w = half ? f3.y : f3.x;
                int s = 2*sp + half;
                *reinterpret_cast<float4*>(
                    &out_cov[(b0 + sq*8 + s)*(ND*ND) + cbase + cg*4]) = v;
            }
        }
    } else if (bid < 2368){
        // ---- trace
        int b0 = (bid - 2304) * 32;
        load_tileT(sT, g_g1[0], b0);
        __syncthreads();
        unsigned long long acc[4][4];
#pragma unroll
        for (int sp = 0; sp < 4; sp++)
#pragma unroll
            for (int cc = 0; cc < 4; cc++) acc[sp][cc] = 0ull;
        gemm_stream<4>(g_P + cg*4, NH, sT + sq*8, acc);
        float T[8][4];
#pragma unroll
        for (int sp = 0; sp < 4; sp++)
#pragma unroll
            for (int cc = 0; cc < 4; cc++){
                float2 f = unpack2(acc[sp][cc]);
                T[2*sp][cc] = f.x; T[2*sp+1][cc] = f.y;
            }
        bilinear_reduce_store(T, g_g2[0], b0, partial, out_trace, 1);
    } else {
        // ---- layer3_score: score = h2s@sW3 + sb3
        int b0 = (bid - 2368) * 32;
        int i  = threadIdx.x & 31;
        int sg = threadIdx.x >> 5;
        load_tileT(sT, g_h2[0], b0);
        __syncthreads();
        float acc[4];
        float bias = sb3[i];
#pragma unroll
        for (int k = 0; k < 4; k++) acc[k] = bias;
#pragma unroll 4
        for (int a = 0; a < NH; a++){
            float w = sW3[a*ND + i];
            float4 v = *reinterpret_cast<const float4*>(&sT[a*TSTR + sg*4]);
            acc[0] = fmaf(v.x, w, acc[0]);
            acc[1] = fmaf(v.y, w, acc[1]);
            acc[2] = fmaf(v.z, w, acc[2]);
            acc[3] = fmaf(v.w, w, acc[3]);
        }
#pragma unroll
        for (int k = 0; k < 4; k++)
            out_score[(b0 + sg*4 + k)*ND + i] = acc[k];
    }
}

// ---------------- launch ----------------
extern "C" void kernel_launch(void* const* d_in, const int* in_sizes, int n_in,
                              void* d_out, int out_size){
    const float* x   = (const float*)d_in[0];
    const float* sW1 = (const float*)d_in[1];
    const float* sb1 = (const float*)d_in[2];
    const float* sW2 = (const float*)d_in[3];
    const float* sb2 = (const float*)d_in[4];
    const float* sW3 = (const float*)d_in[5];
    const float* sb3 = (const float*)d_in[6];
    const float* cW1 = (const float*)d_in[7];
    const float* cb1 = (const float*)d_in[8];
    const float* cW2 = (const float*)d_in[9];
    const float* cb2 = (const float*)d_in[10];
    const float* cW3 = (const float*)d_in[11];
    const float* cb3 = (const float*)d_in[12];

    float* out        = (float*)d_out;
    float* out_score  = out;                                   // [B,32]
    float* out_trace  = out + NB*ND;                           // [B]
    float* out_cov    = out + NB*ND + NB;                      // [B,1024]
    float* out_covdiv = out + NB*ND + NB + NB*ND*ND;           // [B,32]

    k_stageA<<<1024, 256>>>(x, sW1, sb1, sW2, sW3, cW1, cb1, cW2, cW3);
    k_stageB<<<dim3(64,2,2), 256, SM_BYTES>>>(sW2, sb2, cW2, cb2);
    k_stageC<<<2432, 256, SM_BYTES>>>(cW3, cb3, sW3, sb3,
                                      out_score, out_trace, out_cov, out_covdiv);
}

// round 10
// speedup vs baseline: 4.7422x; 1.3676x over previous
#include <cuda_runtime.h>
#include <cuda_bf16.h>

#define NB 2048
#define ND 32
#define NH 256
#define TSTR 36   // padded smem stride (floats)

// ---------------- fp32 scratch ----------------
__device__ float g_h1[2][NB*NH];
__device__ float g_g1[2][NB*NH];
__device__ float g_h2[2][NB*NH];
__device__ float g_g2[2][NB*NH];
__device__ float g_P[NH*NH];

// ---------------- bf16 split scratch (cov-net tensor path) ----------------
__device__ __nv_bfloat16 g_g1h[NB*NH], g_g1l[NB*NH];        // gc1 split
__device__ __nv_bfloat16 g_h2h[NB*NH], g_h2l[NB*NH];        // h2c split
__device__ __nv_bfloat16 g_Qth[ND*NH*NH], g_Qtl[ND*NH*NH];  // Qt[i][c][a]
__device__ __nv_bfloat16 g_w3th[ND*ND*NH], g_w3tl[ND*ND*NH];// cW3t[n][a]

#define SM_FLOATS (NH*TSTR + 64)
#define SM_BYTES  (SM_FLOATS*4)

// ---------------- packed fp32x2 helpers ----------------
static __device__ __forceinline__ unsigned long long pack2(float x, float y){
    unsigned long long r;
    asm("mov.b64 %0, {%1, %2};" : "=l"(r)
        : "r"(__float_as_uint(x)), "r"(__float_as_uint(y)));
    return r;
}
static __device__ __forceinline__ float2 unpack2(unsigned long long v){
    unsigned lo, hi;
    asm("mov.b64 {%0, %1}, %2;" : "=r"(lo), "=r"(hi) : "l"(v));
    return make_float2(__uint_as_float(lo), __uint_as_float(hi));
}
static __device__ __forceinline__ void ffma2(unsigned long long &d,
                                             unsigned long long a,
                                             unsigned long long b){
    asm("fma.rn.f32x2 %0, %1, %2, %0;" : "+l"(d) : "l"(a), "l"(b));
}
static __device__ __forceinline__ void bf16split(float v, __nv_bfloat16& hi, __nv_bfloat16& lo){
    hi = __float2bfloat16(v);
    lo = __float2bfloat16(v - __bfloat162float(hi));
}

// load 32 samples x 256 features, transposed into smem: sm[a*TSTR + s]
static __device__ __forceinline__ void load_tileT(float* sm, const float* g, int b0){
    for (int idx = threadIdx.x; idx < 32*NH; idx += 256){
        int s = idx >> 8;
        int a = idx & 255;
        sm[a*TSTR + s] = g[(b0 + s)*NH + a];
    }
}

// ---------------- fp32 streaming GEMM core (trace path) ----------------
template<int SP>
static __device__ __forceinline__ void gemm_stream(
    const float* __restrict__ Wt, int wstride,
    const float* __restrict__ sTs,
    unsigned long long (&acc)[SP][4])
{
#pragma unroll 8
    for (int a = 0; a < NH; a++){
        float4 wq = __ldg(reinterpret_cast<const float4*>(Wt + (size_t)a*wstride));
        unsigned long long w0 = pack2(wq.x, wq.x);
        unsigned long long w1 = pack2(wq.y, wq.y);
        unsigned long long w2 = pack2(wq.z, wq.z);
        unsigned long long w3 = pack2(wq.w, wq.w);
        const float* srow = sTs + a*TSTR;
#pragma unroll
        for (int p = 0; p < SP/2; p++){
            ulonglong2 r = *reinterpret_cast<const ulonglong2*>(srow + p*4);
            ffma2(acc[2*p][0],   r.x, w0); ffma2(acc[2*p][1],   r.x, w1);
            ffma2(acc[2*p][2],   r.x, w2); ffma2(acc[2*p][3],   r.x, w3);
            ffma2(acc[2*p+1][0], r.y, w0); ffma2(acc[2*p+1][1], r.y, w1);
            ffma2(acc[2*p+1][2], r.y, w2); ffma2(acc[2*p+1][3], r.y, w3);
        }
    }
}

static __device__ __forceinline__ void bilinear_reduce_store(
    const float T[8][4], const float* __restrict__ g2row, int b0,
    float* __restrict__ partial, float* __restrict__ outp, int ostride)
{
    int cg = threadIdx.x & 63;
    int sq = threadIdx.x >> 6;
    float val[8];
#pragma unroll
    for (int s = 0; s < 8; s++){
        float4 gq = *reinterpret_cast<const float4*>(&g2row[(b0 + sq*8 + s)*NH + cg*4]);
        val[s] = T[s][0]*gq.x + T[s][1]*gq.y + T[s][2]*gq.z + T[s][3]*gq.w;
    }
#pragma unroll
    for (int off = 16; off; off >>= 1)
#pragma unroll
        for (int s = 0; s < 8; s++)
            val[s] += __shfl_xor_sync(0xffffffffu, val[s], off);
    int w = threadIdx.x >> 5;
    if ((threadIdx.x & 31) == 0){
#pragma unroll
        for (int s = 0; s < 8; s++) partial[w*8 + s] = val[s];
    }
    __syncthreads();
    if (threadIdx.x < 32){
        int sq2 = threadIdx.x >> 3, s = threadIdx.x & 7;
        float v = partial[(2*sq2)*8 + s] + partial[(2*sq2+1)*8 + s];
        outp[(b0 + threadIdx.x)*ostride] = v;
    }
}

// ---------------- mma.sync helper (baseline PTX, works on compute_103) ----------------
static __device__ __forceinline__ void mma16816(float (&c)[4],
    const unsigned (&a)[4], unsigned b0, unsigned b1)
{
    asm volatile("mma.sync.aligned.m16n8k16.row.col.f32.bf16.bf16.f32 "
        "{%0,%1,%2,%3}, {%4,%5,%6,%7}, {%8,%9}, {%0,%1,%2,%3};"
        : "+f"(c[0]), "+f"(c[1]), "+f"(c[2]), "+f"(c[3])
        : "r"(a[0]), "r"(a[1]), "r"(a[2]), "r"(a[3]), "r"(b0), "r"(b1));
}

// ======================= STAGE A =======================
// grid 1056: [0,256) precompP | [256,512) precompQ | [512,1024) layer1 | [1024,1056) cW3 transpose
__global__ void __launch_bounds__(256)
k_stageA(const float* __restrict__ x,
         const float* __restrict__ sW1, const float* __restrict__ sb1,
         const float* __restrict__ sW2,
         const float* __restrict__ sW3,
         const float* __restrict__ cW1, const float* __restrict__ cb1,
         const float* __restrict__ cW2,
         const float* __restrict__ cW3)
{
    __shared__ float sbuf[256*33 + 32*33];
    int bid = blockIdx.x;
    int t = threadIdx.x;
    if (bid < 256){
        // ---- precompP: P[a][c] = sW2[a,c] * sum_i sW3[c,i]*sW1[i,a]
        int a = bid, c = t;
        float* w1 = sbuf;
        if (c < ND) w1[c] = sW1[c*NH + a];
        __syncthreads();
        const float* s3 = sW3 + c*ND;
        float acc = 0.f;
#pragma unroll
        for (int i = 0; i < ND; i++) acc = fmaf(s3[i], w1[i], acc);
        g_P[a*NH + c] = sW2[a*NH + c] * acc;
    } else if (bid < 512){
        // ---- precompQ (coalesced): Qt[i][c][a] = cW2[a,c] * sum_j cW1[j,a]*cW3[c,i*32+j]
        int r  = bid - 256;
        int i  = r & 31;
        int c0 = (r >> 5) * 32;
        float* w2s = sbuf;            // [256][33]
        float* w3s = sbuf + 256*33;   // [32][33]
        for (int idx = t; idx < 256*32; idx += 256){
            int ar = idx >> 5, cc = idx & 31;
            w2s[ar*33 + cc] = cW2[ar*NH + c0 + cc];
        }
        for (int idx = t; idx < 32*32; idx += 256){
            int cr = idx >> 5, j = idx & 31;
            w3s[cr*33 + j] = cW3[(c0 + cr)*(ND*ND) + i*ND + j];
        }
        __syncthreads();
        int a = t;
        float w1r[ND];
#pragma unroll
        for (int j = 0; j < ND; j++) w1r[j] = cW1[j*NH + a];
#pragma unroll 4
        for (int cc = 0; cc < 32; cc++){
            float acc = 0.f;
#pragma unroll
            for (int j = 0; j < ND; j++) acc = fmaf(w1r[j], w3s[cc*33 + j], acc);
            float q = w2s[a*33 + cc] * acc;
            __nv_bfloat16 hi, lo; bf16split(q, hi, lo);
            size_t o = ((size_t)i*NH + c0 + cc)*NH + a;
            g_Qth[o] = hi; g_Qtl[o] = lo;
        }
    } else if (bid < 1024){
        // ---- layer1
        int r   = bid - 512;
        int net = r >> 8;
        int b0  = (r & 255) * 8;
        const float* W1 = net ? cW1 : sW1;
        const float* b1 = net ? cb1 : sb1;
        float* xs = sbuf;   // [8][32]
        xs[t] = x[b0*ND + t];
        __syncthreads();
        float acc[8];
        float bias = b1[t];
#pragma unroll
        for (int s = 0; s < 8; s++) acc[s] = bias;
#pragma unroll
        for (int k = 0; k < ND; k++){
            float w = W1[k*NH + t];
#pragma unroll
            for (int s = 0; s < 8; s++) acc[s] = fmaf(xs[s*32 + k], w, acc[s]);
        }
        float* hout = g_h1[net];
        float* gout = g_g1[net];
#pragma unroll
        for (int s = 0; s < 8; s++){
            float h = tanhf(acc[s]);
            float g = 1.0f - h*h;
            int row = (b0+s)*NH + t;
            hout[row] = h;
            gout[row] = g;
            if (net == 1){
                __nv_bfloat16 hi, lo; bf16split(g, hi, lo);
                g_g1h[row] = hi; g_g1l[row] = lo;
            }
        }
    } else {
        // ---- transpose cW3 -> w3t[n][a] bf16 hi/lo
        int n0 = (bid - 1024) * 32;
        float* s = sbuf;  // [32][33]
        for (int a0 = 0; a0 < NH; a0 += 32){
            __syncthreads();
#pragma unroll
            for (int pp = 0; pp < 4; pp++){
                int ar = (t >> 5) + pp*8, nc = t & 31;
                s[ar*33 + nc] = cW3[(a0 + ar)*(ND*ND) + n0 + nc];
            }
            __syncthreads();
#pragma unroll
            for (int pp = 0; pp < 4; pp++){
                int nn = (t >> 5) + pp*8, aa = t & 31;
                float v = s[aa*33 + nn];
                __nv_bfloat16 hi, lo; bf16split(v, hi, lo);
                size_t o = ((size_t)(n0 + nn))*NH + a0 + aa;
                g_w3th[o] = hi; g_w3tl[o] = lo;
            }
        }
    }
}

// ======================= STAGE B: layer2 =======================
__global__ void __launch_bounds__(256, 3)
k_stageB(const float* __restrict__ sW2, const float* __restrict__ sb2,
         const float* __restrict__ cW2, const float* __restrict__ cb2)
{
    extern __shared__ float smemf[];
    float* sT = smemf;
    int net   = blockIdx.z;
    int chalf = blockIdx.y;
    int b0    = blockIdx.x * 32;
    const float* W    = net ? cW2 : sW2;
    const float* bias = net ? cb2 : sb2;
    int cg = threadIdx.x & 31;
    int sq = threadIdx.x >> 5;
    int c0 = chalf*128 + cg*4;

    load_tileT(sT, g_h1[net], b0);
    __syncthreads();

    float4 bq = *reinterpret_cast<const float4*>(&bias[c0]);
    unsigned long long acc[2][4];
    acc[0][0] = pack2(bq.x, bq.x); acc[0][1] = pack2(bq.y, bq.y);
    acc[0][2] = pack2(bq.z, bq.z); acc[0][3] = pack2(bq.w, bq.w);
#pragma unroll
    for (int cc = 0; cc < 4; cc++) acc[1][cc] = acc[0][cc];

    gemm_stream<2>(W + c0, NH, sT + sq*4, acc);

    float* h2 = g_h2[net];
    float* g2 = g_g2[net];
#pragma unroll
    for (int p = 0; p < 2; p++){
#pragma unroll
        for (int half = 0; half < 2; half++){
            float v[4];
#pragma unroll
            for (int cc = 0; cc < 4; cc++){
                float2 f = unpack2(acc[p][cc]);
                v[cc] = half ? f.y : f.x;
            }
            float4 hv, gv;
            hv.x = tanhf(v[0]); hv.y = tanhf(v[1]);
            hv.z = tanhf(v[2]); hv.w = tanhf(v[3]);
            gv.x = 1.0f - hv.x*hv.x; gv.y = 1.0f - hv.y*hv.y;
            gv.z = 1.0f - hv.z*hv.z; gv.w = 1.0f - hv.w*hv.w;
            int row = (b0 + sq*4 + p*2 + half)*NH + c0;
            *reinterpret_cast<float4*>(&h2[row]) = hv;
            *reinterpret_cast<float4*>(&g2[row]) = gv;
            if (net == 1){
                __nv_bfloat16 hi, lo;
                bf16split(hv.x, hi, lo); g_h2h[row+0] = hi; g_h2l[row+0] = lo;
                bf16split(hv.y, hi, lo); g_h2h[row+1] = hi; g_h2l[row+1] = lo;
                bf16split(hv.z, hi, lo); g_h2h[row+2] = hi; g_h2l[row+2] = lo;
                bf16split(hv.w, hi, lo); g_h2h[row+3] = hi; g_h2l[row+3] = lo;
            }
        }
    }
}

// ======================= STAGE C: trace + score (fp32) =======================
// grid 128: [0,64) trace, [64,128) score
__global__ void __launch_bounds__(256, 3)
k_stageC(const float* __restrict__ sW3, const float* __restrict__ sb3,
         float* __restrict__ out_score, float* __restrict__ out_trace)
{
    extern __shared__ float smemf[];
    float* sT      = smemf;
    float* partial = smemf + NH*TSTR;
    int bid = blockIdx.x;
    int cg = threadIdx.x & 63;
    int sq = threadIdx.x >> 6;

    if (bid < 64){
        int b0 = bid * 32;
        load_tileT(sT, g_g1[0], b0);
        __syncthreads();
        unsigned long long acc[4][4];
#pragma unroll
        for (int sp = 0; sp < 4; sp++)
#pragma unroll
            for (int cc = 0; cc < 4; cc++) acc[sp][cc] = 0ull;
        gemm_stream<4>(g_P + cg*4, NH, sT + sq*8, acc);
        float T[8][4];
#pragma unroll
        for (int sp = 0; sp < 4; sp++)
#pragma unroll
            for (int cc = 0; cc < 4; cc++){
                float2 f = unpack2(acc[sp][cc]);
                T[2*sp][cc] = f.x; T[2*sp+1][cc] = f.y;
            }
        bilinear_reduce_store(T, g_g2[0], b0, partial, out_trace, 1);
    } else {
        int b0 = (bid - 64) * 32;
        int i  = threadIdx.x & 31;
        int sg = threadIdx.x >> 5;
        load_tileT(sT, g_h2[0], b0);
        __syncthreads();
        float acc[4];
        float bias = sb3[i];
#pragma unroll
        for (int k = 0; k < 4; k++) acc[k] = bias;
#pragma unroll 4
        for (int a = 0; a < NH; a++){
            float w = sW3[a*ND + i];
            float4 v = *reinterpret_cast<const float4*>(&sT[a*TSTR + sg*4]);
            acc[0] = fmaf(v.x, w, acc[0]);
            acc[1] = fmaf(v.y, w, acc[1]);
            acc[2] = fmaf(v.z, w, acc[2]);
            acc[3] = fmaf(v.w, w, acc[3]);
        }
#pragma unroll
        for (int k = 0; k < 4; k++)
            out_score[(b0 + sg*4 + k)*ND + i] = acc[k];
    }
}

// ======================= TENSOR (mma.sync) KERNEL: covdiv + layer3_cov ==============
// grid 576: [0,512) covdiv (i=bid&31, mt=bid>>5); [512,576) l3cov (nt=(r&3), mt=r>>2)
// 512 threads = 16 warps (4 m x 4 n); block tile M=128, N=256, K chunk 32.
// smem bf16 tiles, stride 40 (80B, 16B-aligned, conflict-free frag loads).
#define KC   32
#define KSTR 40
#define SA_ELEM (128*KSTR)          // per A buffer
#define SB_ELEM (256*KSTR)          // per B buffer
#define MM_SMEM ((2*SA_ELEM + 2*SB_ELEM)*2)   // bytes = 61440

__global__ void __launch_bounds__(512)
k_mma(const float* __restrict__ cb3,
      float* __restrict__ out_cov, float* __restrict__ out_covdiv)
{
    extern __shared__ __nv_bfloat16 smb[];
    __nv_bfloat16* sAh = smb;
    __nv_bfloat16* sAl = sAh + SA_ELEM;
    __nv_bfloat16* sBh = sAl + SA_ELEM;
    __nv_bfloat16* sBl = sBh + SB_ELEM;

    int t = threadIdx.x, lane = t & 31, wid = t >> 5;
    int wm = wid & 3, wn = wid >> 2;       // 4x4 warp grid
    int g = lane >> 2, tig = lane & 3;
    int bid = blockIdx.x;
    bool is_cd = bid < 512;

    const __nv_bfloat16 *Ah, *Al, *Bh, *Bl;
    int m0;
    if (is_cd){
        int i = bid & 31; m0 = (bid >> 5)*128;
        Ah = g_g1h; Al = g_g1l;
        Bh = g_Qth + (size_t)i*NH*NH; Bl = g_Qtl + (size_t)i*NH*NH;
    } else {
        int r = bid - 512; m0 = (r >> 2)*128;
        Ah = g_h2h; Al = g_h2l;
        Bh = g_w3th + (size_t)(r & 3)*256*NH; Bl = g_w3tl + (size_t)(r & 3)*256*NH;
    }

    float c[2][8][4];
#pragma unroll
    for (int mi = 0; mi < 2; mi++)
#pragma unroll
        for (int ni = 0; ni < 8; ni++)
#pragma unroll
            for (int q = 0; q < 4; q++) c[mi][ni][q] = 0.f;

    // staging indices
    int ar = t >> 2, aq = t & 3;                  // A: 512 uint4 per buffer

#pragma unroll 1
    for (int kc = 0; kc < NH/KC; kc++){
        int k0 = kc*KC;
        __syncthreads();
        // stage A (hi/lo): row ar, 8-bf16 quad aq
        *reinterpret_cast<uint4*>(sAh + ar*KSTR + aq*8) =
            *reinterpret_cast<const uint4*>(Ah + (size_t)(m0 + ar)*NH + k0 + aq*8);
        *reinterpret_cast<uint4*>(sAl + ar*KSTR + aq*8) =
            *reinterpret_cast<const uint4*>(Al + (size_t)(m0 + ar)*NH + k0 + aq*8);
        // stage B (hi/lo): 1024 uint4 per buffer -> 2 per thread
#pragma unroll
        for (int p = 0; p < 2; p++){
            int idx = t + p*512;
            int br = idx >> 2, bq = idx & 3;
            *reinterpret_cast<uint4*>(sBh + br*KSTR + bq*8) =
                *reinterpret_cast<const uint4*>(Bh + (size_t)br*NH + k0 + bq*8);
            *reinterpret_cast<uint4*>(sBl + br*KSTR + bq*8) =
                *reinterpret_cast<const uint4*>(Bl + (size_t)br*NH + k0 + bq*8);
        }
        __syncthreads();

#pragma unroll
        for (int ks = 0; ks < KC/16; ks++){
            int kk = ks*16 + tig*2;
            unsigned a_hi[2][4], a_lo[2][4];
#pragma unroll
            for (int mi = 0; mi < 2; mi++){
                const __nv_bfloat16* b0p = sAh + (wm*32 + mi*16 + g)*KSTR + kk;
                const __nv_bfloat16* b1p = sAh + (wm*32 + mi*16 + g + 8)*KSTR + kk;
                a_hi[mi][0] = *reinterpret_cast<const unsigned*>(b0p);
                a_hi[mi][1] = *reinterpret_cast<const unsigned*>(b1p);
                a_hi[mi][2] = *reinterpret_cast<const unsigned*>(b0p + 8);
                a_hi[mi][3] = *reinterpret_cast<const unsigned*>(b1p + 8);
                const __nv_bfloat16* c0p = sAl + (wm*32 + mi*16 + g)*KSTR + kk;
                const __nv_bfloat16* c1p = sAl + (wm*32 + mi*16 + g + 8)*KSTR + kk;
                a_lo[mi][0] = *reinterpret_cast<const unsigned*>(c0p);
                a_lo[mi][1] = *reinterpret_cast<const unsigned*>(c1p);
                a_lo[mi][2] = *reinterpret_cast<const unsigned*>(c0p + 8);
                a_lo[mi][3] = *reinterpret_cast<const unsigned*>(c1p + 8);
            }
#pragma unroll
            for (int ni = 0; ni < 8; ni++){
                const __nv_bfloat16* bhp = sBh + (wn*64 + ni*8 + g)*KSTR + kk;
                const __nv_bfloat16* blp = sBl + (wn*64 + ni*8 + g)*KSTR + kk;
                unsigned bh0 = *reinterpret_cast<const unsigned*>(bhp);
                unsigned bh1 = *reinterpret_cast<const unsigned*>(bhp + 8);
                unsigned bl0 = *reinterpret_cast<const unsigned*>(blp);
                unsigned bl1 = *reinterpret_cast<const unsigned*>(blp + 8);
#pragma unroll
                for (int mi = 0; mi < 2; mi++){
                    mma16816(c[mi][ni], a_hi[mi], bh0, bh1);
                    mma16816(c[mi][ni], a_hi[mi], bl0, bl1);
                    mma16816(c[mi][ni], a_lo[mi], bh0, bh1);
                }
            }
        }
    }
    __syncthreads();

    if (is_cd){
        int i = bid & 31;
        // rows owned: wm*32 + mi*16 + g (+8)
        float rs[4];
#pragma unroll
        for (int mi = 0; mi < 2; mi++){
#pragma unroll
            for (int hf = 0; hf < 2; hf++){
                int m = m0 + wm*32 + mi*16 + g + hf*8;
                const float* g2r = g_g2[1] + (size_t)m*NH;
                float s = 0.f;
#pragma unroll
                for (int ni = 0; ni < 8; ni++){
                    int col = wn*64 + ni*8 + tig*2;
                    float2 gg = *reinterpret_cast<const float2*>(g2r + col);
                    s += c[mi][ni][hf*2+0]*gg.x + c[mi][ni][hf*2+1]*gg.y;
                }
                rs[mi*2+hf] = s;
            }
        }
#pragma unroll
        for (int off = 1; off < 4; off <<= 1)
#pragma unroll
            for (int q = 0; q < 4; q++)
                rs[q] += __shfl_xor_sync(0xffffffffu, rs[q], off);
        float* red = reinterpret_cast<float*>(smb);   // [4 wn][128]
        if (tig == 0){
#pragma unroll
            for (int mi = 0; mi < 2; mi++)
#pragma unroll
                for (int hf = 0; hf < 2; hf++)
                    red[wn*128 + wm*32 + mi*16 + g + hf*8] = rs[mi*2+hf];
        }
        __syncthreads();
        if (t < 128){
            float v = red[t] + red[128+t] + red[256+t] + red[384+t];
            out_covdiv[(size_t)(m0 + t)*ND + i] = v;
        }
    } else {
        int n0 = ((bid - 512) & 3)*256;
#pragma unroll
        for (int mi = 0; mi < 2; mi++){
#pragma unroll
            for (int hf = 0; hf < 2; hf++){
                int m = m0 + wm*32 + mi*16 + g + hf*8;
#pragma unroll
                for (int ni = 0; ni < 8; ni++){
                    int col = n0 + wn*64 + ni*8 + tig*2;
                    float2 b = *reinterpret_cast<const float2*>(cb3 + col);
                    float2 v;
                    v.x = c[mi][ni][hf*2+0] + b.x;
                    v.y = c[mi][ni][hf*2+1] + b.y;
                    *reinterpret_cast<float2*>(out_cov + (size_t)m*(ND*ND) + col) = v;
                }
            }
        }
    }
}

// ---------------- launch ----------------
extern "C" void kernel_launch(void* const* d_in, const int* in_sizes, int n_in,
                              void* d_out, int out_size){
    const float* x   = (const float*)d_in[0];
    const float* sW1 = (const float*)d_in[1];
    const float* sb1 = (const float*)d_in[2];
    const float* sW2 = (const float*)d_in[3];
    const float* sb2 = (const float*)d_in[4];
    const float* sW3 = (const float*)d_in[5];
    const float* sb3 = (const float*)d_in[6];
    const float* cW1 = (const float*)d_in[7];
    const float* cb1 = (const float*)d_in[8];
    const float* cW2 = (const float*)d_in[9];
    const float* cb2 = (const float*)d_in[10];
    const float* cW3 = (const float*)d_in[11];
    const float* cb3 = (const float*)d_in[12];

    float* out        = (float*)d_out;
    float* out_score  = out;                                   // [B,32]
    float* out_trace  = out + NB*ND;                           // [B]
    float* out_cov    = out + NB*ND + NB;                      // [B,1024]
    float* out_covdiv = out + NB*ND + NB + NB*ND*ND;           // [B,32]

    static int inited = 0;
    if (!inited){
        cudaFuncSetAttribute(k_mma, cudaFuncAttributeMaxDynamicSharedMemorySize, MM_SMEM);
        inited = 1;
    }

    k_stageA<<<1056, 256>>>(x, sW1, sb1, sW2, sW3, cW1, cb1, cW2, cW3);
    k_stageB<<<dim3(64,2,2), 256, SM_BYTES>>>(sW2, sb2, cW2, cb2);
    k_stageC<<<128, 256, SM_BYTES>>>(sW3, sb3, out_score, out_trace);
    k_mma<<<576, 512, MM_SMEM>>>(cb3, out_cov, out_covdiv);
}

// round 11
// speedup vs baseline: 4.9689x; 1.0478x over previous
#include <cuda_runtime.h>
#include <cuda_bf16.h>

#define NB 2048
#define ND 32
#define NH 256
#define TSTR 36   // padded smem stride (floats)

// ---------------- fp32 scratch ----------------
__device__ float g_h1[2][NB*NH];
__device__ float g_g1[2][NB*NH];
__device__ float g_h2[2][NB*NH];
__device__ float g_g2[2][NB*NH];
__device__ float g_P[NH*NH];

// ---------------- bf16 split scratch (cov-net tensor path) ----------------
__device__ __nv_bfloat16 g_g1h[NB*NH], g_g1l[NB*NH];        // gc1 split
__device__ __nv_bfloat16 g_h2h[NB*NH], g_h2l[NB*NH];        // h2c split
__device__ __nv_bfloat16 g_Qth[ND*NH*NH], g_Qtl[ND*NH*NH];  // Qt[i][c][a]
__device__ __nv_bfloat16 g_w3th[ND*ND*NH], g_w3tl[ND*ND*NH];// cW3t[n][a]

#define SM_FLOATS (NH*TSTR + 64)
#define SM_BYTES  (SM_FLOATS*4)

// ---------------- packed fp32x2 helpers ----------------
static __device__ __forceinline__ unsigned long long pack2(float x, float y){
    unsigned long long r;
    asm("mov.b64 %0, {%1, %2};" : "=l"(r)
        : "r"(__float_as_uint(x)), "r"(__float_as_uint(y)));
    return r;
}
static __device__ __forceinline__ float2 unpack2(unsigned long long v){
    unsigned lo, hi;
    asm("mov.b64 {%0, %1}, %2;" : "=r"(lo), "=r"(hi) : "l"(v));
    return make_float2(__uint_as_float(lo), __uint_as_float(hi));
}
static __device__ __forceinline__ void ffma2(unsigned long long &d,
                                             unsigned long long a,
                                             unsigned long long b){
    asm("fma.rn.f32x2 %0, %1, %2, %0;" : "+l"(d) : "l"(a), "l"(b));
}
static __device__ __forceinline__ void bf16split(float v, __nv_bfloat16& hi, __nv_bfloat16& lo){
    hi = __float2bfloat16(v);
    lo = __float2bfloat16(v - __bfloat162float(hi));
}

// load 32 samples x 256 features, transposed into smem: sm[a*TSTR + s]
static __device__ __forceinline__ void load_tileT(float* sm, const float* g, int b0){
    for (int idx = threadIdx.x; idx < 32*NH; idx += 256){
        int s = idx >> 8;
        int a = idx & 255;
        sm[a*TSTR + s] = g[(b0 + s)*NH + a];
    }
}

// ---------------- fp32 streaming GEMM core (trace path) ----------------
template<int SP>
static __device__ __forceinline__ void gemm_stream(
    const float* __restrict__ Wt, int wstride,
    const float* __restrict__ sTs,
    unsigned long long (&acc)[SP][4])
{
#pragma unroll 8
    for (int a = 0; a < NH; a++){
        float4 wq = __ldg(reinterpret_cast<const float4*>(Wt + (size_t)a*wstride));
        unsigned long long w0 = pack2(wq.x, wq.x);
        unsigned long long w1 = pack2(wq.y, wq.y);
        unsigned long long w2 = pack2(wq.z, wq.z);
        unsigned long long w3 = pack2(wq.w, wq.w);
        const float* srow = sTs + a*TSTR;
#pragma unroll
        for (int p = 0; p < SP/2; p++){
            ulonglong2 r = *reinterpret_cast<const ulonglong2*>(srow + p*4);
            ffma2(acc[2*p][0],   r.x, w0); ffma2(acc[2*p][1],   r.x, w1);
            ffma2(acc[2*p][2],   r.x, w2); ffma2(acc[2*p][3],   r.x, w3);
            ffma2(acc[2*p+1][0], r.y, w0); ffma2(acc[2*p+1][1], r.y, w1);
            ffma2(acc[2*p+1][2], r.y, w2); ffma2(acc[2*p+1][3], r.y, w3);
        }
    }
}

static __device__ __forceinline__ void bilinear_reduce_store(
    const float T[8][4], const float* __restrict__ g2row, int b0,
    float* __restrict__ partial, float* __restrict__ outp, int ostride)
{
    int cg = threadIdx.x & 63;
    int sq = threadIdx.x >> 6;
    float val[8];
#pragma unroll
    for (int s = 0; s < 8; s++){
        float4 gq = *reinterpret_cast<const float4*>(&g2row[(b0 + sq*8 + s)*NH + cg*4]);
        val[s] = T[s][0]*gq.x + T[s][1]*gq.y + T[s][2]*gq.z + T[s][3]*gq.w;
    }
#pragma unroll
    for (int off = 16; off; off >>= 1)
#pragma unroll
        for (int s = 0; s < 8; s++)
            val[s] += __shfl_xor_sync(0xffffffffu, val[s], off);
    int w = threadIdx.x >> 5;
    if ((threadIdx.x & 31) == 0){
#pragma unroll
        for (int s = 0; s < 8; s++) partial[w*8 + s] = val[s];
    }
    __syncthreads();
    if (threadIdx.x < 32){
        int sq2 = threadIdx.x >> 3, s = threadIdx.x & 7;
        float v = partial[(2*sq2)*8 + s] + partial[(2*sq2+1)*8 + s];
        outp[(b0 + threadIdx.x)*ostride] = v;
    }
}

// ---------------- mma.sync / ldmatrix / cp.async helpers (baseline PTX) -------------
static __device__ __forceinline__ void mma16816(float (&c)[4],
    const unsigned (&a)[4], unsigned b0, unsigned b1)
{
    asm volatile("mma.sync.aligned.m16n8k16.row.col.f32.bf16.bf16.f32 "
        "{%0,%1,%2,%3}, {%4,%5,%6,%7}, {%8,%9}, {%0,%1,%2,%3};"
        : "+f"(c[0]), "+f"(c[1]), "+f"(c[2]), "+f"(c[3])
        : "r"(a[0]), "r"(a[1]), "r"(a[2]), "r"(a[3]), "r"(b0), "r"(b1));
}
static __device__ __forceinline__ void ldsm4(unsigned (&r)[4], unsigned addr){
    asm volatile("ldmatrix.sync.aligned.m8n8.x4.shared.b16 {%0,%1,%2,%3}, [%4];"
        : "=r"(r[0]), "=r"(r[1]), "=r"(r[2]), "=r"(r[3]) : "r"(addr));
}
static __device__ __forceinline__ void cpa16(unsigned saddr, const void* g){
    asm volatile("cp.async.cg.shared.global [%0], [%1], 16;" :: "r"(saddr), "l"(g));
}
static __device__ __forceinline__ void cpa_commit(){
    asm volatile("cp.async.commit_group;" ::: "memory");
}
template<int N>
static __device__ __forceinline__ void cpa_wait(){
    asm volatile("cp.async.wait_group %0;" :: "n"(N) : "memory");
}

// ======================= STAGE A =======================
// grid 1056: [0,256) precompP | [256,512) precompQ | [512,1024) layer1 | [1024,1056) cW3 transpose
__global__ void __launch_bounds__(256)
k_stageA(const float* __restrict__ x,
         const float* __restrict__ sW1, const float* __restrict__ sb1,
         const float* __restrict__ sW2,
         const float* __restrict__ sW3,
         const float* __restrict__ cW1, const float* __restrict__ cb1,
         const float* __restrict__ cW2,
         const float* __restrict__ cW3)
{
    __shared__ float sbuf[256*33 + 32*33];
    int bid = blockIdx.x;
    int t = threadIdx.x;
    if (bid < 256){
        int a = bid, c = t;
        float* w1 = sbuf;
        if (c < ND) w1[c] = sW1[c*NH + a];
        __syncthreads();
        const float* s3 = sW3 + c*ND;
        float acc = 0.f;
#pragma unroll
        for (int i = 0; i < ND; i++) acc = fmaf(s3[i], w1[i], acc);
        g_P[a*NH + c] = sW2[a*NH + c] * acc;
    } else if (bid < 512){
        int r  = bid - 256;
        int i  = r & 31;
        int c0 = (r >> 5) * 32;
        float* w2s = sbuf;            // [256][33]
        float* w3s = sbuf + 256*33;   // [32][33]
        for (int idx = t; idx < 256*32; idx += 256){
            int ar = idx >> 5, cc = idx & 31;
            w2s[ar*33 + cc] = cW2[ar*NH + c0 + cc];
        }
        for (int idx = t; idx < 32*32; idx += 256){
            int cr = idx >> 5, j = idx & 31;
            w3s[cr*33 + j] = cW3[(c0 + cr)*(ND*ND) + i*ND + j];
        }
        __syncthreads();
        int a = t;
        float w1r[ND];
#pragma unroll
        for (int j = 0; j < ND; j++) w1r[j] = cW1[j*NH + a];
#pragma unroll 4
        for (int cc = 0; cc < 32; cc++){
            float acc = 0.f;
#pragma unroll
            for (int j = 0; j < ND; j++) acc = fmaf(w1r[j], w3s[cc*33 + j], acc);
            float q = w2s[a*33 + cc] * acc;
            __nv_bfloat16 hi, lo; bf16split(q, hi, lo);
            size_t o = ((size_t)i*NH + c0 + cc)*NH + a;
            g_Qth[o] = hi; g_Qtl[o] = lo;
        }
    } else if (bid < 1024){
        int r   = bid - 512;
        int net = r >> 8;
        int b0  = (r & 255) * 8;
        const float* W1 = net ? cW1 : sW1;
        const float* b1 = net ? cb1 : sb1;
        float* xs = sbuf;   // [8][32]
        xs[t] = x[b0*ND + t];
        __syncthreads();
        float acc[8];
        float bias = b1[t];
#pragma unroll
        for (int s = 0; s < 8; s++) acc[s] = bias;
#pragma unroll
        for (int k = 0; k < ND; k++){
            float w = W1[k*NH + t];
#pragma unroll
            for (int s = 0; s < 8; s++) acc[s] = fmaf(xs[s*32 + k], w, acc[s]);
        }
        float* hout = g_h1[net];
        float* gout = g_g1[net];
#pragma unroll
        for (int s = 0; s < 8; s++){
            float h = tanhf(acc[s]);
            float g = 1.0f - h*h;
            int row = (b0+s)*NH + t;
            hout[row] = h;
            gout[row] = g;
            if (net == 1){
                __nv_bfloat16 hi, lo; bf16split(g, hi, lo);
                g_g1h[row] = hi; g_g1l[row] = lo;
            }
        }
    } else {
        int n0 = (bid - 1024) * 32;
        float* s = sbuf;  // [32][33]
        for (int a0 = 0; a0 < NH; a0 += 32){
            __syncthreads();
#pragma unroll
            for (int pp = 0; pp < 4; pp++){
                int ar = (t >> 5) + pp*8, nc = t & 31;
                s[ar*33 + nc] = cW3[(a0 + ar)*(ND*ND) + n0 + nc];
            }
            __syncthreads();
#pragma unroll
            for (int pp = 0; pp < 4; pp++){
                int nn = (t >> 5) + pp*8, aa = t & 31;
                float v = s[aa*33 + nn];
                __nv_bfloat16 hi, lo; bf16split(v, hi, lo);
                size_t o = ((size_t)(n0 + nn))*NH + a0 + aa;
                g_w3th[o] = hi; g_w3tl[o] = lo;
            }
        }
    }
}

// ======================= STAGE B: layer2 =======================
__global__ void __launch_bounds__(256, 3)
k_stageB(const float* __restrict__ sW2, const float* __restrict__ sb2,
         const float* __restrict__ cW2, const float* __restrict__ cb2)
{
    extern __shared__ float smemf[];
    float* sT = smemf;
    int net   = blockIdx.z;
    int chalf = blockIdx.y;
    int b0    = blockIdx.x * 32;
    const float* W    = net ? cW2 : sW2;
    const float* bias = net ? cb2 : sb2;
    int cg = threadIdx.x & 31;
    int sq = threadIdx.x >> 5;
    int c0 = chalf*128 + cg*4;

    load_tileT(sT, g_h1[net], b0);
    __syncthreads();

    float4 bq = *reinterpret_cast<const float4*>(&bias[c0]);
    unsigned long long acc[2][4];
    acc[0][0] = pack2(bq.x, bq.x); acc[0][1] = pack2(bq.y, bq.y);
    acc[0][2] = pack2(bq.z, bq.z); acc[0][3] = pack2(bq.w, bq.w);
#pragma unroll
    for (int cc = 0; cc < 4; cc++) acc[1][cc] = acc[0][cc];

    gemm_stream<2>(W + c0, NH, sT + sq*4, acc);

    float* h2 = g_h2[net];
    float* g2 = g_g2[net];
#pragma unroll
    for (int p = 0; p < 2; p++){
#pragma unroll
        for (int half = 0; half < 2; half++){
            float v[4];
#pragma unroll
            for (int cc = 0; cc < 4; cc++){
                float2 f = unpack2(acc[p][cc]);
                v[cc] = half ? f.y : f.x;
            }
            float4 hv, gv;
            hv.x = tanhf(v[0]); hv.y = tanhf(v[1]);
            hv.z = tanhf(v[2]); hv.w = tanhf(v[3]);
            gv.x = 1.0f - hv.x*hv.x; gv.y = 1.0f - hv.y*hv.y;
            gv.z = 1.0f - hv.z*hv.z; gv.w = 1.0f - hv.w*hv.w;
            int row = (b0 + sq*4 + p*2 + half)*NH + c0;
            *reinterpret_cast<float4*>(&h2[row]) = hv;
            *reinterpret_cast<float4*>(&g2[row]) = gv;
            if (net == 1){
                __nv_bfloat16 hi, lo;
                bf16split(hv.x, hi, lo); g_h2h[row+0] = hi; g_h2l[row+0] = lo;
                bf16split(hv.y, hi, lo); g_h2h[row+1] = hi; g_h2l[row+1] = lo;
                bf16split(hv.z, hi, lo); g_h2h[row+2] = hi; g_h2l[row+2] = lo;
                bf16split(hv.w, hi, lo); g_h2h[row+3] = hi; g_h2l[row+3] = lo;
            }
        }
    }
}

// ======================= STAGE C: trace + score (fp32) =======================
__global__ void __launch_bounds__(256, 3)
k_stageC(const float* __restrict__ sW3, const float* __restrict__ sb3,
         float* __restrict__ out_score, float* __restrict__ out_trace)
{
    extern __shared__ float smemf[];
    float* sT      = smemf;
    float* partial = smemf + NH*TSTR;
    int bid = blockIdx.x;
    int cg = threadIdx.x & 63;
    int sq = threadIdx.x >> 6;

    if (bid < 64){
        int b0 = bid * 32;
        load_tileT(sT, g_g1[0], b0);
        __syncthreads();
        unsigned long long acc[4][4];
#pragma unroll
        for (int sp = 0; sp < 4; sp++)
#pragma unroll
            for (int cc = 0; cc < 4; cc++) acc[sp][cc] = 0ull;
        gemm_stream<4>(g_P + cg*4, NH, sT + sq*8, acc);
        float T[8][4];
#pragma unroll
        for (int sp = 0; sp < 4; sp++)
#pragma unroll
            for (int cc = 0; cc < 4; cc++){
                float2 f = unpack2(acc[sp][cc]);
                T[2*sp][cc] = f.x; T[2*sp+1][cc] = f.y;
            }
        bilinear_reduce_store(T, g_g2[0], b0, partial, out_trace, 1);
    } else {
        int b0 = (bid - 64) * 32;
        int i  = threadIdx.x & 31;
        int sg = threadIdx.x >> 5;
        load_tileT(sT, g_h2[0], b0);
        __syncthreads();
        float acc[4];
        float bias = sb3[i];
#pragma unroll
        for (int k = 0; k < 4; k++) acc[k] = bias;
#pragma unroll 4
        for (int a = 0; a < NH; a++){
            float w = sW3[a*ND + i];
            float4 v = *reinterpret_cast<const float4*>(&sT[a*TSTR + sg*4]);
            acc[0] = fmaf(v.x, w, acc[0]);
            acc[1] = fmaf(v.y, w, acc[1]);
            acc[2] = fmaf(v.z, w, acc[2]);
            acc[3] = fmaf(v.w, w, acc[3]);
        }
#pragma unroll
        for (int k = 0; k < 4; k++)
            out_score[(b0 + sg*4 + k)*ND + i] = acc[k];
    }
}

// ======================= TENSOR (mma.sync) KERNEL: covdiv + layer3_cov ==============
// grid 576; 512 threads = 16 warps (4m x 4n); tile M=128 N=256, K chunk 32.
// Double-buffered cp.async staging + ldmatrix fragment loads.
#define KC    32
#define KSTR  40
#define SA_E  (128*KSTR)            // 5120 elems (10 KB)
#define SB_E  (256*KSTR)            // 10240 elems (20 KB)
#define STG_E (2*SA_E + 2*SB_E)     // per stage elems (60 KB)
#define MM_SMEM (2*STG_E*2)         // bytes = 122880

__global__ void __launch_bounds__(512)
k_mma(const float* __restrict__ cb3,
      float* __restrict__ out_cov, float* __restrict__ out_covdiv)
{
    extern __shared__ __nv_bfloat16 smb[];
    unsigned smu = (unsigned)__cvta_generic_to_shared(smb);

    int t = threadIdx.x, lane = t & 31, wid = t >> 5;
    int wm = wid & 3, wn = wid >> 2;       // 4x4 warp grid
    int g = lane >> 2, tig = lane & 3;
    int bid = blockIdx.x;
    bool is_cd = bid < 512;

    const __nv_bfloat16 *Ah, *Al, *Bh, *Bl;
    int m0;
    if (is_cd){
        int i = bid & 31; m0 = (bid >> 5)*128;
        Ah = g_g1h; Al = g_g1l;
        Bh = g_Qth + (size_t)i*NH*NH; Bl = g_Qtl + (size_t)i*NH*NH;
    } else {
        int r = bid - 512; m0 = (r >> 2)*128;
        Ah = g_h2h; Al = g_h2l;
        Bh = g_w3th + (size_t)(r & 3)*256*NH; Bl = g_w3tl + (size_t)(r & 3)*256*NH;
    }

    float c[2][8][4];
#pragma unroll
    for (int mi = 0; mi < 2; mi++)
#pragma unroll
        for (int ni = 0; ni < 8; ni++)
#pragma unroll
            for (int q = 0; q < 4; q++) c[mi][ni][q] = 0.f;

    // ldmatrix per-lane offsets (bf16 elements within tile)
    int lrow = lane & 7, sel = lane >> 3;
    int aoff = ((sel & 1)*8 + lrow)*KSTR + (sel >> 1)*8;      // A: r0=a0,r1=a1,r2=a2,r3=a3
    int boff = ((sel >> 1)*8 + lrow)*KSTR + (sel & 1)*8;      // B: r0=b0(n),r1=b1(n),r2=b0(n+8),r3=b1(n+8)

    // staging indices: A 512 x 16B per buf (1/thread), B 1024 x 16B (2/thread)
    int ar = t >> 2, aq = t & 3;

    // stage(chunk kc, stage s)
    auto stage = [&](int kc, int s){
        int k0 = kc*KC;
        unsigned base = smu + (unsigned)s*STG_E*2;
        unsigned dAh = base + (ar*KSTR + aq*8)*2;
        cpa16(dAh,            Ah + (size_t)(m0 + ar)*NH + k0 + aq*8);
        cpa16(dAh + SA_E*2,   Al + (size_t)(m0 + ar)*NH + k0 + aq*8);
#pragma unroll
        for (int p = 0; p < 2; p++){
            int idx = t + p*512;
            int br = idx >> 2, bq = idx & 3;
            unsigned dBh = base + (2*SA_E + br*KSTR + bq*8)*2;
            cpa16(dBh,          Bh + (size_t)br*NH + k0 + bq*8);
            cpa16(dBh + SB_E*2, Bl + (size_t)br*NH + k0 + bq*8);
        }
        cpa_commit();
    };

    stage(0, 0);

#pragma unroll 1
    for (int kc = 0; kc < NH/KC; kc++){
        if (kc + 1 < NH/KC) stage(kc+1, (kc+1)&1);
        if (kc + 1 < NH/KC) cpa_wait<1>(); else cpa_wait<0>();
        __syncthreads();

        unsigned base = smu + (unsigned)(kc&1)*STG_E*2;
        unsigned aAh = base + (wm*32*KSTR + aoff)*2;
        unsigned aAl = aAh + SA_E*2;
        unsigned aBh = base + (2*SA_E + wn*64*KSTR + boff)*2;
        unsigned aBl = aBh + SB_E*2;

#pragma unroll
        for (int ks = 0; ks < KC/16; ks++){
            unsigned kofs = (unsigned)(ks*16)*2;
            unsigned ah[2][4], al[2][4];
#pragma unroll
            for (int mi = 0; mi < 2; mi++){
                ldsm4(ah[mi], aAh + (unsigned)(mi*16*KSTR)*2 + kofs);
                ldsm4(al[mi], aAl + (unsigned)(mi*16*KSTR)*2 + kofs);
            }
#pragma unroll
            for (int p = 0; p < 4; p++){
                unsigned bh[4], bl[4];
                ldsm4(bh, aBh + (unsigned)(p*16*KSTR)*2 + kofs);
                ldsm4(bl, aBl + (unsigned)(p*16*KSTR)*2 + kofs);
#pragma unroll
                for (int sub = 0; sub < 2; sub++){
                    int ni = 2*p + sub;
#pragma unroll
                    for (int mi = 0; mi < 2; mi++){
                        mma16816(c[mi][ni], ah[mi], bh[sub*2], bh[sub*2+1]);
                        mma16816(c[mi][ni], ah[mi], bl[sub*2], bl[sub*2+1]);
                        mma16816(c[mi][ni], al[mi], bh[sub*2], bh[sub*2+1]);
                    }
                }
            }
        }
        __syncthreads();
    }

    if (is_cd){
        int i = bid & 31;
        float rs[4];
#pragma unroll
        for (int mi = 0; mi < 2; mi++){
#pragma unroll
            for (int hf = 0; hf < 2; hf++){
                int m = m0 + wm*32 + mi*16 + g + hf*8;
                const float* g2r = g_g2[1] + (size_t)m*NH;
                float s = 0.f;
#pragma unroll
                for (int ni = 0; ni < 8; ni++){
                    int col = wn*64 + ni*8 + tig*2;
                    float2 gg = *reinterpret_cast<const float2*>(g2r + col);
                    s += c[mi][ni][hf*2+0]*gg.x + c[mi][ni][hf*2+1]*gg.y;
                }
                rs[mi*2+hf] = s;
            }
        }
#pragma unroll
        for (int off = 1; off < 4; off <<= 1)
#pragma unroll
            for (int q = 0; q < 4; q++)
                rs[q] += __shfl_xor_sync(0xffffffffu, rs[q], off);
        float* red = reinterpret_cast<float*>(smb);   // [4 wn][128]
        if (tig == 0){
#pragma unroll
            for (int mi = 0; mi < 2; mi++)
#pragma unroll
                for (int hf = 0; hf < 2; hf++)
                    red[wn*128 + wm*32 + mi*16 + g + hf*8] = rs[mi*2+hf];
        }
        __syncthreads();
        if (t < 128){
            float v = red[t] + red[128+t] + red[256+t] + red[384+t];
            out_covdiv[(size_t)(m0 + t)*ND + i] = v;
        }
    } else {
        int n0 = ((bid - 512) & 3)*256;
#pragma unroll
        for (int mi = 0; mi < 2; mi++){
#pragma unroll
            for (int hf = 0; hf < 2; hf++){
                int m = m0 + wm*32 + mi*16 + g + hf*8;
#pragma unroll
                for (int ni = 0; ni < 8; ni++){
                    int col = n0 + wn*64 + ni*8 + tig*2;
                    float2 b = *reinterpret_cast<const float2*>(cb3 + col);
                    float2 v;
                    v.x = c[mi][ni][hf*2+0] + b.x;
                    v.y = c[mi][ni][hf*2+1] + b.y;
                    *reinterpret_cast<float2*>(out_cov + (size_t)m*(ND*ND) + col) = v;
                }
            }
        }
    }
}

// ---------------- launch ----------------
extern "C" void kernel_launch(void* const* d_in, const int* in_sizes, int n_in,
                              void* d_out, int out_size){
    const float* x   = (const float*)d_in[0];
    const float* sW1 = (const float*)d_in[1];
    const float* sb1 = (const float*)d_in[2];
    const float* sW2 = (const float*)d_in[3];
    const float* sb2 = (const float*)d_in[4];
    const float* sW3 = (const float*)d_in[5];
    const float* sb3 = (const float*)d_in[6];
    const float* cW1 = (const float*)d_in[7];
    const float* cb1 = (const float*)d_in[8];
    const float* cW2 = (const float*)d_in[9];
    const float* cb2 = (const float*)d_in[10];
    const float* cW3 = (const float*)d_in[11];
    const float* cb3 = (const float*)d_in[12];

    float* out        = (float*)d_out;
    float* out_score  = out;                                   // [B,32]
    float* out_trace  = out + NB*ND;                           // [B]
    float* out_cov    = out + NB*ND + NB;                      // [B,1024]
    float* out_covdiv = out + NB*ND + NB + NB*ND*ND;           // [B,32]

    static int inited = 0;
    if (!inited){
        cudaFuncSetAttribute(k_mma, cudaFuncAttributeMaxDynamicSharedMemorySize, MM_SMEM);
        inited = 1;
    }

    k_stageA<<<1056, 256>>>(x, sW1, sb1, sW2, sW3, cW1, cb1, cW2, cW3);
    k_stageB<<<dim3(64,2,2), 256, SM_BYTES>>>(sW2, sb2, cW2, cb2);
    k_stageC<<<128, 256, SM_BYTES>>>(sW3, sb3, out_score, out_trace);
    k_mma<<<576, 512, MM_SMEM>>>(cb3, out_cov, out_covdiv);
}

// round 12
// speedup vs baseline: 5.2268x; 1.0519x over previous
#include <cuda_runtime.h>
#include <cuda_bf16.h>

#define NB 2048
#define ND 32
#define NH 256
#define TSTR 36   // padded smem stride (floats)

// ---------------- fp32 scratch ----------------
__device__ float g_h1[2][NB*NH];
__device__ float g_g1[2][NB*NH];
__device__ float g_h2[2][NB*NH];
__device__ float g_g2[2][NB*NH];
__device__ float g_P[NH*NH];

// ---------------- bf16 split scratch (cov-net tensor path) ----------------
__device__ __nv_bfloat16 g_g1h[NB*NH], g_g1l[NB*NH];        // gc1 split
__device__ __nv_bfloat16 g_h2h[NB*NH], g_h2l[NB*NH];        // h2c split
__device__ __nv_bfloat16 g_Qth[ND*NH*NH], g_Qtl[ND*NH*NH];  // Qt[i][c][a]
__device__ __nv_bfloat16 g_w3th[ND*ND*NH], g_w3tl[ND*ND*NH];// cW3t[n][a]

#define SM_FLOATS (NH*TSTR + 64)
#define SM_BYTES  (SM_FLOATS*4)

// ---------------- packed fp32x2 helpers ----------------
static __device__ __forceinline__ unsigned long long pack2(float x, float y){
    unsigned long long r;
    asm("mov.b64 %0, {%1, %2};" : "=l"(r)
        : "r"(__float_as_uint(x)), "r"(__float_as_uint(y)));
    return r;
}
static __device__ __forceinline__ float2 unpack2(unsigned long long v){
    unsigned lo, hi;
    asm("mov.b64 {%0, %1}, %2;" : "=r"(lo), "=r"(hi) : "l"(v));
    return make_float2(__uint_as_float(lo), __uint_as_float(hi));
}
static __device__ __forceinline__ void ffma2(unsigned long long &d,
                                             unsigned long long a,
                                             unsigned long long b){
    asm("fma.rn.f32x2 %0, %1, %2, %0;" : "+l"(d) : "l"(a), "l"(b));
}
static __device__ __forceinline__ void bf16split(float v, __nv_bfloat16& hi, __nv_bfloat16& lo){
    hi = __float2bfloat16(v);
    lo = __float2bfloat16(v - __bfloat162float(hi));
}

// load 32 samples x 256 features, transposed into smem: sm[a*TSTR + s]
static __device__ __forceinline__ void load_tileT(float* sm, const float* g, int b0){
    for (int idx = threadIdx.x; idx < 32*NH; idx += 256){
        int s = idx >> 8;
        int a = idx & 255;
        sm[a*TSTR + s] = g[(b0 + s)*NH + a];
    }
}

// ---------------- fp32 streaming GEMM core (trace path) ----------------
template<int SP>
static __device__ __forceinline__ void gemm_stream(
    const float* __restrict__ Wt, int wstride,
    const float* __restrict__ sTs,
    unsigned long long (&acc)[SP][4])
{
#pragma unroll 8
    for (int a = 0; a < NH; a++){
        float4 wq = __ldg(reinterpret_cast<const float4*>(Wt + (size_t)a*wstride));
        unsigned long long w0 = pack2(wq.x, wq.x);
        unsigned long long w1 = pack2(wq.y, wq.y);
        unsigned long long w2 = pack2(wq.z, wq.z);
        unsigned long long w3 = pack2(wq.w, wq.w);
        const float* srow = sTs + a*TSTR;
#pragma unroll
        for (int p = 0; p < SP/2; p++){
            ulonglong2 r = *reinterpret_cast<const ulonglong2*>(srow + p*4);
            ffma2(acc[2*p][0],   r.x, w0); ffma2(acc[2*p][1],   r.x, w1);
            ffma2(acc[2*p][2],   r.x, w2); ffma2(acc[2*p][3],   r.x, w3);
            ffma2(acc[2*p+1][0], r.y, w0); ffma2(acc[2*p+1][1], r.y, w1);
            ffma2(acc[2*p+1][2], r.y, w2); ffma2(acc[2*p+1][3], r.y, w3);
        }
    }
}

static __device__ __forceinline__ void bilinear_reduce_store(
    const float T[8][4], const float* __restrict__ g2row, int b0,
    float* __restrict__ partial, float* __restrict__ outp, int ostride)
{
    int cg = threadIdx.x & 63;
    int sq = threadIdx.x >> 6;
    float val[8];
#pragma unroll
    for (int s = 0; s < 8; s++){
        float4 gq = *reinterpret_cast<const float4*>(&g2row[(b0 + sq*8 + s)*NH + cg*4]);
        val[s] = T[s][0]*gq.x + T[s][1]*gq.y + T[s][2]*gq.z + T[s][3]*gq.w;
    }
#pragma unroll
    for (int off = 16; off; off >>= 1)
#pragma unroll
        for (int s = 0; s < 8; s++)
            val[s] += __shfl_xor_sync(0xffffffffu, val[s], off);
    int w = threadIdx.x >> 5;
    if ((threadIdx.x & 31) == 0){
#pragma unroll
        for (int s = 0; s < 8; s++) partial[w*8 + s] = val[s];
    }
    __syncthreads();
    if (threadIdx.x < 32){
        int sq2 = threadIdx.x >> 3, s = threadIdx.x & 7;
        float v = partial[(2*sq2)*8 + s] + partial[(2*sq2+1)*8 + s];
        outp[(b0 + threadIdx.x)*ostride] = v;
    }
}

// ---------------- mma.sync / ldmatrix / cp.async helpers (baseline PTX) -------------
static __device__ __forceinline__ void mma16816(float (&c)[4],
    const unsigned (&a)[4], unsigned b0, unsigned b1)
{
    asm volatile("mma.sync.aligned.m16n8k16.row.col.f32.bf16.bf16.f32 "
        "{%0,%1,%2,%3}, {%4,%5,%6,%7}, {%8,%9}, {%0,%1,%2,%3};"
        : "+f"(c[0]), "+f"(c[1]), "+f"(c[2]), "+f"(c[3])
        : "r"(a[0]), "r"(a[1]), "r"(a[2]), "r"(a[3]), "r"(b0), "r"(b1));
}
static __device__ __forceinline__ void ldsm4(unsigned (&r)[4], unsigned addr){
    asm volatile("ldmatrix.sync.aligned.m8n8.x4.shared.b16 {%0,%1,%2,%3}, [%4];"
        : "=r"(r[0]), "=r"(r[1]), "=r"(r[2]), "=r"(r[3]) : "r"(addr));
}
static __device__ __forceinline__ void cpa16(unsigned saddr, const void* g){
    asm volatile("cp.async.cg.shared.global [%0], [%1], 16;" :: "r"(saddr), "l"(g));
}
static __device__ __forceinline__ void cpa_commit(){
    asm volatile("cp.async.commit_group;" ::: "memory");
}
template<int N>
static __device__ __forceinline__ void cpa_wait(){
    asm volatile("cp.async.wait_group %0;" :: "n"(N) : "memory");
}

// ======================= STAGE A =======================
// grid 1056: [0,256) precompP | [256,512) precompQ | [512,1024) layer1 | [1024,1056) cW3 transpose
__global__ void __launch_bounds__(256)
k_stageA(const float* __restrict__ x,
         const float* __restrict__ sW1, const float* __restrict__ sb1,
         const float* __restrict__ sW2,
         const float* __restrict__ sW3,
         const float* __restrict__ cW1, const float* __restrict__ cb1,
         const float* __restrict__ cW2,
         const float* __restrict__ cW3)
{
    __shared__ float sbuf[256*33 + 32*33];
    int bid = blockIdx.x;
    int t = threadIdx.x;
    if (bid < 256){
        int a = bid, c = t;
        float* w1 = sbuf;
        if (c < ND) w1[c] = sW1[c*NH + a];
        __syncthreads();
        const float* s3 = sW3 + c*ND;
        float acc = 0.f;
#pragma unroll
        for (int i = 0; i < ND; i++) acc = fmaf(s3[i], w1[i], acc);
        g_P[a*NH + c] = sW2[a*NH + c] * acc;
    } else if (bid < 512){
        int r  = bid - 256;
        int i  = r & 31;
        int c0 = (r >> 5) * 32;
        float* w2s = sbuf;            // [256][33]
        float* w3s = sbuf + 256*33;   // [32][33]
        for (int idx = t; idx < 256*32; idx += 256){
            int ar = idx >> 5, cc = idx & 31;
            w2s[ar*33 + cc] = cW2[ar*NH + c0 + cc];
        }
        for (int idx = t; idx < 32*32; idx += 256){
            int cr = idx >> 5, j = idx & 31;
            w3s[cr*33 + j] = cW3[(c0 + cr)*(ND*ND) + i*ND + j];
        }
        __syncthreads();
        int a = t;
        float w1r[ND];
#pragma unroll
        for (int j = 0; j < ND; j++) w1r[j] = cW1[j*NH + a];
#pragma unroll 4
        for (int cc = 0; cc < 32; cc++){
            float acc = 0.f;
#pragma unroll
            for (int j = 0; j < ND; j++) acc = fmaf(w1r[j], w3s[cc*33 + j], acc);
            float q = w2s[a*33 + cc] * acc;
            __nv_bfloat16 hi, lo; bf16split(q, hi, lo);
            size_t o = ((size_t)i*NH + c0 + cc)*NH + a;
            g_Qth[o] = hi; g_Qtl[o] = lo;
        }
    } else if (bid < 1024){
        int r   = bid - 512;
        int net = r >> 8;
        int b0  = (r & 255) * 8;
        const float* W1 = net ? cW1 : sW1;
        const float* b1 = net ? cb1 : sb1;
        float* xs = sbuf;   // [8][32]
        xs[t] = x[b0*ND + t];
        __syncthreads();
        float acc[8];
        float bias = b1[t];
#pragma unroll
        for (int s = 0; s < 8; s++) acc[s] = bias;
#pragma unroll
        for (int k = 0; k < ND; k++){
            float w = W1[k*NH + t];
#pragma unroll
            for (int s = 0; s < 8; s++) acc[s] = fmaf(xs[s*32 + k], w, acc[s]);
        }
        float* hout = g_h1[net];
        float* gout = g_g1[net];
#pragma unroll
        for (int s = 0; s < 8; s++){
            float h = tanhf(acc[s]);
            float g = 1.0f - h*h;
            int row = (b0+s)*NH + t;
            hout[row] = h;
            gout[row] = g;
            if (net == 1){
                __nv_bfloat16 hi, lo; bf16split(g, hi, lo);
                g_g1h[row] = hi; g_g1l[row] = lo;
            }
        }
    } else {
        int n0 = (bid - 1024) * 32;
        float* s = sbuf;  // [32][33]
        for (int a0 = 0; a0 < NH; a0 += 32){
            __syncthreads();
#pragma unroll
            for (int pp = 0; pp < 4; pp++){
                int ar = (t >> 5) + pp*8, nc = t & 31;
                s[ar*33 + nc] = cW3[(a0 + ar)*(ND*ND) + n0 + nc];
            }
            __syncthreads();
#pragma unroll
            for (int pp = 0; pp < 4; pp++){
                int nn = (t >> 5) + pp*8, aa = t & 31;
                float v = s[aa*33 + nn];
                __nv_bfloat16 hi, lo; bf16split(v, hi, lo);
                size_t o = ((size_t)(n0 + nn))*NH + a0 + aa;
                g_w3th[o] = hi; g_w3tl[o] = lo;
            }
        }
    }
}

// ======================= STAGE B: layer2 =======================
__global__ void __launch_bounds__(256, 3)
k_stageB(const float* __restrict__ sW2, const float* __restrict__ sb2,
         const float* __restrict__ cW2, const float* __restrict__ cb2)
{
    extern __shared__ float smemf[];
    float* sT = smemf;
    int net   = blockIdx.z;
    int chalf = blockIdx.y;
    int b0    = blockIdx.x * 32;
    const float* W    = net ? cW2 : sW2;
    const float* bias = net ? cb2 : sb2;
    int cg = threadIdx.x & 31;
    int sq = threadIdx.x >> 5;
    int c0 = chalf*128 + cg*4;

    load_tileT(sT, g_h1[net], b0);
    __syncthreads();

    float4 bq = *reinterpret_cast<const float4*>(&bias[c0]);
    unsigned long long acc[2][4];
    acc[0][0] = pack2(bq.x, bq.x); acc[0][1] = pack2(bq.y, bq.y);
    acc[0][2] = pack2(bq.z, bq.z); acc[0][3] = pack2(bq.w, bq.w);
#pragma unroll
    for (int cc = 0; cc < 4; cc++) acc[1][cc] = acc[0][cc];

    gemm_stream<2>(W + c0, NH, sT + sq*4, acc);

    float* h2 = g_h2[net];
    float* g2 = g_g2[net];
#pragma unroll
    for (int p = 0; p < 2; p++){
#pragma unroll
        for (int half = 0; half < 2; half++){
            float v[4];
#pragma unroll
            for (int cc = 0; cc < 4; cc++){
                float2 f = unpack2(acc[p][cc]);
                v[cc] = half ? f.y : f.x;
            }
            float4 hv, gv;
            hv.x = tanhf(v[0]); hv.y = tanhf(v[1]);
            hv.z = tanhf(v[2]); hv.w = tanhf(v[3]);
            gv.x = 1.0f - hv.x*hv.x; gv.y = 1.0f - hv.y*hv.y;
            gv.z = 1.0f - hv.z*hv.z; gv.w = 1.0f - hv.w*hv.w;
            int row = (b0 + sq*4 + p*2 + half)*NH + c0;
            *reinterpret_cast<float4*>(&h2[row]) = hv;
            *reinterpret_cast<float4*>(&g2[row]) = gv;
            if (net == 1){
                __nv_bfloat16 hi, lo;
                bf16split(hv.x, hi, lo); g_h2h[row+0] = hi; g_h2l[row+0] = lo;
                bf16split(hv.y, hi, lo); g_h2h[row+1] = hi; g_h2l[row+1] = lo;
                bf16split(hv.z, hi, lo); g_h2h[row+2] = hi; g_h2l[row+2] = lo;
                bf16split(hv.w, hi, lo); g_h2h[row+3] = hi; g_h2l[row+3] = lo;
            }
        }
    }
}

// ======================= STAGE C: trace + score (fp32) =======================
__global__ void __launch_bounds__(256, 3)
k_stageC(const float* __restrict__ sW3, const float* __restrict__ sb3,
         float* __restrict__ out_score, float* __restrict__ out_trace)
{
    extern __shared__ float smemf[];
    float* sT      = smemf;
    float* partial = smemf + NH*TSTR;
    int bid = blockIdx.x;
    int cg = threadIdx.x & 63;
    int sq = threadIdx.x >> 6;

    if (bid < 64){
        int b0 = bid * 32;
        load_tileT(sT, g_g1[0], b0);
        __syncthreads();
        unsigned long long acc[4][4];
#pragma unroll
        for (int sp = 0; sp < 4; sp++)
#pragma unroll
            for (int cc = 0; cc < 4; cc++) acc[sp][cc] = 0ull;
        gemm_stream<4>(g_P + cg*4, NH, sT + sq*8, acc);
        float T[8][4];
#pragma unroll
        for (int sp = 0; sp < 4; sp++)
#pragma unroll
            for (int cc = 0; cc < 4; cc++){
                float2 f = unpack2(acc[sp][cc]);
                T[2*sp][cc] = f.x; T[2*sp+1][cc] = f.y;
            }
        bilinear_reduce_store(T, g_g2[0], b0, partial, out_trace, 1);
    } else {
        int b0 = (bid - 64) * 32;
        int i  = threadIdx.x & 31;
        int sg = threadIdx.x >> 5;
        load_tileT(sT, g_h2[0], b0);
        __syncthreads();
        float acc[4];
        float bias = sb3[i];
#pragma unroll
        for (int k = 0; k < 4; k++) acc[k] = bias;
#pragma unroll 4
        for (int a = 0; a < NH; a++){
            float w = sW3[a*ND + i];
            float4 v = *reinterpret_cast<const float4*>(&sT[a*TSTR + sg*4]);
            acc[0] = fmaf(v.x, w, acc[0]);
            acc[1] = fmaf(v.y, w, acc[1]);
            acc[2] = fmaf(v.z, w, acc[2]);
            acc[3] = fmaf(v.w, w, acc[3]);
        }
#pragma unroll
        for (int k = 0; k < 4; k++)
            out_score[(b0 + sg*4 + k)*ND + i] = acc[k];
    }
}

// ======================= TENSOR (mma.sync) KERNEL: covdiv + layer3_cov ==============
// grid 576, 256 threads (8 warps: 4m x 2n). Block tile M=128 x N=128, with the full
// N=256 covered by an in-block nh loop (accumulators reused; covdiv partial dots kept
// in registers across halves). 2-stage cp.async pipeline; 2 blocks/SM.
#define KC    32
#define KSTR  40
#define AE    (128*KSTR)            // elems per (A or B) buffer (5120 = 10 KB)
#define STG_E (4*AE)                // Ah|Al|Bh|Bl per stage (40 KB)
#define MM_SMEM (2*STG_E*2)         // bytes = 81920

__global__ void __launch_bounds__(256, 2)
k_mma(const float* __restrict__ cb3,
      float* __restrict__ out_cov, float* __restrict__ out_covdiv)
{
    extern __shared__ __nv_bfloat16 smb[];
    unsigned smu = (unsigned)__cvta_generic_to_shared(smb);

    int t = threadIdx.x, lane = t & 31, wid = t >> 5;
    int wm = wid & 3, wn = wid >> 2;       // 4x2 warp grid
    int g = lane >> 2, tig = lane & 3;
    int bid = blockIdx.x;
    bool is_cd = bid < 512;

    const __nv_bfloat16 *Ah, *Al, *Bh0, *Bl0;
    int m0, nt = 0, i = 0;
    if (is_cd){
        i = bid & 31; m0 = (bid >> 5)*128;
        Ah = g_g1h; Al = g_g1l;
        Bh0 = g_Qth + (size_t)i*NH*NH; Bl0 = g_Qtl + (size_t)i*NH*NH;
    } else {
        int r = bid - 512; nt = r & 3; m0 = (r >> 2)*128;
        Ah = g_h2h; Al = g_h2l;
        Bh0 = g_w3th + (size_t)nt*256*NH; Bl0 = g_w3tl + (size_t)nt*256*NH;
    }

    float c[2][8][4];
#pragma unroll
    for (int mi = 0; mi < 2; mi++)
#pragma unroll
        for (int ni = 0; ni < 8; ni++)
#pragma unroll
            for (int q = 0; q < 4; q++) c[mi][ni][q] = 0.f;
    float rs[4] = {0.f, 0.f, 0.f, 0.f};

    // ldmatrix per-lane offsets (bf16 elems within tile)
    int lrow = lane & 7, sel = lane >> 3;
    int aoff = ((sel & 1)*8 + lrow)*KSTR + (sel >> 1)*8;
    int boff = ((sel >> 1)*8 + lrow)*KSTR + (sel & 1)*8;

    // staging: each buffer = 128 rows x 4 16B-quads = 512 copies; 2 per thread
    // stage chunk j (j = nh*8 + kc) into buffer j&1
    auto stage = [&](int j){
        int nh = j >> 3, k0 = (j & 7)*KC;
        unsigned base = smu + (unsigned)(j & 1)*STG_E*2;
#pragma unroll
        for (int p = 0; p < 2; p++){
            int idx = t + p*256;
            int r = idx >> 2, q = idx & 3;
            unsigned d = base + (unsigned)(r*KSTR + q*8)*2;
            const __nv_bfloat16* ga = Ah + (size_t)(m0 + r)*NH + k0 + q*8;
            const __nv_bfloat16* gal = Al + (size_t)(m0 + r)*NH + k0 + q*8;
            const __nv_bfloat16* gb = Bh0 + (size_t)(nh*128 + r)*NH + k0 + q*8;
            const __nv_bfloat16* gbl = Bl0 + (size_t)(nh*128 + r)*NH + k0 + q*8;
            cpa16(d,            ga);
            cpa16(d + AE*2,     gal);
            cpa16(d + 2*AE*2,   gb);
            cpa16(d + 3*AE*2,   gbl);
        }
        cpa_commit();
    };

    stage(0);

#pragma unroll 1
    for (int j = 0; j < 16; j++){
        if (j + 1 < 16) stage(j+1);
        if (j + 1 < 16) cpa_wait<1>(); else cpa_wait<0>();
        __syncthreads();

        unsigned base = smu + (unsigned)(j & 1)*STG_E*2;
        unsigned aAh = base + (unsigned)(wm*32*KSTR + aoff)*2;
        unsigned aAl = aAh + AE*2;
        unsigned aBh = base + 2*AE*2 + (unsigned)(wn*64*KSTR + boff)*2;
        unsigned aBl = aBh + AE*2;

#pragma unroll
        for (int ks = 0; ks < KC/16; ks++){
            unsigned kofs = (unsigned)(ks*16)*2;
            unsigned ah[2][4], al[2][4];
#pragma unroll
            for (int mi = 0; mi < 2; mi++){
                ldsm4(ah[mi], aAh + (unsigned)(mi*16*KSTR)*2 + kofs);
                ldsm4(al[mi], aAl + (unsigned)(mi*16*KSTR)*2 + kofs);
            }
#pragma unroll
            for (int p = 0; p < 4; p++){
                unsigned bh[4], bl[4];
                ldsm4(bh, aBh + (unsigned)(p*16*KSTR)*2 + kofs);
                ldsm4(bl, aBl + (unsigned)(p*16*KSTR)*2 + kofs);
                // term-major: accumulator reuse distance = 4
#pragma unroll
                for (int sub = 0; sub < 2; sub++)
#pragma unroll
                    for (int mi = 0; mi < 2; mi++)
                        mma16816(c[mi][2*p+sub], ah[mi], bh[sub*2], bh[sub*2+1]);
#pragma unroll
                for (int sub = 0; sub < 2; sub++)
#pragma unroll
                    for (int mi = 0; mi < 2; mi++)
                        mma16816(c[mi][2*p+sub], ah[mi], bl[sub*2], bl[sub*2+1]);
#pragma unroll
                for (int sub = 0; sub < 2; sub++)
#pragma unroll
                    for (int mi = 0; mi < 2; mi++)
                        mma16816(c[mi][2*p+sub], al[mi], bh[sub*2], bh[sub*2+1]);
            }
        }
        __syncthreads();

        if ((j & 7) == 7){
            int nh = j >> 3;
            if (is_cd){
                // partial bilinear dot for this n-half; keep in regs
#pragma unroll
                for (int mi = 0; mi < 2; mi++){
#pragma unroll
                    for (int hf = 0; hf < 2; hf++){
                        int m = m0 + wm*32 + mi*16 + g + hf*8;
                        const float* g2r = g_g2[1] + (size_t)m*NH + nh*128;
                        float s = 0.f;
#pragma unroll
                        for (int ni = 0; ni < 8; ni++){
                            int col = wn*64 + ni*8 + tig*2;
                            float2 gg = *reinterpret_cast<const float2*>(g2r + col);
                            s += c[mi][ni][hf*2+0]*gg.x + c[mi][ni][hf*2+1]*gg.y;
                        }
                        rs[mi*2+hf] += s;
                    }
                }
            } else {
                int n0 = nt*256 + nh*128;
#pragma unroll
                for (int mi = 0; mi < 2; mi++){
#pragma unroll
                    for (int hf = 0; hf < 2; hf++){
                        int m = m0 + wm*32 + mi*16 + g + hf*8;
#pragma unroll
                        for (int ni = 0; ni < 8; ni++){
                            int col = n0 + wn*64 + ni*8 + tig*2;
                            float2 b = *reinterpret_cast<const float2*>(cb3 + col);
                            float2 v;
                            v.x = c[mi][ni][hf*2+0] + b.x;
                            v.y = c[mi][ni][hf*2+1] + b.y;
                            *reinterpret_cast<float2*>(out_cov + (size_t)m*(ND*ND) + col) = v;
                        }
                    }
                }
            }
            if (j < 15){
#pragma unroll
                for (int mi = 0; mi < 2; mi++)
#pragma unroll
                    for (int ni = 0; ni < 8; ni++)
#pragma unroll
                        for (int q = 0; q < 4; q++) c[mi][ni][q] = 0.f;
            }
        }
    }

    if (is_cd){
#pragma unroll
        for (int off = 1; off < 4; off <<= 1)
#pragma unroll
            for (int q = 0; q < 4; q++)
                rs[q] += __shfl_xor_sync(0xffffffffu, rs[q], off);
        float* red = reinterpret_cast<float*>(smb);   // [2 wn][128]
        __syncthreads();
        if (tig == 0){
#pragma unroll
            for (int mi = 0; mi < 2; mi++)
#pragma unroll
                for (int hf = 0; hf < 2; hf++)
                    red[wn*128 + wm*32 + mi*16 + g + hf*8] = rs[mi*2+hf];
        }
        __syncthreads();
        if (t < 128)
            out_covdiv[(size_t)(m0 + t)*ND + i] = red[t] + red[128+t];
    }
}

// ---------------- launch ----------------
extern "C" void kernel_launch(void* const* d_in, const int* in_sizes, int n_in,
                              void* d_out, int out_size){
    const float* x   = (const float*)d_in[0];
    const float* sW1 = (const float*)d_in[1];
    const float* sb1 = (const float*)d_in[2];
    const float* sW2 = (const float*)d_in[3];
    const float* sb2 = (const float*)d_in[4];
    const float* sW3 = (const float*)d_in[5];
    const float* sb3 = (const float*)d_in[6];
    const float* cW1 = (const float*)d_in[7];
    const float* cb1 = (const float*)d_in[8];
    const float* cW2 = (const float*)d_in[9];
    const float* cb2 = (const float*)d_in[10];
    const float* cW3 = (const float*)d_in[11];
    const float* cb3 = (const float*)d_in[12];

    float* out        = (float*)d_out;
    float* out_score  = out;                                   // [B,32]
    float* out_trace  = out + NB*ND;                           // [B]
    float* out_cov    = out + NB*ND + NB;                      // [B,1024]
    float* out_covdiv = out + NB*ND + NB + NB*ND*ND;           // [B,32]

    static int inited = 0;
    if (!inited){
        cudaFuncSetAttribute(k_mma, cudaFuncAttributeMaxDynamicSharedMemorySize, MM_SMEM);
        inited = 1;
    }

    k_stageA<<<1056, 256>>>(x, sW1, sb1, sW2, sW3, cW1, cb1, cW2, cW3);
    k_stageB<<<dim3(64,2,2), 256, SM_BYTES>>>(sW2, sb2, cW2, cb2);
    k_stageC<<<128, 256, SM_BYTES>>>(sW3, sb3, out_score, out_trace);
    k_mma<<<576, 256, MM_SMEM>>>(cb3, out_cov, out_covdiv);
}

// round 15
// speedup vs baseline: 6.2177x; 1.1896x over previous
#include <cuda_runtime.h>
#include <cuda_bf16.h>

#define NB 2048
#define ND 32
#define NH 256
#define TSTR 36   // padded smem stride (floats)

// ---------------- fp32 scratch ----------------
__device__ float g_h1[2][NB*NH];
__device__ float g_g1[2][NB*NH];
__device__ float g_h2[2][NB*NH];
__device__ float g_g2[2][NB*NH];
__device__ float g_P[NH*NH];

// ---------------- bf16 split scratch (cov-net tensor path) ----------------
__device__ __nv_bfloat16 g_g1h[NB*NH], g_g1l[NB*NH];        // gc1 split
__device__ __nv_bfloat16 g_h2h[NB*NH], g_h2l[NB*NH];        // h2c split
__device__ __nv_bfloat16 g_Qth[ND*NH*NH], g_Qtl[ND*NH*NH];  // Qt[i][c][a]
__device__ __nv_bfloat16 g_w3th[ND*ND*NH], g_w3tl[ND*ND*NH];// cW3t[n][a]

#define SM_FLOATS (NH*TSTR + 64)
#define SM_BYTES  (SM_FLOATS*4)

// ---------------- packed fp32x2 helpers ----------------
static __device__ __forceinline__ unsigned long long pack2(float x, float y){
    unsigned long long r;
    asm("mov.b64 %0, {%1, %2};" : "=l"(r)
        : "r"(__float_as_uint(x)), "r"(__float_as_uint(y)));
    return r;
}
static __device__ __forceinline__ float2 unpack2(unsigned long long v){
    unsigned lo, hi;
    asm("mov.b64 {%0, %1}, %2;" : "=r"(lo), "=r"(hi) : "l"(v));
    return make_float2(__uint_as_float(lo), __uint_as_float(hi));
}
static __device__ __forceinline__ void ffma2(unsigned long long &d,
                                             unsigned long long a,
                                             unsigned long long b){
    asm("fma.rn.f32x2 %0, %1, %2, %0;" : "+l"(d) : "l"(a), "l"(b));
}
static __device__ __forceinline__ void bf16split(float v, __nv_bfloat16& hi, __nv_bfloat16& lo){
    hi = __float2bfloat16(v);
    lo = __float2bfloat16(v - __bfloat162float(hi));
}

// load 32 samples x 256 features, transposed into smem: sm[a*TSTR + s]
static __device__ __forceinline__ void load_tileT(float* sm, const float* g, int b0){
    for (int idx = threadIdx.x; idx < 32*NH; idx += 256){
        int s = idx >> 8;
        int a = idx & 255;
        sm[a*TSTR + s] = g[(b0 + s)*NH + a];
    }
}

// ---------------- fp32 streaming GEMM core ----------------
template<int SP>
static __device__ __forceinline__ void gemm_stream(
    const float* __restrict__ Wt, int wstride,
    const float* __restrict__ sTs,
    unsigned long long (&acc)[SP][4])
{
#pragma unroll 8
    for (int a = 0; a < NH; a++){
        float4 wq = __ldg(reinterpret_cast<const float4*>(Wt + (size_t)a*wstride));
        unsigned long long w0 = pack2(wq.x, wq.x);
        unsigned long long w1 = pack2(wq.y, wq.y);
        unsigned long long w2 = pack2(wq.z, wq.z);
        unsigned long long w3 = pack2(wq.w, wq.w);
        const float* srow = sTs + a*TSTR;
#pragma unroll
        for (int p = 0; p < SP/2; p++){
            ulonglong2 r = *reinterpret_cast<const ulonglong2*>(srow + p*4);
            ffma2(acc[2*p][0],   r.x, w0); ffma2(acc[2*p][1],   r.x, w1);
            ffma2(acc[2*p][2],   r.x, w2); ffma2(acc[2*p][3],   r.x, w3);
            ffma2(acc[2*p+1][0], r.y, w0); ffma2(acc[2*p+1][1], r.y, w1);
            ffma2(acc[2*p+1][2], r.y, w2); ffma2(acc[2*p+1][3], r.y, w3);
        }
    }
}

static __device__ __forceinline__ void bilinear_reduce_store(
    const float T[8][4], const float* __restrict__ g2row, int b0,
    float* __restrict__ partial, float* __restrict__ outp, int ostride)
{
    int cg = threadIdx.x & 63;
    int sq = threadIdx.x >> 6;
    float val[8];
#pragma unroll
    for (int s = 0; s < 8; s++){
        float4 gq = *reinterpret_cast<const float4*>(&g2row[(b0 + sq*8 + s)*NH + cg*4]);
        val[s] = T[s][0]*gq.x + T[s][1]*gq.y + T[s][2]*gq.z + T[s][3]*gq.w;
    }
#pragma unroll
    for (int off = 16; off; off >>= 1)
#pragma unroll
        for (int s = 0; s < 8; s++)
            val[s] += __shfl_xor_sync(0xffffffffu, val[s], off);
    int w = threadIdx.x >> 5;
    if ((threadIdx.x & 31) == 0){
#pragma unroll
        for (int s = 0; s < 8; s++) partial[w*8 + s] = val[s];
    }
    __syncthreads();
    if (threadIdx.x < 32){
        int sq2 = threadIdx.x >> 3, s = threadIdx.x & 7;
        float v = partial[(2*sq2)*8 + s] + partial[(2*sq2+1)*8 + s];
        outp[(b0 + threadIdx.x)*ostride] = v;
    }
}

// ---------------- mma.sync / ldmatrix / cp.async helpers (baseline PTX) -------------
static __device__ __forceinline__ void mma16816(float (&c)[4],
    const unsigned (&a)[4], unsigned b0, unsigned b1)
{
    asm volatile("mma.sync.aligned.m16n8k16.row.col.f32.bf16.bf16.f32 "
        "{%0,%1,%2,%3}, {%4,%5,%6,%7}, {%8,%9}, {%0,%1,%2,%3};"
        : "+f"(c[0]), "+f"(c[1]), "+f"(c[2]), "+f"(c[3])
        : "r"(a[0]), "r"(a[1]), "r"(a[2]), "r"(a[3]), "r"(b0), "r"(b1));
}
static __device__ __forceinline__ void ldsm4(unsigned (&r)[4], unsigned addr){
    asm volatile("ldmatrix.sync.aligned.m8n8.x4.shared.b16 {%0,%1,%2,%3}, [%4];"
        : "=r"(r[0]), "=r"(r[1]), "=r"(r[2]), "=r"(r[3]) : "r"(addr));
}
static __device__ __forceinline__ void cpa16(unsigned saddr, const void* g){
    asm volatile("cp.async.cg.shared.global [%0], [%1], 16;" :: "r"(saddr), "l"(g));
}
static __device__ __forceinline__ void cpa_commit(){
    asm volatile("cp.async.commit_group;" ::: "memory");
}
template<int N>
static __device__ __forceinline__ void cpa_wait(){
    asm volatile("cp.async.wait_group %0;" :: "n"(N) : "memory");
}

// ======================= STAGE A =======================
// grid 1056: [0,256) precompP | [256,512) precompQ | [512,1024) layer1 | [1024,1056) cW3 transpose
__global__ void __launch_bounds__(256)
k_stageA(const float* __restrict__ x,
         const float* __restrict__ sW1, const float* __restrict__ sb1,
         const float* __restrict__ sW2,
         const float* __restrict__ sW3,
         const float* __restrict__ cW1, const float* __restrict__ cb1,
         const float* __restrict__ cW2,
         const float* __restrict__ cW3)
{
    __shared__ float sbuf[256*33 + 32*33];
    int bid = blockIdx.x;
    int t = threadIdx.x;
    if (bid < 256){
        int a = bid, c = t;
        float* w1 = sbuf;
        if (c < ND) w1[c] = sW1[c*NH + a];
        __syncthreads();
        const float* s3 = sW3 + c*ND;
        float acc = 0.f;
#pragma unroll
        for (int i = 0; i < ND; i++) acc = fmaf(s3[i], w1[i], acc);
        g_P[a*NH + c] = sW2[a*NH + c] * acc;
    } else if (bid < 512){
        int r  = bid - 256;
        int i  = r & 31;
        int c0 = (r >> 5) * 32;
        float* w2s = sbuf;            // [256][33]
        float* w3s = sbuf + 256*33;   // [32][33]
        for (int idx = t; idx < 256*32; idx += 256){
            int ar = idx >> 5, cc = idx & 31;
            w2s[ar*33 + cc] = cW2[ar*NH + c0 + cc];
        }
        for (int idx = t; idx < 32*32; idx += 256){
            int cr = idx >> 5, j = idx & 31;
            w3s[cr*33 + j] = cW3[(c0 + cr)*(ND*ND) + i*ND + j];
        }
        __syncthreads();
        int a = t;
        float w1r[ND];
#pragma unroll
        for (int j = 0; j < ND; j++) w1r[j] = cW1[j*NH + a];
#pragma unroll 4
        for (int cc = 0; cc < 32; cc++){
            float acc = 0.f;
#pragma unroll
            for (int j = 0; j < ND; j++) acc = fmaf(w1r[j], w3s[cc*33 + j], acc);
            float q = w2s[a*33 + cc] * acc;
            __nv_bfloat16 hi, lo; bf16split(q, hi, lo);
            size_t o = ((size_t)i*NH + c0 + cc)*NH + a;
            g_Qth[o] = hi; g_Qtl[o] = lo;
        }
    } else if (bid < 1024){
        int r   = bid - 512;
        int net = r >> 8;
        int b0  = (r & 255) * 8;
        const float* W1 = net ? cW1 : sW1;
        const float* b1 = net ? cb1 : sb1;
        float* xs = sbuf;   // [8][32]
        xs[t] = x[b0*ND + t];
        __syncthreads();
        float acc[8];
        float bias = b1[t];
#pragma unroll
        for (int s = 0; s < 8; s++) acc[s] = bias;
#pragma unroll
        for (int k = 0; k < ND; k++){
            float w = W1[k*NH + t];
#pragma unroll
            for (int s = 0; s < 8; s++) acc[s] = fmaf(xs[s*32 + k], w, acc[s]);
        }
        float* hout = g_h1[net];
        float* gout = g_g1[net];
#pragma unroll
        for (int s = 0; s < 8; s++){
            float h = tanhf(acc[s]);
            float g = 1.0f - h*h;
            int row = (b0+s)*NH + t;
            hout[row] = h;
            gout[row] = g;
            if (net == 1){
                __nv_bfloat16 hi, lo; bf16split(g, hi, lo);
                g_g1h[row] = hi; g_g1l[row] = lo;
            }
        }
    } else {
        int n0 = (bid - 1024) * 32;
        float* s = sbuf;  // [32][33]
        for (int a0 = 0; a0 < NH; a0 += 32){
            __syncthreads();
#pragma unroll
            for (int pp = 0; pp < 4; pp++){
                int ar = (t >> 5) + pp*8, nc = t & 31;
                s[ar*33 + nc] = cW3[(a0 + ar)*(ND*ND) + n0 + nc];
            }
            __syncthreads();
#pragma unroll
            for (int pp = 0; pp < 4; pp++){
                int nn = (t >> 5) + pp*8, aa = t & 31;
                float v = s[aa*33 + nn];
                __nv_bfloat16 hi, lo; bf16split(v, hi, lo);
                size_t o = ((size_t)(n0 + nn))*NH + a0 + aa;
                g_w3th[o] = hi; g_w3tl[o] = lo;
            }
        }
    }
}

// ======================= STAGE B: layer2 =======================
__global__ void __launch_bounds__(256, 3)
k_stageB(const float* __restrict__ sW2, const float* __restrict__ sb2,
         const float* __restrict__ cW2, const float* __restrict__ cb2)
{
    extern __shared__ float smemf[];
    float* sT = smemf;
    int net   = blockIdx.z;
    int chalf = blockIdx.y;
    int b0    = blockIdx.x * 32;
    const float* W    = net ? cW2 : sW2;
    const float* bias = net ? cb2 : sb2;
    int cg = threadIdx.x & 31;
    int sq = threadIdx.x >> 5;
    int c0 = chalf*128 + cg*4;

    load_tileT(sT, g_h1[net], b0);
    __syncthreads();

    float4 bq = *reinterpret_cast<const float4*>(&bias[c0]);
    unsigned long long acc[2][4];
    acc[0][0] = pack2(bq.x, bq.x); acc[0][1] = pack2(bq.y, bq.y);
    acc[0][2] = pack2(bq.z, bq.z); acc[0][3] = pack2(bq.w, bq.w);
#pragma unroll
    for (int cc = 0; cc < 4; cc++) acc[1][cc] = acc[0][cc];

    gemm_stream<2>(W + c0, NH, sT + sq*4, acc);

    float* h2 = g_h2[net];
    float* g2 = g_g2[net];
#pragma unroll
    for (int p = 0; p < 2; p++){
#pragma unroll
        for (int half = 0; half < 2; half++){
            float v[4];
#pragma unroll
            for (int cc = 0; cc < 4; cc++){
                float2 f = unpack2(acc[p][cc]);
                v[cc] = half ? f.y : f.x;
            }
            float4 hv, gv;
            hv.x = tanhf(v[0]); hv.y = tanhf(v[1]);
            hv.z = tanhf(v[2]); hv.w = tanhf(v[3]);
            gv.x = 1.0f - hv.x*hv.x; gv.y = 1.0f - hv.y*hv.y;
            gv.z = 1.0f - hv.z*hv.z; gv.w = 1.0f - hv.w*hv.w;
            int row = (b0 + sq*4 + p*2 + half)*NH + c0;
            *reinterpret_cast<float4*>(&h2[row]) = hv;
            *reinterpret_cast<float4*>(&g2[row]) = gv;
            if (net == 1){
                __nv_bfloat16 hi, lo;
                bf16split(hv.x, hi, lo); g_h2h[row+0] = hi; g_h2l[row+0] = lo;
                bf16split(hv.y, hi, lo); g_h2h[row+1] = hi; g_h2l[row+1] = lo;
                bf16split(hv.z, hi, lo); g_h2h[row+2] = hi; g_h2l[row+2] = lo;
                bf16split(hv.w, hi, lo); g_h2h[row+3] = hi; g_h2l[row+3] = lo;
            }
        }
    }
}

// ======================= FUSED TENSOR KERNEL =======================
// grid 704:
//   [0,512)   covdiv   (i = bid&31, mt = bid>>5)
//   [512,576) layer3_cov (nt = r&3, mt = r>>2)
//   [576,640) trace    (fp32, tail-fills tensor-idle SMs)
//   [640,704) score
// Tensor blocks: 256 threads (8 warps: 4m x 2n), tile M=128 x N=128, nh loop over 2
// halves. 3-stage cp.async pipeline (1 syncthreads/chunk), swizzled 64B rows.
#define KC     32
#define BUF_B  8192u                // one buffer: 128 rows x 64B
#define STG_B  (4*BUF_B)            // Ah|Al|Bh|Bl = 32KB
#define MM_SMEM (3*STG_B)           // 98304
#define SWZ(r, q) ((unsigned)(((r)*4 + ((q) ^ (((r)>>1)&3)))*16))

__global__ void __launch_bounds__(256, 2)
k_fused(const float* __restrict__ cb3,
        const float* __restrict__ sW3, const float* __restrict__ sb3,
        float* __restrict__ out_cov, float* __restrict__ out_covdiv,
        float* __restrict__ out_score, float* __restrict__ out_trace)
{
    extern __shared__ __nv_bfloat16 smb[];
    int bid = blockIdx.x;
    int t = threadIdx.x;

    if (bid >= 576){
        // ---------------- fp32 tail work (trace / score) ----------------
        float* smemf   = reinterpret_cast<float*>(smb);
        float* sT      = smemf;
        float* partial = smemf + NH*TSTR;
        int r2 = bid - 576;
        if (r2 < 64){
            int b0 = r2 * 32;
            int cg = t & 63, sq = t >> 6;
            load_tileT(sT, g_g1[0], b0);
            __syncthreads();
            unsigned long long acc[4][4];
#pragma unroll
            for (int sp = 0; sp < 4; sp++)
#pragma unroll
                for (int cc = 0; cc < 4; cc++) acc[sp][cc] = 0ull;
            gemm_stream<4>(g_P + cg*4, NH, sT + sq*8, acc);
            float T[8][4];
#pragma unroll
            for (int sp = 0; sp < 4; sp++)
#pragma unroll
                for (int cc = 0; cc < 4; cc++){
                    float2 f = unpack2(acc[sp][cc]);
                    T[2*sp][cc] = f.x; T[2*sp+1][cc] = f.y;
                }
            bilinear_reduce_store(T, g_g2[0], b0, partial, out_trace, 1);
        } else {
            int b0 = (r2 - 64) * 32;
            int i  = t & 31, sg = t >> 5;
            load_tileT(sT, g_h2[0], b0);
            __syncthreads();
            float acc[4];
            float bias = sb3[i];
#pragma unroll
            for (int k = 0; k < 4; k++) acc[k] = bias;
#pragma unroll 4
            for (int a = 0; a < NH; a++){
                float w = sW3[a*ND + i];
                float4 v = *reinterpret_cast<const float4*>(&sT[a*TSTR + sg*4]);
                acc[0] = fmaf(v.x, w, acc[0]);
                acc[1] = fmaf(v.y, w, acc[1]);
                acc[2] = fmaf(v.z, w, acc[2]);
                acc[3] = fmaf(v.w, w, acc[3]);
            }
#pragma unroll
            for (int k = 0; k < 4; k++)
                out_score[(b0 + sg*4 + k)*ND + i] = acc[k];
        }
        return;
    }

    // ---------------- tensor path ----------------
    unsigned smu = (unsigned)__cvta_generic_to_shared(smb);
    int lane = t & 31, wid = t >> 5;
    int wm = wid & 3, wn = wid >> 2;       // 4x2 warp grid
    int g = lane >> 2, tig = lane & 3;
    bool is_cd = bid < 512;

    const __nv_bfloat16 *Ah, *Al, *Bh0, *Bl0;
    int m0, nt = 0, i = 0;
    if (is_cd){
        i = bid & 31; m0 = (bid >> 5)*128;
        Ah = g_g1h; Al = g_g1l;
        Bh0 = g_Qth + (size_t)i*NH*NH; Bl0 = g_Qtl + (size_t)i*NH*NH;
    } else {
        int r = bid - 512; nt = r & 3; m0 = (r >> 2)*128;
        Ah = g_h2h; Al = g_h2l;
        Bh0 = g_w3th + (size_t)nt*256*NH; Bl0 = g_w3tl + (size_t)nt*256*NH;
    }
    const __nv_bfloat16* bsrc[4] = {Ah, Al, Bh0, Bl0};

    float c[2][8][4];
#pragma unroll
    for (int mi = 0; mi < 2; mi++)
#pragma unroll
        for (int ni = 0; ni < 8; ni++)
#pragma unroll
            for (int q = 0; q < 4; q++) c[mi][ni][q] = 0.f;
    float rs[4] = {0.f, 0.f, 0.f, 0.f};

    // ldmatrix lane geometry
    int lrow = lane & 7, sel = lane >> 3;
    int qaSel = sel >> 1, qbSel = sel & 1;
    int ra4[2], rxA[2], rb4[4], rxB[4];
#pragma unroll
    for (int mi = 0; mi < 2; mi++){
        int ra = wm*32 + mi*16 + (sel & 1)*8 + lrow;
        ra4[mi] = ra*4; rxA[mi] = (ra >> 1) & 3;
    }
#pragma unroll
    for (int p = 0; p < 4; p++){
        int rb = wn*64 + p*16 + (sel >> 1)*8 + lrow;
        rb4[p] = rb*4; rxB[p] = (rb >> 1) & 3;
    }

    // staging: thread covers 8 x 16B; p -> buffer p>>1
    int sr = ((t & 3) == (t & 3)) ? 0 : 0; (void)sr;
    auto stage = [&](int j){
        int nh = j >> 3, k0 = (j & 7)*KC;
        unsigned sb = smu + (unsigned)(j % 3)*STG_B;
#pragma unroll
        for (int p = 0; p < 8; p++){
            const int buf = p >> 1;
            int r = ((p & 1) << 6) + (t >> 2);
            int q = t & 3;
            int grow = (buf < 2 ? m0 : nh*128) + r;
            cpa16(sb + (unsigned)buf*BUF_B + SWZ(r, q),
                  bsrc[buf] + (size_t)grow*NH + k0 + q*8);
        }
        cpa_commit();
    };

    stage(0); stage(1);

#pragma unroll 1
    for (int j = 0; j < 16; j++){
        __syncthreads();                 // all warps done reading buffer (j+2)%3
        if (j + 2 < 16) stage(j + 2);
        if (j < 14) cpa_wait<2>();
        else if (j == 14) cpa_wait<1>();
        else cpa_wait<0>();
        // NOTE: cp.async completion is per-thread visible; smem data written by
        // OTHER threads for buffer j was committed at least 2 chunks ago and its
        // group completion was awaited by the writer before the sync above.
        __syncwarp();

        unsigned sb = smu + (unsigned)(j % 3)*STG_B;

#pragma unroll
        for (int ks = 0; ks < 2; ks++){
            unsigned ah[2][4], al[2][4];
#pragma unroll
            for (int mi = 0; mi < 2; mi++){
                unsigned off = (unsigned)((ra4[mi] + ((ks*2 + qaSel) ^ rxA[mi])) << 4);
                ldsm4(ah[mi], sb + off);
                ldsm4(al[mi], sb + BUF_B + off);
            }
#pragma unroll
            for (int p = 0; p < 4; p++){
                unsigned offb = (unsigned)((rb4[p] + ((ks*2 + qbSel) ^ rxB[p])) << 4);
                unsigned bh[4], bl[4];
                ldsm4(bh, sb + 2*BUF_B + offb);
                ldsm4(bl, sb + 3*BUF_B + offb);
#pragma unroll
                for (int sub = 0; sub < 2; sub++)
#pragma unroll
                    for (int mi = 0; mi < 2; mi++)
                        mma16816(c[mi][2*p+sub], ah[mi], bh[sub*2], bh[sub*2+1]);
#pragma unroll
                for (int sub = 0; sub < 2; sub++)
#pragma unroll
                    for (int mi = 0; mi < 2; mi++)
                        mma16816(c[mi][2*p+sub], ah[mi], bl[sub*2], bl[sub*2+1]);
#pragma unroll
                for (int sub = 0; sub < 2; sub++)
#pragma unroll
                    for (int mi = 0; mi < 2; mi++)
                        mma16816(c[mi][2*p+sub], al[mi], bh[sub*2], bh[sub*2+1]);
            }
        }

        if ((j & 7) == 7){
            int nh = j >> 3;
            if (is_cd){
#pragma unroll
                for (int mi = 0; mi < 2; mi++){
#pragma unroll
                    for (int hf = 0; hf < 2; hf++){
                        int m = m0 + wm*32 + mi*16 + g + hf*8;
                        const float* g2r = g_g2[1] + (size_t)m*NH + nh*128;
                        float s = 0.f;
#pragma unroll
                        for (int ni = 0; ni < 8; ni++){
                            int col = wn*64 + ni*8 + tig*2;
                            float2 gg = *reinterpret_cast<const float2*>(g2r + col);
                            s += c[mi][ni][hf*2+0]*gg.x + c[mi][ni][hf*2+1]*gg.y;
                        }
                        rs[mi*2+hf] += s;
                    }
                }
            } else {
                int n0 = nt*256 + nh*128;
#pragma unroll
                for (int mi = 0; mi < 2; mi++){
#pragma unroll
                    for (int hf = 0; hf < 2; hf++){
                        int m = m0 + wm*32 + mi*16 + g + hf*8;
#pragma unroll
                        for (int ni = 0; ni < 8; ni++){
                            int col = n0 + wn*64 + ni*8 + tig*2;
                            float2 b = *reinterpret_cast<const float2*>(cb3 + col);
                            float2 v;
                            v.x = c[mi][ni][hf*2+0] + b.x;
                            v.y = c[mi][ni][hf*2+1] + b.y;
                            *reinterpret_cast<float2*>(out_cov + (size_t)m*(ND*ND) + col) = v;
                        }
                    }
                }
            }
            if (j < 15){
#pragma unroll
                for (int mi = 0; mi < 2; mi++)
#pragma unroll
                    for (int ni = 0; ni < 8; ni++)
#pragma unroll
                        for (int q = 0; q < 4; q++) c[mi][ni][q] = 0.f;
            }
        }
    }

    if (is_cd){
#pragma unroll
        for (int off = 1; off < 4; off <<= 1)
#pragma unroll
            for (int q = 0; q < 4; q++)
                rs[q] += __shfl_xor_sync(0xffffffffu, rs[q], off);
        float* red = reinterpret_cast<float*>(smb);   // [2 wn][128]
        __syncthreads();
        if (tig == 0){
#pragma unroll
            for (int mi = 0; mi < 2; mi++)
#pragma unroll
                for (int hf = 0; hf < 2; hf++)
                    red[wn*128 + wm*32 + mi*16 + g + hf*8] = rs[mi*2+hf];
        }
        __syncthreads();
        if (t < 128)
            out_covdiv[(size_t)(m0 + t)*ND + i] = red[t] + red[128+t];
    }
}

// ---------------- launch ----------------
extern "C" void kernel_launch(void* const* d_in, const int* in_sizes, int n_in,
                              void* d_out, int out_size){
    const float* x   = (const float*)d_in[0];
    const float* sW1 = (const float*)d_in[1];
    const float* sb1 = (const float*)d_in[2];
    const float* sW2 = (const float*)d_in[3];
    const float* sb2 = (const float*)d_in[4];
    const float* sW3 = (const float*)d_in[5];
    const float* sb3 = (const float*)d_in[6];
    const float* cW1 = (const float*)d_in[7];
    const float* cb1 = (const float*)d_in[8];
    const float* cW2 = (const float*)d_in[9];
    const float* cb2 = (const float*)d_in[10];
    const float* cW3 = (const float*)d_in[11];
    const float* cb3 = (const float*)d_in[12];

    float* out        = (float*)d_out;
    float* out_score  = out;                                   // [B,32]
    float* out_trace  = out + NB*ND;                           // [B]
    float* out_cov    = out + NB*ND + NB;                      // [B,1024]
    float* out_covdiv = out + NB*ND + NB + NB*ND*ND;           // [B,32]

    static int inited = 0;
    if (!inited){
        cudaFuncSetAttribute(k_fused, cudaFuncAttributeMaxDynamicSharedMemorySize, MM_SMEM);
        inited = 1;
    }

    k_stageA<<<1056, 256>>>(x, sW1, sb1, sW2, sW3, cW1, cb1, cW2, cW3);
    k_stageB<<<dim3(64,2,2), 256, SM_BYTES>>>(sW2, sb2, cW2, cb2);
    k_fused<<<704, 256, MM_SMEM>>>(cb3, sW3, sb3,
                                   out_cov, out_covdiv, out_score, out_trace);
}

// round 16
// speedup vs baseline: 6.9415x; 1.1164x over previous
#include <cuda_runtime.h>
#include <cuda_bf16.h>

#define NB 2048
#define ND 32
#define NH 256
#define TSTR 36   // padded smem stride (floats)

// ---------------- fp32 scratch ----------------
__device__ float g_h1[2][NB*NH];
__device__ float g_g1[2][NB*NH];
__device__ float g_h2[2][NB*NH];
__device__ float g_g2[2][NB*NH];
__device__ float g_P[NH*NH];

// ---------------- bf16 split scratch (cov-net tensor path) ----------------
__device__ __nv_bfloat16 g_g1h[NB*NH], g_g1l[NB*NH];        // gc1 split
__device__ __nv_bfloat16 g_h2h[NB*NH], g_h2l[NB*NH];        // h2c split
__device__ __nv_bfloat16 g_Qth[ND*NH*NH], g_Qtl[ND*NH*NH];  // Qt[i][c][a]
__device__ __nv_bfloat16 g_w3th[ND*ND*NH], g_w3tl[ND*ND*NH];// cW3t[n][a]

#define SM_FLOATS (NH*TSTR + 64)
#define SM_BYTES  (SM_FLOATS*4)
#define MID_SMEM  ((256*33 + 32*33)*4)   // 38016 B (precompQ is the max user)

// ---------------- packed fp32x2 helpers ----------------
static __device__ __forceinline__ unsigned long long pack2(float x, float y){
    unsigned long long r;
    asm("mov.b64 %0, {%1, %2};" : "=l"(r)
        : "r"(__float_as_uint(x)), "r"(__float_as_uint(y)));
    return r;
}
static __device__ __forceinline__ float2 unpack2(unsigned long long v){
    unsigned lo, hi;
    asm("mov.b64 {%0, %1}, %2;" : "=r"(lo), "=r"(hi) : "l"(v));
    return make_float2(__uint_as_float(lo), __uint_as_float(hi));
}
static __device__ __forceinline__ void ffma2(unsigned long long &d,
                                             unsigned long long a,
                                             unsigned long long b){
    asm("fma.rn.f32x2 %0, %1, %2, %0;" : "+l"(d) : "l"(a), "l"(b));
}
static __device__ __forceinline__ void bf16split(float v, __nv_bfloat16& hi, __nv_bfloat16& lo){
    hi = __float2bfloat16(v);
    lo = __float2bfloat16(v - __bfloat162float(hi));
}

// load 32 samples x 256 features, transposed into smem: sm[a*TSTR + s]
static __device__ __forceinline__ void load_tileT(float* sm, const float* g, int b0){
    for (int idx = threadIdx.x; idx < 32*NH; idx += 256){
        int s = idx >> 8;
        int a = idx & 255;
        sm[a*TSTR + s] = g[(b0 + s)*NH + a];
    }
}

// ---------------- fp32 streaming GEMM core ----------------
template<int SP>
static __device__ __forceinline__ void gemm_stream(
    const float* __restrict__ Wt, int wstride,
    const float* __restrict__ sTs,
    unsigned long long (&acc)[SP][4])
{
#pragma unroll 8
    for (int a = 0; a < NH; a++){
        float4 wq = __ldg(reinterpret_cast<const float4*>(Wt + (size_t)a*wstride));
        unsigned long long w0 = pack2(wq.x, wq.x);
        unsigned long long w1 = pack2(wq.y, wq.y);
        unsigned long long w2 = pack2(wq.z, wq.z);
        unsigned long long w3 = pack2(wq.w, wq.w);
        const float* srow = sTs + a*TSTR;
#pragma unroll
        for (int p = 0; p < SP/2; p++){
            ulonglong2 r = *reinterpret_cast<const ulonglong2*>(srow + p*4);
            ffma2(acc[2*p][0],   r.x, w0); ffma2(acc[2*p][1],   r.x, w1);
            ffma2(acc[2*p][2],   r.x, w2); ffma2(acc[2*p][3],   r.x, w3);
            ffma2(acc[2*p+1][0], r.y, w0); ffma2(acc[2*p+1][1], r.y, w1);
            ffma2(acc[2*p+1][2], r.y, w2); ffma2(acc[2*p+1][3], r.y, w3);
        }
    }
}

static __device__ __forceinline__ void bilinear_reduce_store(
    const float T[8][4], const float* __restrict__ g2row, int b0,
    float* __restrict__ partial, float* __restrict__ outp, int ostride)
{
    int cg = threadIdx.x & 63;
    int sq = threadIdx.x >> 6;
    float val[8];
#pragma unroll
    for (int s = 0; s < 8; s++){
        float4 gq = *reinterpret_cast<const float4*>(&g2row[(b0 + sq*8 + s)*NH + cg*4]);
        val[s] = T[s][0]*gq.x + T[s][1]*gq.y + T[s][2]*gq.z + T[s][3]*gq.w;
    }
#pragma unroll
    for (int off = 16; off; off >>= 1)
#pragma unroll
        for (int s = 0; s < 8; s++)
            val[s] += __shfl_xor_sync(0xffffffffu, val[s], off);
    int w = threadIdx.x >> 5;
    if ((threadIdx.x & 31) == 0){
#pragma unroll
        for (int s = 0; s < 8; s++) partial[w*8 + s] = val[s];
    }
    __syncthreads();
    if (threadIdx.x < 32){
        int sq2 = threadIdx.x >> 3, s = threadIdx.x & 7;
        float v = partial[(2*sq2)*8 + s] + partial[(2*sq2+1)*8 + s];
        outp[(b0 + threadIdx.x)*ostride] = v;
    }
}

// ---------------- mma.sync / ldmatrix / cp.async helpers (baseline PTX) -------------
static __device__ __forceinline__ void mma16816(float (&c)[4],
    const unsigned (&a)[4], unsigned b0, unsigned b1)
{
    asm volatile("mma.sync.aligned.m16n8k16.row.col.f32.bf16.bf16.f32 "
        "{%0,%1,%2,%3}, {%4,%5,%6,%7}, {%8,%9}, {%0,%1,%2,%3};"
        : "+f"(c[0]), "+f"(c[1]), "+f"(c[2]), "+f"(c[3])
        : "r"(a[0]), "r"(a[1]), "r"(a[2]), "r"(a[3]), "r"(b0), "r"(b1));
}
static __device__ __forceinline__ void ldsm4(unsigned (&r)[4], unsigned addr){
    asm volatile("ldmatrix.sync.aligned.m8n8.x4.shared.b16 {%0,%1,%2,%3}, [%4];"
        : "=r"(r[0]), "=r"(r[1]), "=r"(r[2]), "=r"(r[3]) : "r"(addr));
}
static __device__ __forceinline__ void cpa16(unsigned saddr, const void* g){
    asm volatile("cp.async.cg.shared.global [%0], [%1], 16;" :: "r"(saddr), "l"(g));
}
static __device__ __forceinline__ void cpa_commit(){
    asm volatile("cp.async.commit_group;" ::: "memory");
}
template<int N>
static __device__ __forceinline__ void cpa_wait(){
    asm volatile("cp.async.wait_group %0;" :: "n"(N) : "memory");
}

// ======================= K1: layer1 (both nets) =======================
// grid 512: net = bid>>8, b0 = (bid&255)*8
__global__ void __launch_bounds__(256)
k_layer1(const float* __restrict__ x,
         const float* __restrict__ sW1, const float* __restrict__ sb1,
         const float* __restrict__ cW1, const float* __restrict__ cb1)
{
    __shared__ float xs[8*32];
    int bid = blockIdx.x;
    int t = threadIdx.x;
    int net = bid >> 8;
    int b0  = (bid & 255) * 8;
    const float* W1 = net ? cW1 : sW1;
    const float* b1 = net ? cb1 : sb1;
    xs[t] = x[b0*ND + t];
    __syncthreads();
    float acc[8];
    float bias = b1[t];
#pragma unroll
    for (int s = 0; s < 8; s++) acc[s] = bias;
#pragma unroll
    for (int k = 0; k < ND; k++){
        float w = W1[k*NH + t];
#pragma unroll
        for (int s = 0; s < 8; s++) acc[s] = fmaf(xs[s*32 + k], w, acc[s]);
    }
    float* hout = g_h1[net];
    float* gout = g_g1[net];
#pragma unroll
    for (int s = 0; s < 8; s++){
        float h = tanhf(acc[s]);
        float g = 1.0f - h*h;
        int row = (b0+s)*NH + t;
        hout[row] = h;
        gout[row] = g;
        if (net == 1){
            __nv_bfloat16 hi, lo; bf16split(g, hi, lo);
            g_g1h[row] = hi; g_g1l[row] = lo;
        }
    }
}

// ======================= K_MID: layer2 | precompQ | transpose | precompP ============
// grid 576: [0,256) layer2 | [256,512) precompQ | [512,544) cW3-transpose | [544,576) precompP
__global__ void __launch_bounds__(256)
k_mid(const float* __restrict__ sW1,
      const float* __restrict__ sW2, const float* __restrict__ sb2,
      const float* __restrict__ sW3,
      const float* __restrict__ cW1,
      const float* __restrict__ cW2, const float* __restrict__ cb2,
      const float* __restrict__ cW3)
{
    extern __shared__ float smemf[];
    int bid = blockIdx.x;
    int t = threadIdx.x;

    if (bid < 256){
        // ---- layer2: h2 = tanh(h1@W2+b2), g2 = 1-h2^2 (+ bf16 split for cov net)
        int net   = bid >> 7;
        int chalf = (bid >> 6) & 1;
        int b0    = (bid & 63) * 32;
        float* sT = smemf;
        const float* W    = net ? cW2 : sW2;
        const float* bias = net ? cb2 : sb2;
        int cg = t & 31;
        int sq = t >> 5;
        int c0 = chalf*128 + cg*4;

        load_tileT(sT, g_h1[net], b0);
        __syncthreads();

        float4 bq = *reinterpret_cast<const float4*>(&bias[c0]);
        unsigned long long acc[2][4];
        acc[0][0] = pack2(bq.x, bq.x); acc[0][1] = pack2(bq.y, bq.y);
        acc[0][2] = pack2(bq.z, bq.z); acc[0][3] = pack2(bq.w, bq.w);
#pragma unroll
        for (int cc = 0; cc < 4; cc++) acc[1][cc] = acc[0][cc];

        gemm_stream<2>(W + c0, NH, sT + sq*4, acc);

        float* h2 = g_h2[net];
        float* g2 = g_g2[net];
#pragma unroll
        for (int p = 0; p < 2; p++){
#pragma unroll
            for (int half = 0; half < 2; half++){
                float v[4];
#pragma unroll
                for (int cc = 0; cc < 4; cc++){
                    float2 f = unpack2(acc[p][cc]);
                    v[cc] = half ? f.y : f.x;
                }
                float4 hv, gv;
                hv.x = tanhf(v[0]); hv.y = tanhf(v[1]);
                hv.z = tanhf(v[2]); hv.w = tanhf(v[3]);
                gv.x = 1.0f - hv.x*hv.x; gv.y = 1.0f - hv.y*hv.y;
                gv.z = 1.0f - hv.z*hv.z; gv.w = 1.0f - hv.w*hv.w;
                int row = (b0 + sq*4 + p*2 + half)*NH + c0;
                *reinterpret_cast<float4*>(&h2[row]) = hv;
                *reinterpret_cast<float4*>(&g2[row]) = gv;
                if (net == 1){
                    __nv_bfloat16 hi, lo;
                    bf16split(hv.x, hi, lo); g_h2h[row+0] = hi; g_h2l[row+0] = lo;
                    bf16split(hv.y, hi, lo); g_h2h[row+1] = hi; g_h2l[row+1] = lo;
                    bf16split(hv.z, hi, lo); g_h2h[row+2] = hi; g_h2l[row+2] = lo;
                    bf16split(hv.w, hi, lo); g_h2h[row+3] = hi; g_h2l[row+3] = lo;
                }
            }
        }
    } else if (bid < 512){
        // ---- precompQ: Qt[i][c][a] = cW2[a,c] * sum_j cW1[j,a]*cW3[c,i*32+j]
        int r  = bid - 256;
        int i  = r & 31;
        int c0 = (r >> 5) * 32;
        float* w2s = smemf;            // [256][33]
        float* w3s = smemf + 256*33;   // [32][33]
        for (int idx = t; idx < 256*32; idx += 256){
            int ar = idx >> 5, cc = idx & 31;
            w2s[ar*33 + cc] = cW2[ar*NH + c0 + cc];
        }
        for (int idx = t; idx < 32*32; idx += 256){
            int cr = idx >> 5, j = idx & 31;
            w3s[cr*33 + j] = cW3[(c0 + cr)*(ND*ND) + i*ND + j];
        }
        __syncthreads();
        int a = t;
        float w1r[ND];
#pragma unroll
        for (int j = 0; j < ND; j++) w1r[j] = cW1[j*NH + a];
#pragma unroll 4
        for (int cc = 0; cc < 32; cc++){
            float acc = 0.f;
#pragma unroll
            for (int j = 0; j < ND; j++) acc = fmaf(w1r[j], w3s[cc*33 + j], acc);
            float q = w2s[a*33 + cc] * acc;
            __nv_bfloat16 hi, lo; bf16split(q, hi, lo);
            size_t o = ((size_t)i*NH + c0 + cc)*NH + a;
            g_Qth[o] = hi; g_Qtl[o] = lo;
        }
    } else if (bid < 544){
        // ---- transpose cW3 -> w3t[n][a] bf16 hi/lo
        int n0 = (bid - 512) * 32;
        float* s = smemf;  // [32][33]
        for (int a0 = 0; a0 < NH; a0 += 32){
            __syncthreads();
#pragma unroll
            for (int pp = 0; pp < 4; pp++){
                int ar = (t >> 5) + pp*8, nc = t & 31;
                s[ar*33 + nc] = cW3[(a0 + ar)*(ND*ND) + n0 + nc];
            }
            __syncthreads();
#pragma unroll
            for (int pp = 0; pp < 4; pp++){
                int nn = (t >> 5) + pp*8, aa = t & 31;
                float v = s[aa*33 + nn];
                __nv_bfloat16 hi, lo; bf16split(v, hi, lo);
                size_t o = ((size_t)(n0 + nn))*NH + a0 + aa;
                g_w3th[o] = hi; g_w3tl[o] = lo;
            }
        }
    } else {
        // ---- precompP (coalesced): P[a][c] = sW2[a,c] * sum_i sW3[c,i]*sW1[i,a]
        // 32 blocks, 8 a-rows each; sW3 staged coalesced, read back stride-33.
        int a0 = (bid - 544) * 8;
        float* s3s = smemf;            // [256][33]
        float* w1s = smemf + 256*33;   // [32][8]
        for (int idx = t; idx < 256*32; idx += 256){
            int cc = idx >> 5, ii = idx & 31;
            s3s[cc*33 + ii] = sW3[cc*ND + ii];
        }
        if (t < 256){
            // w1s[i][aa] for i<32, aa<8 : 256 entries, one per thread
            int ii = t >> 3, aa = t & 7;
            w1s[ii*8 + aa] = sW1[ii*NH + a0 + aa];
        }
        __syncthreads();
        int c = t;
        float accv[8];
#pragma unroll
        for (int aa = 0; aa < 8; aa++) accv[aa] = 0.f;
#pragma unroll
        for (int ii = 0; ii < ND; ii++){
            float s3 = s3s[c*33 + ii];
#pragma unroll
            for (int aa = 0; aa < 8; aa++)
                accv[aa] = fmaf(s3, w1s[ii*8 + aa], accv[aa]);
        }
#pragma unroll
        for (int aa = 0; aa < 8; aa++)
            g_P[(a0 + aa)*NH + c] = sW2[(a0 + aa)*NH + c] * accv[aa];
    }
}

// ======================= FUSED TENSOR KERNEL =======================
// grid 704:
//   [0,512)   covdiv   (i = bid&31, mt = bid>>5)
//   [512,576) layer3_cov (nt = r&3, mt = r>>2)
//   [576,640) trace    (fp32, tail-fills tensor-idle SMs)
//   [640,704) score
#define KC     32
#define BUF_B  8192u                // one buffer: 128 rows x 64B
#define STG_B  (4*BUF_B)            // Ah|Al|Bh|Bl = 32KB
#define MM_SMEM (3*STG_B)           // 98304
#define SWZ(r, q) ((unsigned)(((r)*4 + ((q) ^ (((r)>>1)&3)))*16))

__global__ void __launch_bounds__(256, 2)
k_fused(const float* __restrict__ cb3,
        const float* __restrict__ sW3, const float* __restrict__ sb3,
        float* __restrict__ out_cov, float* __restrict__ out_covdiv,
        float* __restrict__ out_score, float* __restrict__ out_trace)
{
    extern __shared__ __nv_bfloat16 smb[];
    int bid = blockIdx.x;
    int t = threadIdx.x;

    if (bid >= 576){
        // ---------------- fp32 tail work (trace / score) ----------------
        float* smemf   = reinterpret_cast<float*>(smb);
        float* sT      = smemf;
        float* partial = smemf + NH*TSTR;
        int r2 = bid - 576;
        if (r2 < 64){
            int b0 = r2 * 32;
            int cg = t & 63, sq = t >> 6;
            load_tileT(sT, g_g1[0], b0);
            __syncthreads();
            unsigned long long acc[4][4];
#pragma unroll
            for (int sp = 0; sp < 4; sp++)
#pragma unroll
                for (int cc = 0; cc < 4; cc++) acc[sp][cc] = 0ull;
            gemm_stream<4>(g_P + cg*4, NH, sT + sq*8, acc);
            float T[8][4];
#pragma unroll
            for (int sp = 0; sp < 4; sp++)
#pragma unroll
                for (int cc = 0; cc < 4; cc++){
                    float2 f = unpack2(acc[sp][cc]);
                    T[2*sp][cc] = f.x; T[2*sp+1][cc] = f.y;
                }
            bilinear_reduce_store(T, g_g2[0], b0, partial, out_trace, 1);
        } else {
            int b0 = (r2 - 64) * 32;
            int i  = t & 31, sg = t >> 5;
            load_tileT(sT, g_h2[0], b0);
            __syncthreads();
            float acc[4];
            float bias = sb3[i];
#pragma unroll
            for (int k = 0; k < 4; k++) acc[k] = bias;
#pragma unroll 4
            for (int a = 0; a < NH; a++){
                float w = sW3[a*ND + i];
                float4 v = *reinterpret_cast<const float4*>(&sT[a*TSTR + sg*4]);
                acc[0] = fmaf(v.x, w, acc[0]);
                acc[1] = fmaf(v.y, w, acc[1]);
                acc[2] = fmaf(v.z, w, acc[2]);
                acc[3] = fmaf(v.w, w, acc[3]);
            }
#pragma unroll
            for (int k = 0; k < 4; k++)
                out_score[(b0 + sg*4 + k)*ND + i] = acc[k];
        }
        return;
    }

    // ---------------- tensor path ----------------
    unsigned smu = (unsigned)__cvta_generic_to_shared(smb);
    int lane = t & 31, wid = t >> 5;
    int wm = wid & 3, wn = wid >> 2;       // 4x2 warp grid
    int g = lane >> 2, tig = lane & 3;
    bool is_cd = bid < 512;

    const __nv_bfloat16 *Ah, *Al, *Bh0, *Bl0;
    int m0, nt = 0, i = 0;
    if (is_cd){
        i = bid & 31; m0 = (bid >> 5)*128;
        Ah = g_g1h; Al = g_g1l;
        Bh0 = g_Qth + (size_t)i*NH*NH; Bl0 = g_Qtl + (size_t)i*NH*NH;
    } else {
        int r = bid - 512; nt = r & 3; m0 = (r >> 2)*128;
        Ah = g_h2h; Al = g_h2l;
        Bh0 = g_w3th + (size_t)nt*256*NH; Bl0 = g_w3tl + (size_t)nt*256*NH;
    }
    const __nv_bfloat16* bsrc[4] = {Ah, Al, Bh0, Bl0};

    float c[2][8][4];
#pragma unroll
    for (int mi = 0; mi < 2; mi++)
#pragma unroll
        for (int ni = 0; ni < 8; ni++)
#pragma unroll
            for (int q = 0; q < 4; q++) c[mi][ni][q] = 0.f;
    float rs[4] = {0.f, 0.f, 0.f, 0.f};

    // ldmatrix lane geometry
    int lrow = lane & 7, sel = lane >> 3;
    int qaSel = sel >> 1, qbSel = sel & 1;
    int ra4[2], rxA[2], rb4[4], rxB[4];
#pragma unroll
    for (int mi = 0; mi < 2; mi++){
        int ra = wm*32 + mi*16 + (sel & 1)*8 + lrow;
        ra4[mi] = ra*4; rxA[mi] = (ra >> 1) & 3;
    }
#pragma unroll
    for (int p = 0; p < 4; p++){
        int rb = wn*64 + p*16 + (sel >> 1)*8 + lrow;
        rb4[p] = rb*4; rxB[p] = (rb >> 1) & 3;
    }

    auto stage = [&](int j){
        int nh = j >> 3, k0 = (j & 7)*KC;
        unsigned sb = smu + (unsigned)(j % 3)*STG_B;
#pragma unroll
        for (int p = 0; p < 8; p++){
            const int buf = p >> 1;
            int r = ((p & 1) << 6) + (t >> 2);
            int q = t & 3;
            int grow = (buf < 2 ? m0 : nh*128) + r;
            cpa16(sb + (unsigned)buf*BUF_B + SWZ(r, q),
                  bsrc[buf] + (size_t)grow*NH + k0 + q*8);
        }
        cpa_commit();
    };

    stage(0); stage(1);

#pragma unroll 1
    for (int j = 0; j < 16; j++){
        __syncthreads();                 // all warps done reading buffer (j+2)%3
        if (j + 2 < 16) stage(j + 2);
        if (j < 14) cpa_wait<2>();
        else if (j == 14) cpa_wait<1>();
        else cpa_wait<0>();
        __syncwarp();

        unsigned sb = smu + (unsigned)(j % 3)*STG_B;

#pragma unroll
        for (int ks = 0; ks < 2; ks++){
            unsigned ah[2][4], al[2][4];
#pragma unroll
            for (int mi = 0; mi < 2; mi++){
                unsigned off = (unsigned)((ra4[mi] + ((ks*2 + qaSel) ^ rxA[mi])) << 4);
                ldsm4(ah[mi], sb + off);
                ldsm4(al[mi], sb + BUF_B + off);
            }
#pragma unroll
            for (int p = 0; p < 4; p++){
                unsigned offb = (unsigned)((rb4[p] + ((ks*2 + qbSel) ^ rxB[p])) << 4);
                unsigned bh[4], bl[4];
                ldsm4(bh, sb + 2*BUF_B + offb);
                ldsm4(bl, sb + 3*BUF_B + offb);
#pragma unroll
                for (int sub = 0; sub < 2; sub++)
#pragma unroll
                    for (int mi = 0; mi < 2; mi++)
                        mma16816(c[mi][2*p+sub], ah[mi], bh[sub*2], bh[sub*2+1]);
#pragma unroll
                for (int sub = 0; sub < 2; sub++)
#pragma unroll
                    for (int mi = 0; mi < 2; mi++)
                        mma16816(c[mi][2*p+sub], ah[mi], bl[sub*2], bl[sub*2+1]);
#pragma unroll
                for (int sub = 0; sub < 2; sub++)
#pragma unroll
                    for (int mi = 0; mi < 2; mi++)
                        mma16816(c[mi][2*p+sub], al[mi], bh[sub*2], bh[sub*2+1]);
            }
        }

        if ((j & 7) == 7){
            int nh = j >> 3;
            if (is_cd){
#pragma unroll
                for (int mi = 0; mi < 2; mi++){
#pragma unroll
                    for (int hf = 0; hf < 2; hf++){
                        int m = m0 + wm*32 + mi*16 + g + hf*8;
                        const float* g2r = g_g2[1] + (size_t)m*NH + nh*128;
                        float s = 0.f;
#pragma unroll
                        for (int ni = 0; ni < 8; ni++){
                            int col = wn*64 + ni*8 + tig*2;
                            float2 gg = *reinterpret_cast<const float2*>(g2r + col);
                            s += c[mi][ni][hf*2+0]*gg.x + c[mi][ni][hf*2+1]*gg.y;
                        }
                        rs[mi*2+hf] += s;
                    }
                }
            } else {
                int n0 = nt*256 + nh*128;
#pragma unroll
                for (int mi = 0; mi < 2; mi++){
#pragma unroll
                    for (int hf = 0; hf < 2; hf++){
                        int m = m0 + wm*32 + mi*16 + g + hf*8;
#pragma unroll
                        for (int ni = 0; ni < 8; ni++){
                            int col = n0 + wn*64 + ni*8 + tig*2;
                            float2 b = *reinterpret_cast<const float2*>(cb3 + col);
                            float2 v;
                            v.x = c[mi][ni][hf*2+0] + b.x;
                            v.y = c[mi][ni][hf*2+1] + b.y;
                            *reinterpret_cast<float2*>(out_cov + (size_t)m*(ND*ND) + col) = v;
                        }
                    }
                }
            }
            if (j < 15){
#pragma unroll
                for (int mi = 0; mi < 2; mi++)
#pragma unroll
                    for (int ni = 0; ni < 8; ni++)
#pragma unroll
                        for (int q = 0; q < 4; q++) c[mi][ni][q] = 0.f;
            }
        }
    }

    if (is_cd){
#pragma unroll
        for (int off = 1; off < 4; off <<= 1)
#pragma unroll
            for (int q = 0; q < 4; q++)
                rs[q] += __shfl_xor_sync(0xffffffffu, rs[q], off);
        float* red = reinterpret_cast<float*>(smb);   // [2 wn][128]
        __syncthreads();
        if (tig == 0){
#pragma unroll
            for (int mi = 0; mi < 2; mi++)
#pragma unroll
                for (int hf = 0; hf < 2; hf++)
                    red[wn*128 + wm*32 + mi*16 + g + hf*8] = rs[mi*2+hf];
        }
        __syncthreads();
        if (t < 128)
            out_covdiv[(size_t)(m0 + t)*ND + i] = red[t] + red[128+t];
    }
}

// ---------------- launch ----------------
extern "C" void kernel_launch(void* const* d_in, const int* in_sizes, int n_in,
                              void* d_out, int out_size){
    const float* x   = (const float*)d_in[0];
    const float* sW1 = (const float*)d_in[1];
    const float* sb1 = (const float*)d_in[2];
    const float* sW2 = (const float*)d_in[3];
    const float* sb2 = (const float*)d_in[4];
    const float* sW3 = (const float*)d_in[5];
    const float* sb3 = (const float*)d_in[6];
    const float* cW1 = (const float*)d_in[7];
    const float* cb1 = (const float*)d_in[8];
    const float* cW2 = (const float*)d_in[9];
    const float* cb2 = (const float*)d_in[10];
    const float* cW3 = (const float*)d_in[11];
    const float* cb3 = (const float*)d_in[12];

    float* out        = (float*)d_out;
    float* out_score  = out;                                   // [B,32]
    float* out_trace  = out + NB*ND;                           // [B]
    float* out_cov    = out + NB*ND + NB;                      // [B,1024]
    float* out_covdiv = out + NB*ND + NB + NB*ND*ND;           // [B,32]

    static int inited = 0;
    if (!inited){
        cudaFuncSetAttribute(k_fused, cudaFuncAttributeMaxDynamicSharedMemorySize, MM_SMEM);
        cudaFuncSetAttribute(k_mid,   cudaFuncAttributeMaxDynamicSharedMemorySize, MID_SMEM);
        inited = 1;
    }

    k_layer1<<<512, 256>>>(x, sW1, sb1, cW1, cb1);
    k_mid<<<576, 256, MID_SMEM>>>(sW1, sW2, sb2, sW3, cW1, cW2, cb2, cW3);
    k_fused<<<704, 256, MM_SMEM>>>(cb3, sW3, sb3,
                                   out_cov, out_covdiv, out_score, out_trace);
}

// round 17
// speedup vs baseline: 6.9434x; 1.0003x over previous
#include <cuda_runtime.h>
#include <cuda_bf16.h>

#define NB 2048
#define ND 32
#define NH 256
#define TSTR 36   // padded smem stride (floats)

// ---------------- fp32 scratch ----------------
__device__ float g_g1[NB*NH];          // score-net g1 (fp32, for trace)
__device__ float g_h2[2][NB*NH];
__device__ float g_g2[2][NB*NH];
__device__ float g_P[NH*NH];

// ---------------- bf16 split scratch (cov-net tensor path) ----------------
__device__ __nv_bfloat16 g_g1h[NB*NH], g_g1l[NB*NH];        // gc1 split
__device__ __nv_bfloat16 g_h2h[NB*NH], g_h2l[NB*NH];        // h2c split
__device__ __nv_bfloat16 g_Qth[ND*NH*NH], g_Qtl[ND*NH*NH];  // Qt[i][c][a]
__device__ __nv_bfloat16 g_w3th[ND*ND*NH], g_w3tl[ND*ND*NH];// cW3t[n][a]

#define SM_FLOATS (NH*TSTR + 64)
#define SM_BYTES  (SM_FLOATS*4)
#define MID_SMEM  ((NH*TSTR + 1024 > 256*33 + 32*33 ? NH*TSTR + 1024 : 256*33 + 32*33)*4)

// ---------------- packed fp32x2 helpers ----------------
static __device__ __forceinline__ unsigned long long pack2(float x, float y){
    unsigned long long r;
    asm("mov.b64 %0, {%1, %2};" : "=l"(r)
        : "r"(__float_as_uint(x)), "r"(__float_as_uint(y)));
    return r;
}
static __device__ __forceinline__ float2 unpack2(unsigned long long v){
    unsigned lo, hi;
    asm("mov.b64 {%0, %1}, %2;" : "=r"(lo), "=r"(hi) : "l"(v));
    return make_float2(__uint_as_float(lo), __uint_as_float(hi));
}
static __device__ __forceinline__ void ffma2(unsigned long long &d,
                                             unsigned long long a,
                                             unsigned long long b){
    asm("fma.rn.f32x2 %0, %1, %2, %0;" : "+l"(d) : "l"(a), "l"(b));
}
static __device__ __forceinline__ void bf16split(float v, __nv_bfloat16& hi, __nv_bfloat16& lo){
    hi = __float2bfloat16(v);
    lo = __float2bfloat16(v - __bfloat162float(hi));
}

// load 32 samples x 256 features, transposed into smem: sm[a*TSTR + s]
static __device__ __forceinline__ void load_tileT(float* sm, const float* g, int b0){
    for (int idx = threadIdx.x; idx < 32*NH; idx += 256){
        int s = idx >> 8;
        int a = idx & 255;
        sm[a*TSTR + s] = g[(b0 + s)*NH + a];
    }
}

// ---------------- fp32 streaming GEMM core ----------------
template<int SP>
static __device__ __forceinline__ void gemm_stream(
    const float* __restrict__ Wt, int wstride,
    const float* __restrict__ sTs,
    unsigned long long (&acc)[SP][4])
{
#pragma unroll 8
    for (int a = 0; a < NH; a++){
        float4 wq = __ldg(reinterpret_cast<const float4*>(Wt + (size_t)a*wstride));
        unsigned long long w0 = pack2(wq.x, wq.x);
        unsigned long long w1 = pack2(wq.y, wq.y);
        unsigned long long w2 = pack2(wq.z, wq.z);
        unsigned long long w3 = pack2(wq.w, wq.w);
        const float* srow = sTs + a*TSTR;
#pragma unroll
        for (int p = 0; p < SP/2; p++){
            ulonglong2 r = *reinterpret_cast<const ulonglong2*>(srow + p*4);
            ffma2(acc[2*p][0],   r.x, w0); ffma2(acc[2*p][1],   r.x, w1);
            ffma2(acc[2*p][2],   r.x, w2); ffma2(acc[2*p][3],   r.x, w3);
            ffma2(acc[2*p+1][0], r.y, w0); ffma2(acc[2*p+1][1], r.y, w1);
            ffma2(acc[2*p+1][2], r.y, w2); ffma2(acc[2*p+1][3], r.y, w3);
        }
    }
}

static __device__ __forceinline__ void bilinear_reduce_store(
    const float T[8][4], const float* __restrict__ g2row, int b0,
    float* __restrict__ partial, float* __restrict__ outp, int ostride)
{
    int cg = threadIdx.x & 63;
    int sq = threadIdx.x >> 6;
    float val[8];
#pragma unroll
    for (int s = 0; s < 8; s++){
        float4 gq = *reinterpret_cast<const float4*>(&g2row[(b0 + sq*8 + s)*NH + cg*4]);
        val[s] = T[s][0]*gq.x + T[s][1]*gq.y + T[s][2]*gq.z + T[s][3]*gq.w;
    }
#pragma unroll
    for (int off = 16; off; off >>= 1)
#pragma unroll
        for (int s = 0; s < 8; s++)
            val[s] += __shfl_xor_sync(0xffffffffu, val[s], off);
    int w = threadIdx.x >> 5;
    if ((threadIdx.x & 31) == 0){
#pragma unroll
        for (int s = 0; s < 8; s++) partial[w*8 + s] = val[s];
    }
    __syncthreads();
    if (threadIdx.x < 32){
        int sq2 = threadIdx.x >> 3, s = threadIdx.x & 7;
        float v = partial[(2*sq2)*8 + s] + partial[(2*sq2+1)*8 + s];
        outp[(b0 + threadIdx.x)*ostride] = v;
    }
}

// ---------------- mma.sync / ldmatrix / cp.async helpers (baseline PTX) -------------
static __device__ __forceinline__ void mma16816(float (&c)[4],
    const unsigned (&a)[4], unsigned b0, unsigned b1)
{
    asm volatile("mma.sync.aligned.m16n8k16.row.col.f32.bf16.bf16.f32 "
        "{%0,%1,%2,%3}, {%4,%5,%6,%7}, {%8,%9}, {%0,%1,%2,%3};"
        : "+f"(c[0]), "+f"(c[1]), "+f"(c[2]), "+f"(c[3])
        : "r"(a[0]), "r"(a[1]), "r"(a[2]), "r"(a[3]), "r"(b0), "r"(b1));
}
static __device__ __forceinline__ void ldsm4(unsigned (&r)[4], unsigned addr){
    asm volatile("ldmatrix.sync.aligned.m8n8.x4.shared.b16 {%0,%1,%2,%3}, [%4];"
        : "=r"(r[0]), "=r"(r[1]), "=r"(r[2]), "=r"(r[3]) : "r"(addr));
}
static __device__ __forceinline__ void cpa16(unsigned saddr, const void* g){
    asm volatile("cp.async.cg.shared.global [%0], [%1], 16;" :: "r"(saddr), "l"(g));
}
static __device__ __forceinline__ void cpa_commit(){
    asm volatile("cp.async.commit_group;" ::: "memory");
}
template<int N>
static __device__ __forceinline__ void cpa_wait(){
    asm volatile("cp.async.wait_group %0;" :: "n"(N) : "memory");
}

// ======================= K_MID: (layer1+layer2) | precompQ | transpose | precompP ====
// grid 576: [0,256) layer1+2 fused | [256,512) precompQ | [512,544) cW3-T | [544,576) precompP
__global__ void __launch_bounds__(256)
k_mid(const float* __restrict__ x,
      const float* __restrict__ sW1, const float* __restrict__ sb1,
      const float* __restrict__ sW2, const float* __restrict__ sb2,
      const float* __restrict__ sW3,
      const float* __restrict__ cW1, const float* __restrict__ cb1,
      const float* __restrict__ cW2, const float* __restrict__ cb2,
      const float* __restrict__ cW3)
{
    extern __shared__ float smemf[];
    int bid = blockIdx.x;
    int t = threadIdx.x;

    if (bid < 256){
        // ---- fused layer1+layer2 for one (net, c-half, 32-sample tile)
        int net   = bid >> 7;
        int chalf = (bid >> 6) & 1;
        int b0    = (bid & 63) * 32;
        float* sT = smemf;              // NH*TSTR
        float* xs = smemf + NH*TSTR;    // 32*32
        const float* W1 = net ? cW1 : sW1;
        const float* b1 = net ? cb1 : sb1;
        const float* W    = net ? cW2 : sW2;
        const float* bias = net ? cb2 : sb2;

        // load x tile
        for (int idx = t; idx < 32*ND; idx += 256)
            xs[idx] = x[b0*ND + idx];
        __syncthreads();

        // layer1: thread t owns feature a=t across all 32 samples
        {
            float w1r[ND];
#pragma unroll
            for (int k = 0; k < ND; k++) w1r[k] = W1[k*NH + t];
            float bias1 = b1[t];
#pragma unroll 4
            for (int s = 0; s < 32; s++){
                float acc = bias1;
#pragma unroll
                for (int k = 0; k < ND; k++)
                    acc = fmaf(xs[s*32 + k], w1r[k], acc);
                float h = tanhf(acc);
                float gg = 1.0f - h*h;
                sT[t*TSTR + s] = h;
                int row = (b0 + s)*NH + t;
                if (net == 0){
                    g_g1[row] = gg;
                } else {
                    __nv_bfloat16 hi, lo; bf16split(gg, hi, lo);
                    g_g1h[row] = hi; g_g1l[row] = lo;
                }
            }
        }
        __syncthreads();

        // layer2 on the in-smem h1 tile
        int cg = t & 31;
        int sq = t >> 5;
        int c0 = chalf*128 + cg*4;

        float4 bq = *reinterpret_cast<const float4*>(&bias[c0]);
        unsigned long long acc[2][4];
        acc[0][0] = pack2(bq.x, bq.x); acc[0][1] = pack2(bq.y, bq.y);
        acc[0][2] = pack2(bq.z, bq.z); acc[0][3] = pack2(bq.w, bq.w);
#pragma unroll
        for (int cc = 0; cc < 4; cc++) acc[1][cc] = acc[0][cc];

        gemm_stream<2>(W + c0, NH, sT + sq*4, acc);

        float* h2 = g_h2[net];
        float* g2 = g_g2[net];
#pragma unroll
        for (int p = 0; p < 2; p++){
#pragma unroll
            for (int half = 0; half < 2; half++){
                float v[4];
#pragma unroll
                for (int cc = 0; cc < 4; cc++){
                    float2 f = unpack2(acc[p][cc]);
                    v[cc] = half ? f.y : f.x;
                }
                float4 hv, gv;
                hv.x = tanhf(v[0]); hv.y = tanhf(v[1]);
                hv.z = tanhf(v[2]); hv.w = tanhf(v[3]);
                gv.x = 1.0f - hv.x*hv.x; gv.y = 1.0f - hv.y*hv.y;
                gv.z = 1.0f - hv.z*hv.z; gv.w = 1.0f - hv.w*hv.w;
                int row = (b0 + sq*4 + p*2 + half)*NH + c0;
                *reinterpret_cast<float4*>(&h2[row]) = hv;
                *reinterpret_cast<float4*>(&g2[row]) = gv;
                if (net == 1){
                    __nv_bfloat16 hi, lo;
                    bf16split(hv.x, hi, lo); g_h2h[row+0] = hi; g_h2l[row+0] = lo;
                    bf16split(hv.y, hi, lo); g_h2h[row+1] = hi; g_h2l[row+1] = lo;
                    bf16split(hv.z, hi, lo); g_h2h[row+2] = hi; g_h2l[row+2] = lo;
                    bf16split(hv.w, hi, lo); g_h2h[row+3] = hi; g_h2l[row+3] = lo;
                }
            }
        }
    } else if (bid < 512){
        // ---- precompQ: Qt[i][c][a] = cW2[a,c] * sum_j cW1[j,a]*cW3[c,i*32+j]
        int r  = bid - 256;
        int i  = r & 31;
        int c0 = (r >> 5) * 32;
        float* w2s = smemf;            // [256][33]
        float* w3s = smemf + 256*33;   // [32][33]
        for (int idx = t; idx < 256*32; idx += 256){
            int ar = idx >> 5, cc = idx & 31;
            w2s[ar*33 + cc] = cW2[ar*NH + c0 + cc];
        }
        for (int idx = t; idx < 32*32; idx += 256){
            int cr = idx >> 5, j = idx & 31;
            w3s[cr*33 + j] = cW3[(c0 + cr)*(ND*ND) + i*ND + j];
        }
        __syncthreads();
        int a = t;
        float w1r[ND];
#pragma unroll
        for (int j = 0; j < ND; j++) w1r[j] = cW1[j*NH + a];
#pragma unroll 4
        for (int cc = 0; cc < 32; cc++){
            float acc = 0.f;
#pragma unroll
            for (int j = 0; j < ND; j++) acc = fmaf(w1r[j], w3s[cc*33 + j], acc);
            float q = w2s[a*33 + cc] * acc;
            __nv_bfloat16 hi, lo; bf16split(q, hi, lo);
            size_t o = ((size_t)i*NH + c0 + cc)*NH + a;
            g_Qth[o] = hi; g_Qtl[o] = lo;
        }
    } else if (bid < 544){
        // ---- transpose cW3 -> w3t[n][a] bf16 hi/lo
        int n0 = (bid - 512) * 32;
        float* s = smemf;  // [32][33]
        for (int a0 = 0; a0 < NH; a0 += 32){
            __syncthreads();
#pragma unroll
            for (int pp = 0; pp < 4; pp++){
                int ar = (t >> 5) + pp*8, nc = t & 31;
                s[ar*33 + nc] = cW3[(a0 + ar)*(ND*ND) + n0 + nc];
            }
            __syncthreads();
#pragma unroll
            for (int pp = 0; pp < 4; pp++){
                int nn = (t >> 5) + pp*8, aa = t & 31;
                float v = s[aa*33 + nn];
                __nv_bfloat16 hi, lo; bf16split(v, hi, lo);
                size_t o = ((size_t)(n0 + nn))*NH + a0 + aa;
                g_w3th[o] = hi; g_w3tl[o] = lo;
            }
        }
    } else {
        // ---- precompP (coalesced): P[a][c] = sW2[a,c] * sum_i sW3[c,i]*sW1[i,a]
        int a0 = (bid - 544) * 8;
        float* s3s = smemf;            // [256][33]
        float* w1s = smemf + 256*33;   // [32][8]
        for (int idx = t; idx < 256*32; idx += 256){
            int cc = idx >> 5, ii = idx & 31;
            s3s[cc*33 + ii] = sW3[cc*ND + ii];
        }
        {
            int ii = t >> 3, aa = t & 7;
            w1s[ii*8 + aa] = sW1[ii*NH + a0 + aa];
        }
        __syncthreads();
        int c = t;
        float accv[8];
#pragma unroll
        for (int aa = 0; aa < 8; aa++) accv[aa] = 0.f;
#pragma unroll
        for (int ii = 0; ii < ND; ii++){
            float s3 = s3s[c*33 + ii];
#pragma unroll
            for (int aa = 0; aa < 8; aa++)
                accv[aa] = fmaf(s3, w1s[ii*8 + aa], accv[aa]);
        }
#pragma unroll
        for (int aa = 0; aa < 8; aa++)
            g_P[(a0 + aa)*NH + c] = sW2[(a0 + aa)*NH + c] * accv[aa];
    }
}

// ======================= FUSED TENSOR KERNEL =======================
// grid 704:
//   [0,512)   covdiv   (i = bid&31, mt = bid>>5)
//   [512,576) layer3_cov (nt = r&3, mt = r>>2)
//   [576,640) trace    (fp32, tail-fills tensor-idle SMs)
//   [640,704) score
#define KC     32
#define BUF_B  8192u                // one buffer: 128 rows x 64B
#define STG_B  (4*BUF_B)            // Ah|Al|Bh|Bl = 32KB
#define MM_SMEM (3*STG_B)           // 98304
#define SWZ(r, q) ((unsigned)(((r)*4 + ((q) ^ (((r)>>1)&3)))*16))

__global__ void __launch_bounds__(256, 2)
k_fused(const float* __restrict__ cb3,
        const float* __restrict__ sW3, const float* __restrict__ sb3,
        float* __restrict__ out_cov, float* __restrict__ out_covdiv,
        float* __restrict__ out_score, float* __restrict__ out_trace)
{
    extern __shared__ __nv_bfloat16 smb[];
    int bid = blockIdx.x;
    int t = threadIdx.x;

    if (bid >= 576){
        // ---------------- fp32 tail work (trace / score) ----------------
        float* smemf   = reinterpret_cast<float*>(smb);
        float* sT      = smemf;
        float* partial = smemf + NH*TSTR;
        int r2 = bid - 576;
        if (r2 < 64){
            int b0 = r2 * 32;
            int cg = t & 63, sq = t >> 6;
            load_tileT(sT, g_g1, b0);
            __syncthreads();
            unsigned long long acc[4][4];
#pragma unroll
            for (int sp = 0; sp < 4; sp++)
#pragma unroll
                for (int cc = 0; cc < 4; cc++) acc[sp][cc] = 0ull;
            gemm_stream<4>(g_P + cg*4, NH, sT + sq*8, acc);
            float T[8][4];
#pragma unroll
            for (int sp = 0; sp < 4; sp++)
#pragma unroll
                for (int cc = 0; cc < 4; cc++){
                    float2 f = unpack2(acc[sp][cc]);
                    T[2*sp][cc] = f.x; T[2*sp+1][cc] = f.y;
                }
            bilinear_reduce_store(T, g_g2[0], b0, partial, out_trace, 1);
        } else {
            int b0 = (r2 - 64) * 32;
            int i  = t & 31, sg = t >> 5;
            load_tileT(sT, g_h2[0], b0);
            __syncthreads();
            float acc[4];
            float bias = sb3[i];
#pragma unroll
            for (int k = 0; k < 4; k++) acc[k] = bias;
#pragma unroll 4
            for (int a = 0; a < NH; a++){
                float w = sW3[a*ND + i];
                float4 v = *reinterpret_cast<const float4*>(&sT[a*TSTR + sg*4]);
                acc[0] = fmaf(v.x, w, acc[0]);
                acc[1] = fmaf(v.y, w, acc[1]);
                acc[2] = fmaf(v.z, w, acc[2]);
                acc[3] = fmaf(v.w, w, acc[3]);
            }
#pragma unroll
            for (int k = 0; k < 4; k++)
                out_score[(b0 + sg*4 + k)*ND + i] = acc[k];
        }
        return;
    }

    // ---------------- tensor path ----------------
    unsigned smu = (unsigned)__cvta_generic_to_shared(smb);
    int lane = t & 31, wid = t >> 5;
    int wm = wid & 3, wn = wid >> 2;       // 4x2 warp grid
    int g = lane >> 2, tig = lane & 3;
    bool is_cd = bid < 512;

    const __nv_bfloat16 *Ah, *Al, *Bh0, *Bl0;
    int m0, nt = 0, i = 0;
    if (is_cd){
        i = bid & 31; m0 = (bid >> 5)*128;
        Ah = g_g1h; Al = g_g1l;
        Bh0 = g_Qth + (size_t)i*NH*NH; Bl0 = g_Qtl + (size_t)i*NH*NH;
    } else {
        int r = bid - 512; nt = r & 3; m0 = (r >> 2)*128;
        Ah = g_h2h; Al = g_h2l;
        Bh0 = g_w3th + (size_t)nt*256*NH; Bl0 = g_w3tl + (size_t)nt*256*NH;
    }
    const __nv_bfloat16* bsrc[4] = {Ah, Al, Bh0, Bl0};

    float c[2][8][4];
#pragma unroll
    for (int mi = 0; mi < 2; mi++)
#pragma unroll
        for (int ni = 0; ni < 8; ni++)
#pragma unroll
            for (int q = 0; q < 4; q++) c[mi][ni][q] = 0.f;
    float rs[4] = {0.f, 0.f, 0.f, 0.f};

    // ldmatrix lane geometry
    int lrow = lane & 7, sel = lane >> 3;
    int qaSel = sel >> 1, qbSel = sel & 1;
    int ra4[2], rxA[2], rb4[4], rxB[4];
#pragma unroll
    for (int mi = 0; mi < 2; mi++){
        int ra = wm*32 + mi*16 + (sel & 1)*8 + lrow;
        ra4[mi] = ra*4; rxA[mi] = (ra >> 1) & 3;
    }
#pragma unroll
    for (int p = 0; p < 4; p++){
        int rb = wn*64 + p*16 + (sel >> 1)*8 + lrow;
        rb4[p] = rb*4; rxB[p] = (rb >> 1) & 3;
    }

    auto stage = [&](int j){
        int nh = j >> 3, k0 = (j & 7)*KC;
        unsigned sb = smu + (unsigned)(j % 3)*STG_B;
#pragma unroll
        for (int p = 0; p < 8; p++){
            const int buf = p >> 1;
            int r = ((p & 1) << 6) + (t >> 2);
            int q = t & 3;
            int grow = (buf < 2 ? m0 : nh*128) + r;
            cpa16(sb + (unsigned)buf*BUF_B + SWZ(r, q),
                  bsrc[buf] + (size_t)grow*NH + k0 + q*8);
        }
        cpa_commit();
    };

    stage(0); stage(1);

#pragma unroll 1
    for (int j = 0; j < 16; j++){
        __syncthreads();                 // all warps done reading buffer (j+2)%3
        if (j + 2 < 16) stage(j + 2);
        if (j < 14) cpa_wait<2>();
        else if (j == 14) cpa_wait<1>();
        else cpa_wait<0>();
        __syncwarp();

        unsigned sb = smu + (unsigned)(j % 3)*STG_B;

#pragma unroll
        for (int ks = 0; ks < 2; ks++){
            unsigned ah[2][4], al[2][4];
#pragma unroll
            for (int mi = 0; mi < 2; mi++){
                unsigned off = (unsigned)((ra4[mi] + ((ks*2 + qaSel) ^ rxA[mi])) << 4);
                ldsm4(ah[mi], sb + off);
                ldsm4(al[mi], sb + BUF_B + off);
            }
#pragma unroll
            for (int p = 0; p < 4; p++){
                unsigned offb = (unsigned)((rb4[p] + ((ks*2 + qbSel) ^ rxB[p])) << 4);
                unsigned bh[4], bl[4];
                ldsm4(bh, sb + 2*BUF_B + offb);
                ldsm4(bl, sb + 3*BUF_B + offb);
#pragma unroll
                for (int sub = 0; sub < 2; sub++)
#pragma unroll
                    for (int mi = 0; mi < 2; mi++)
                        mma16816(c[mi][2*p+sub], ah[mi], bh[sub*2], bh[sub*2+1]);
#pragma unroll
                for (int sub = 0; sub < 2; sub++)
#pragma unroll
                    for (int mi = 0; mi < 2; mi++)
                        mma16816(c[mi][2*p+sub], ah[mi], bl[sub*2], bl[sub*2+1]);
#pragma unroll
                for (int sub = 0; sub < 2; sub++)
#pragma unroll
                    for (int mi = 0; mi < 2; mi++)
                        mma16816(c[mi][2*p+sub], al[mi], bh[sub*2], bh[sub*2+1]);
            }
        }

        if ((j & 7) == 7){
            int nh = j >> 3;
            if (is_cd){
#pragma unroll
                for (int mi = 0; mi < 2; mi++){
#pragma unroll
                    for (int hf = 0; hf < 2; hf++){
                        int m = m0 + wm*32 + mi*16 + g + hf*8;
                        const float* g2r = g_g2[1] + (size_t)m*NH + nh*128;
                        float s = 0.f;
#pragma unroll
                        for (int ni = 0; ni < 8; ni++){
                            int col = wn*64 + ni*8 + tig*2;
                            float2 gg = *reinterpret_cast<const float2*>(g2r + col);
                            s += c[mi][ni][hf*2+0]*gg.x + c[mi][ni][hf*2+1]*gg.y;
                        }
                        rs[mi*2+hf] += s;
                    }
                }
            } else {
                int n0 = nt*256 + nh*128;
#pragma unroll
                for (int mi = 0; mi < 2; mi++){
#pragma unroll
                    for (int hf = 0; hf < 2; hf++){
                        int m = m0 + wm*32 + mi*16 + g + hf*8;
#pragma unroll
                        for (int ni = 0; ni < 8; ni++){
                            int col = n0 + wn*64 + ni*8 + tig*2;
                            float2 b = *reinterpret_cast<const float2*>(cb3 + col);
                            float2 v;
                            v.x = c[mi][ni][hf*2+0] + b.x;
                            v.y = c[mi][ni][hf*2+1] + b.y;
                            *reinterpret_cast<float2*>(out_cov + (size_t)m*(ND*ND) + col) = v;
                        }
                    }
                }
            }
            if (j < 15){
#pragma unroll
                for (int mi = 0; mi < 2; mi++)
#pragma unroll
                    for (int ni = 0; ni < 8; ni++)
#pragma unroll
                        for (int q = 0; q < 4; q++) c[mi][ni][q] = 0.f;
            }
        }
    }

    if (is_cd){
#pragma unroll
        for (int off = 1; off < 4; off <<= 1)
#pragma unroll
            for (int q = 0; q < 4; q++)
                rs[q] += __shfl_xor_sync(0xffffffffu, rs[q], off);
        float* red = reinterpret_cast<float*>(smb);   // [2 wn][128]
        __syncthreads();
        if (tig == 0){
#pragma unroll
            for (int mi = 0; mi < 2; mi++)
#pragma unroll
                for (int hf = 0; hf < 2; hf++)
                    red[wn*128 + wm*32 + mi*16 + g + hf*8] = rs[mi*2+hf];
        }
        __syncthreads();
        if (t < 128)
            out_covdiv[(size_t)(m0 + t)*ND + i] = red[t] + red[128+t];
    }
}

// ---------------- launch ----------------
extern "C" void kernel_launch(void* const* d_in, const int* in_sizes, int n_in,
                              void* d_out, int out_size){
    const float* x   = (const float*)d_in[0];
    const float* sW1 = (const float*)d_in[1];
    const float* sb1 = (const float*)d_in[2];
    const float* sW2 = (const float*)d_in[3];
    const float* sb2 = (const float*)d_in[4];
    const float* sW3 = (const float*)d_in[5];
    const float* sb3 = (const float*)d_in[6];
    const float* cW1 = (const float*)d_in[7];
    const float* cb1 = (const float*)d_in[8];
    const float* cW2 = (const float*)d_in[9];
    const float* cb2 = (const float*)d_in[10];
    const float* cW3 = (const float*)d_in[11];
    const float* cb3 = (const float*)d_in[12];

    float* out        = (float*)d_out;
    float* out_score  = out;                                   // [B,32]
    float* out_trace  = out + NB*ND;                           // [B]
    float* out_cov    = out + NB*ND + NB;                      // [B,1024]
    float* out_covdiv = out + NB*ND + NB + NB*ND*ND;           // [B,32]

    static int inited = 0;
    if (!inited){
        cudaFuncSetAttribute(k_fused, cudaFuncAttributeMaxDynamicSharedMemorySize, MM_SMEM);
        cudaFuncSetAttribute(k_mid,   cudaFuncAttributeMaxDynamicSharedMemorySize, MID_SMEM);
        inited = 1;
    }

    k_mid<<<576, 256, MID_SMEM>>>(x, sW1, sb1, sW2, sb2, sW3,
                                  cW1, cb1, cW2, cb2, cW3);
    k_fused<<<704, 256, MM_SMEM>>>(cb3, sW3, sb3,
                                   out_cov, out_covdiv, out_score, out_trace);
}